// round 1
// baseline (speedup 1.0000x reference)
#include <cuda_runtime.h>
#include <math.h>

#define T_ 3
#define N_ 20000
#define F_ 256
#define FO_ 256
#define E_ 320000
#define R_ 4
#define C_ 5            // cells: 0 = self, 1..4 = relations
#define MAT_ (F_*FO_)   // 65536

// ---------------- scratch (static device globals; no allocs allowed) ----------------
__device__ float g_scores[C_*N_];
__device__ float g_vals  [C_*FO_];
__device__ int   g_tidx  [C_*FO_];
__device__ float g_zt    [C_*MAT_];   // ztT layout: [c][j][k]  (j = topk rank, k = feature)
__device__ float g_upd   [C_*MAT_];
__device__ float g_rst   [C_*MAT_];
__device__ float g_Q  [2][C_*MAT_];   // double buffered Q state, row-major [F][FO]
__device__ float g_Y     [R_*N_*FO_]; // xt @ Qr[r], layout [r][n][f]
__device__ float g_deg   [R_*N_];
__device__ float g_dis   [R_*N_];
__device__ float g_denom [C_];

__device__ __forceinline__ float neg_inf() { return __int_as_float(0xff800000); }

// ---------------- init: Q[0] <- [W_self_init, W_rel_init] ----------------
__global__ void k_init(const float* __restrict__ Wself, const float* __restrict__ Wrel) {
    int i = blockIdx.x * blockDim.x + threadIdx.x;
    if (i < C_*MAT_) {
        int c = i / MAT_;
        int off = i - c*MAT_;
        g_Q[0][i] = (c == 0) ? Wself[off] : Wrel[(c-1)*MAT_ + off];
    }
}

// ---------------- scorer norms (constant over t) ----------------
__global__ void k_norm(const float* __restrict__ s_sc, const float* __restrict__ r_sc) {
    int c = blockIdx.x;
    const float* sc = (c == 0) ? s_sc : r_sc + (c-1)*F_;
    float v = sc[threadIdx.x];
    __shared__ float red[256];
    red[threadIdx.x] = v * v;
    __syncthreads();
    for (int o = 128; o > 0; o >>= 1) {
        if (threadIdx.x < o) red[threadIdx.x] += red[threadIdx.x + o];
        __syncthreads();
    }
    if (threadIdx.x == 0) g_denom[c] = sqrtf(red[0]) + 1e-8f;
}

// ---------------- scores: g_scores[c][n] = dot(x_t[n], scorer_c)/denom_c + mask[t][n] ----------------
__global__ __launch_bounds__(256) void k_scores(const float* __restrict__ x,
                                                const float* __restrict__ mask,
                                                const float* __restrict__ s_sc,
                                                const float* __restrict__ r_sc, int t) {
    __shared__ float sc[C_][F_];
    for (int i = threadIdx.x; i < C_*F_; i += blockDim.x) {
        int c = i / F_, f = i - c*F_;
        sc[c][f] = (c == 0) ? s_sc[f] : r_sc[(c-1)*F_ + f];
    }
    __syncthreads();
    int warp = threadIdx.x >> 5, lane = threadIdx.x & 31;
    int n = blockIdx.x * 8 + warp;
    if (n >= N_) return;
    const float* xr = x + ((size_t)t*N_ + n) * F_;
    float acc[C_] = {0.f, 0.f, 0.f, 0.f, 0.f};
    #pragma unroll
    for (int q = 0; q < 8; q++) {
        float xv = xr[lane + q*32];
        #pragma unroll
        for (int c = 0; c < C_; c++) acc[c] += xv * sc[c][lane + q*32];
    }
    #pragma unroll
    for (int c = 0; c < C_; c++) {
        float v = acc[c];
        for (int o = 16; o > 0; o >>= 1) v += __shfl_down_sync(0xffffffffu, v, o);
        if (lane == 0) g_scores[c*N_ + n] = v / g_denom[c] + mask[(size_t)t*N_ + n];
    }
}

// ---------------- top-256 of 20000, descending, ties -> lower index ----------------
extern __shared__ float s_topk[];
__global__ __launch_bounds__(1024) void k_topk() {
    int c = blockIdx.x;
    int tid = threadIdx.x;
    for (int i = tid; i < N_; i += 1024) s_topk[i] = g_scores[c*N_ + i];
    __syncthreads();
    __shared__ float rv[32];
    __shared__ int   ri[32];
    for (int j = 0; j < FO_; j++) {
        float bv = neg_inf(); int bi = 0x7fffffff;
        for (int i = tid; i < N_; i += 1024) {
            float v = s_topk[i];
            if (v > bv || (v == bv && i < bi)) { bv = v; bi = i; }
        }
        #pragma unroll
        for (int o = 16; o > 0; o >>= 1) {
            float ov = __shfl_down_sync(0xffffffffu, bv, o);
            int   oi = __shfl_down_sync(0xffffffffu, bi, o);
            if (ov > bv || (ov == bv && oi < bi)) { bv = ov; bi = oi; }
        }
        if ((tid & 31) == 0) { rv[tid >> 5] = bv; ri[tid >> 5] = bi; }
        __syncthreads();
        if (tid < 32) {
            bv = rv[tid]; bi = ri[tid];
            #pragma unroll
            for (int o = 16; o > 0; o >>= 1) {
                float ov = __shfl_down_sync(0xffffffffu, bv, o);
                int   oi = __shfl_down_sync(0xffffffffu, bi, o);
                if (ov > bv || (ov == bv && oi < bi)) { bv = ov; bi = oi; }
            }
            if (tid == 0) {
                g_vals[c*FO_ + j] = bv;
                g_tidx[c*FO_ + j] = bi;
                s_topk[bi] = neg_inf();
            }
        }
        __syncthreads();
    }
}

// ---------------- build ztT[c][j][k] = x_t[idx][k] * tanh(val_j) ----------------
__global__ void k_zt(const float* __restrict__ x, int t) {
    int c = blockIdx.y, j = blockIdx.x;
    int idx = g_tidx[c*FO_ + j];
    float tv = tanhf(g_vals[c*FO_ + j]);
    const float4* xr = (const float4*)(x + ((size_t)t*N_ + idx) * F_);
    float4 v = xr[threadIdx.x];
    v.x *= tv; v.y *= tv; v.z *= tv; v.w *= tv;
    ((float4*)(g_zt + (size_t)(c*FO_ + j) * F_))[threadIdx.x] = v;
}

// ---------------- cell stage 1: upd = sig(W@zt + U@Q + b), rst likewise ----------------
__global__ __launch_bounds__(256) void k_cell1(
    const float* sWz, const float* sUz, const float* sbz,
    const float* sWr, const float* sUr, const float* sbr,
    const float* rWz, const float* rUz, const float* rbz,
    const float* rWr, const float* rUr, const float* rbr, int par) {
    int o = blockIdx.z & 1, c = blockIdx.z >> 1;
    const float *W, *U, *B;
    if (o == 0) { W = c ? rWz + (c-1)*MAT_ : sWz; U = c ? rUz + (c-1)*MAT_ : sUz; B = c ? rbz + (c-1)*MAT_ : sbz; }
    else        { W = c ? rWr + (c-1)*MAT_ : sWr; U = c ? rUr + (c-1)*MAT_ : sUr; B = c ? rbr + (c-1)*MAT_ : sbr; }
    const float* Z  = g_zt + c*MAT_;
    const float* Qm = g_Q[par] + c*MAT_;
    float* OUT = (o == 0 ? g_upd : g_rst) + c*MAT_;

    __shared__ float Wt[32][33], Ut[32][33], Zt[32][33], Qt[32][33];
    int tid = threadIdx.x;
    int ty = tid >> 4, tx = tid & 15;
    int i0 = blockIdx.y * 32, j0 = blockIdx.x * 32;
    int lr = tid >> 3, lc = (tid & 7) * 4;
    float a00 = 0.f, a01 = 0.f, a10 = 0.f, a11 = 0.f;
    for (int kb = 0; kb < 256; kb += 32) {
        float4 w4 = *(const float4*)(W  + (size_t)(i0+lr)*256 + kb + lc);
        float4 u4 = *(const float4*)(U  + (size_t)(i0+lr)*256 + kb + lc);
        float4 z4 = *(const float4*)(Z  + (size_t)(j0+lr)*256 + kb + lc);
        float4 q4 = *(const float4*)(Qm + (size_t)(kb+lr)*256 + j0 + lc);
        Wt[lr][lc]=w4.x; Wt[lr][lc+1]=w4.y; Wt[lr][lc+2]=w4.z; Wt[lr][lc+3]=w4.w;
        Ut[lr][lc]=u4.x; Ut[lr][lc+1]=u4.y; Ut[lr][lc+2]=u4.z; Ut[lr][lc+3]=u4.w;
        Zt[lr][lc]=z4.x; Zt[lr][lc+1]=z4.y; Zt[lr][lc+2]=z4.z; Zt[lr][lc+3]=z4.w;
        Qt[lr][lc]=q4.x; Qt[lr][lc+1]=q4.y; Qt[lr][lc+2]=q4.z; Qt[lr][lc+3]=q4.w;
        __syncthreads();
        #pragma unroll
        for (int kk = 0; kk < 32; kk++) {
            float w0 = Wt[ty*2][kk],   w1 = Wt[ty*2+1][kk];
            float u0 = Ut[ty*2][kk],   u1 = Ut[ty*2+1][kk];
            float z0 = Zt[tx*2][kk],   z1 = Zt[tx*2+1][kk];
            float q0 = Qt[kk][tx*2],   q1 = Qt[kk][tx*2+1];
            a00 += w0*z0 + u0*q0;  a01 += w0*z1 + u0*q1;
            a10 += w1*z0 + u1*q0;  a11 += w1*z1 + u1*q1;
        }
        __syncthreads();
    }
    int i = i0 + ty*2, j = j0 + tx*2;
    OUT[(size_t)i*256 + j]         = 1.f/(1.f+expf(-(a00 + B[(size_t)i*256 + j])));
    OUT[(size_t)i*256 + j + 1]     = 1.f/(1.f+expf(-(a01 + B[(size_t)i*256 + j + 1])));
    OUT[(size_t)(i+1)*256 + j]     = 1.f/(1.f+expf(-(a10 + B[(size_t)(i+1)*256 + j])));
    OUT[(size_t)(i+1)*256 + j + 1] = 1.f/(1.f+expf(-(a11 + B[(size_t)(i+1)*256 + j + 1])));
}

// ---------------- cell stage 2: hcap = tanh(Wh@zt + Uh@(rst*Q) + bh); Qout = blend ----------------
__global__ __launch_bounds__(256) void k_cell2(
    const float* sWh, const float* sUh, const float* sbh,
    const float* rWh, const float* rUh, const float* rbh, int par) {
    int c = blockIdx.z;
    const float* W = c ? rWh + (c-1)*MAT_ : sWh;
    const float* U = c ? rUh + (c-1)*MAT_ : sUh;
    const float* B = c ? rbh + (c-1)*MAT_ : sbh;
    const float* Z   = g_zt  + c*MAT_;
    const float* Qin = g_Q[par] + c*MAT_;
    const float* RST = g_rst + c*MAT_;
    const float* UPD = g_upd + c*MAT_;
    float* Qout = g_Q[par ^ 1] + c*MAT_;

    __shared__ float Wt[32][33], Ut[32][33], Zt[32][33], Qt[32][33];
    int tid = threadIdx.x;
    int ty = tid >> 4, tx = tid & 15;
    int i0 = blockIdx.y * 32, j0 = blockIdx.x * 32;
    int lr = tid >> 3, lc = (tid & 7) * 4;
    float a00 = 0.f, a01 = 0.f, a10 = 0.f, a11 = 0.f;
    for (int kb = 0; kb < 256; kb += 32) {
        float4 w4 = *(const float4*)(W   + (size_t)(i0+lr)*256 + kb + lc);
        float4 u4 = *(const float4*)(U   + (size_t)(i0+lr)*256 + kb + lc);
        float4 z4 = *(const float4*)(Z   + (size_t)(j0+lr)*256 + kb + lc);
        float4 q4 = *(const float4*)(Qin + (size_t)(kb+lr)*256 + j0 + lc);
        float4 r4 = *(const float4*)(RST + (size_t)(kb+lr)*256 + j0 + lc);
        Wt[lr][lc]=w4.x; Wt[lr][lc+1]=w4.y; Wt[lr][lc+2]=w4.z; Wt[lr][lc+3]=w4.w;
        Ut[lr][lc]=u4.x; Ut[lr][lc+1]=u4.y; Ut[lr][lc+2]=u4.z; Ut[lr][lc+3]=u4.w;
        Zt[lr][lc]=z4.x; Zt[lr][lc+1]=z4.y; Zt[lr][lc+2]=z4.z; Zt[lr][lc+3]=z4.w;
        Qt[lr][lc]=q4.x*r4.x; Qt[lr][lc+1]=q4.y*r4.y; Qt[lr][lc+2]=q4.z*r4.z; Qt[lr][lc+3]=q4.w*r4.w;
        __syncthreads();
        #pragma unroll
        for (int kk = 0; kk < 32; kk++) {
            float w0 = Wt[ty*2][kk],   w1 = Wt[ty*2+1][kk];
            float u0 = Ut[ty*2][kk],   u1 = Ut[ty*2+1][kk];
            float z0 = Zt[tx*2][kk],   z1 = Zt[tx*2+1][kk];
            float q0 = Qt[kk][tx*2],   q1 = Qt[kk][tx*2+1];
            a00 += w0*z0 + u0*q0;  a01 += w0*z1 + u0*q1;
            a10 += w1*z0 + u1*q0;  a11 += w1*z1 + u1*q1;
        }
        __syncthreads();
    }
    int i = i0 + ty*2, j = j0 + tx*2;
    #pragma unroll
    for (int a = 0; a < 2; a++) {
        #pragma unroll
        for (int b = 0; b < 2; b++) {
            float acc = (a==0) ? (b==0?a00:a01) : (b==0?a10:a11);
            size_t ij = (size_t)(i+a)*256 + (j+b);
            float h = tanhf(acc + B[ij]);
            float u = UPD[ij];
            Qout[ij] = (1.f - u) * Qin[ij] + u * h;
        }
    }
}

// ---------------- big GEMM: x_t[20000,256] @ Q_c[256,256] ----------------
// c==0 -> d_out[t]; c>=1 -> g_Y[c-1]
__global__ __launch_bounds__(256) void k_biggemm(const float* __restrict__ x,
                                                 float* __restrict__ out, int t, int qsel) {
    int c = blockIdx.z;
    const float* Bm = g_Q[qsel] + c*MAT_;
    float* dst = (c == 0) ? out + (size_t)t*N_*FO_ : g_Y + (size_t)(c-1)*N_*FO_;
    int m0 = blockIdx.x * 64;
    int n0 = blockIdx.y * 64;

    __shared__ float As[16][68];  // [k][m]
    __shared__ float Bs[16][68];  // [k][n]
    int tid = threadIdx.x;
    int ty = tid >> 4, tx = tid & 15;
    float acc[4][4];
    #pragma unroll
    for (int a = 0; a < 4; a++)
        #pragma unroll
        for (int b = 0; b < 4; b++) acc[a][b] = 0.f;

    int alr = tid >> 2, alc = (tid & 3) * 4;   // A: row 0..63, kcol group
    int blr = tid >> 4, blc = (tid & 15) * 4;  // B: krow 0..15, ncol group

    for (int kb = 0; kb < 256; kb += 16) {
        float4 a4 = make_float4(0.f, 0.f, 0.f, 0.f);
        if (m0 + alr < N_)
            a4 = *(const float4*)(x + ((size_t)t*N_ + m0 + alr)*256 + kb + alc);
        As[alc][alr] = a4.x; As[alc+1][alr] = a4.y; As[alc+2][alr] = a4.z; As[alc+3][alr] = a4.w;
        float4 b4 = *(const float4*)(Bm + (size_t)(kb + blr)*256 + n0 + blc);
        *(float4*)&Bs[blr][blc] = b4;
        __syncthreads();
        #pragma unroll
        for (int kk = 0; kk < 16; kk++) {
            float4 av = *(float4*)&As[kk][ty*4];
            float4 bv = *(float4*)&Bs[kk][tx*4];
            float ar[4] = {av.x, av.y, av.z, av.w};
            float br[4] = {bv.x, bv.y, bv.z, bv.w};
            #pragma unroll
            for (int a = 0; a < 4; a++)
                #pragma unroll
                for (int b = 0; b < 4; b++) acc[a][b] += ar[a] * br[b];
        }
        __syncthreads();
    }
    #pragma unroll
    for (int a = 0; a < 4; a++) {
        int gm = m0 + ty*4 + a;
        if (gm < N_) {
            float4 v = make_float4(acc[a][0], acc[a][1], acc[a][2], acc[a][3]);
            *(float4*)&dst[(size_t)gm*256 + n0 + tx*4] = v;
        }
    }
}

// ---------------- edges ----------------
__global__ void k_zero_deg() {
    int i = blockIdx.x * blockDim.x + threadIdx.x;
    if (i < R_*N_) g_deg[i] = 0.f;
}
__global__ void k_count(const int* __restrict__ ei, const int* __restrict__ et, int t) {
    int e = blockIdx.x * blockDim.x + threadIdx.x;
    if (e >= E_) return;
    int row = ei[(size_t)t*2*E_ + e];
    int r   = et[(size_t)t*E_ + e];
    atomicAdd(&g_deg[r*N_ + row], 1.f);
}
__global__ void k_dis() {
    int i = blockIdx.x * blockDim.x + threadIdx.x;
    if (i >= R_*N_) return;
    float d = g_deg[i];
    g_dis[i] = (d > 0.f) ? (1.f / sqrtf(d)) : 0.f;
}
__global__ __launch_bounds__(256) void k_agg(const int* __restrict__ ei,
                                             const int* __restrict__ et,
                                             float* __restrict__ out, int t) {
    int g = blockIdx.x * blockDim.x + threadIdx.x;
    int e = g >> 5;
    int lane = g & 31;
    if (e >= E_) return;
    int row = ei[(size_t)t*2*E_ + e];
    int col = ei[(size_t)t*2*E_ + E_ + e];
    int r   = et[(size_t)t*E_ + e];
    float norm = g_dis[r*N_ + row] * g_dis[r*N_ + col];
    if (norm == 0.f) return;
    const float4* src = (const float4*)(g_Y + ((size_t)r*N_ + col) * 256);
    float* dstrow = out + (size_t)t*N_*256 + (size_t)row*256;
    #pragma unroll
    for (int q = 0; q < 2; q++) {
        float4 v = src[lane + q*32];
        int base = (lane + q*32) * 4;
        atomicAdd(dstrow + base + 0, v.x * norm);
        atomicAdd(dstrow + base + 1, v.y * norm);
        atomicAdd(dstrow + base + 2, v.z * norm);
        atomicAdd(dstrow + base + 3, v.w * norm);
    }
}
__global__ void k_relu(float* __restrict__ out, int t) {
    int i = blockIdx.x * blockDim.x + threadIdx.x;
    if (i >= N_*256/4) return;
    float4* p = (float4*)(out + (size_t)t*N_*256);
    float4 v = p[i];
    v.x = fmaxf(v.x, 0.f); v.y = fmaxf(v.y, 0.f);
    v.z = fmaxf(v.z, 0.f); v.w = fmaxf(v.w, 0.f);
    p[i] = v;
}

// ---------------- launcher ----------------
extern "C" void kernel_launch(void* const* d_in, const int* in_sizes, int n_in,
                              void* d_out, int out_size) {
    const float* x       = (const float*)d_in[0];
    const float* mask    = (const float*)d_in[1];
    const float* Wself   = (const float*)d_in[2];
    const float* Wrel    = (const float*)d_in[3];
    const float* sWz     = (const float*)d_in[4];
    const float* sUz     = (const float*)d_in[5];
    const float* sbz     = (const float*)d_in[6];
    const float* sWr     = (const float*)d_in[7];
    const float* sUr     = (const float*)d_in[8];
    const float* sbr     = (const float*)d_in[9];
    const float* sWh     = (const float*)d_in[10];
    const float* sUh     = (const float*)d_in[11];
    const float* sbh     = (const float*)d_in[12];
    const float* s_sc    = (const float*)d_in[13];
    const float* rWz     = (const float*)d_in[14];
    const float* rUz     = (const float*)d_in[15];
    const float* rbz     = (const float*)d_in[16];
    const float* rWr     = (const float*)d_in[17];
    const float* rUr     = (const float*)d_in[18];
    const float* rbr     = (const float*)d_in[19];
    const float* rWh     = (const float*)d_in[20];
    const float* rUh     = (const float*)d_in[21];
    const float* rbh     = (const float*)d_in[22];
    const float* r_sc    = (const float*)d_in[23];
    const int*   ei      = (const int*)d_in[24];
    const int*   et      = (const int*)d_in[25];
    float* out = (float*)d_out;

    static bool attr_set = false;
    if (!attr_set) {
        cudaFuncSetAttribute(k_topk, cudaFuncAttributeMaxDynamicSharedMemorySize,
                             N_ * (int)sizeof(float));
        attr_set = true;
    }

    k_init<<<(C_*MAT_ + 255)/256, 256>>>(Wself, Wrel);
    k_norm<<<C_, 256>>>(s_sc, r_sc);

    for (int t = 0; t < T_; t++) {
        int par = t & 1;   // input parity; updated Q goes to par^1
        k_scores<<<2500, 256>>>(x, mask, s_sc, r_sc, t);
        k_topk<<<C_, 1024, N_ * sizeof(float)>>>();
        k_zt<<<dim3(FO_, C_), 64>>>(x, t);
        k_cell1<<<dim3(8, 8, 2*C_), 256>>>(sWz, sUz, sbz, sWr, sUr, sbr,
                                           rWz, rUz, rbz, rWr, rUr, rbr, par);
        k_cell2<<<dim3(8, 8, C_), 256>>>(sWh, sUh, sbh, rWh, rUh, rbh, par);
        k_biggemm<<<dim3((N_ + 63)/64, FO_/64, C_), 256>>>(x, out, t, par ^ 1);
        k_zero_deg<<<(R_*N_ + 255)/256, 256>>>();
        k_count<<<(E_ + 255)/256, 256>>>(ei, et, t);
        k_dis<<<(R_*N_ + 255)/256, 256>>>();
        k_agg<<<(E_*32 + 255)/256, 256>>>(ei, et, out, t);
        k_relu<<<(N_*256/4 + 255)/256, 256>>>(out, t);
    }
}

// round 2
// speedup vs baseline: 1.6614x; 1.6614x over previous
#include <cuda_runtime.h>
#include <math.h>
#include <stdint.h>

#define T_ 3
#define N_ 20000
#define F_ 256
#define FO_ 256
#define E_ 320000
#define R_ 4
#define C_ 5            // cells: 0 = self, 1..4 = relations
#define MAT_ (F_*FO_)   // 65536

// ---------------- scratch (static device globals; no allocs allowed) ----------------
__device__ float g_scores[C_*N_];
__device__ float g_vals  [C_*FO_];
__device__ int   g_tidx  [C_*FO_];
__device__ float g_zt    [C_*MAT_];   // ztT layout: [c][j][k]  (j = topk rank, k = feature)
__device__ float g_upd   [C_*MAT_];
__device__ float g_rst   [C_*MAT_];
__device__ float g_Q  [2][C_*MAT_];   // double buffered Q state, row-major [F][FO]
__device__ float g_Y     [R_*N_*FO_]; // xt @ Qr[r], layout [r][n][f]
__device__ float g_deg   [R_*N_];
__device__ float g_dis   [R_*N_];
__device__ float g_denom [C_];

__device__ __forceinline__ float neg_inf() { return __int_as_float(0xff800000); }

// order-preserving float->uint key (larger float => larger key)
__device__ __forceinline__ uint32_t f2key(float f) {
    uint32_t u = __float_as_uint(f);
    return (u & 0x80000000u) ? ~u : (u | 0x80000000u);
}
__device__ __forceinline__ float key2f(uint32_t k) {
    return (k & 0x80000000u) ? __uint_as_float(k & 0x7FFFFFFFu) : __uint_as_float(~k);
}

// ---------------- init: Q[0] <- [W_self_init, W_rel_init] ----------------
__global__ void k_init(const float* __restrict__ Wself, const float* __restrict__ Wrel) {
    int i = blockIdx.x * blockDim.x + threadIdx.x;
    if (i < C_*MAT_) {
        int c = i / MAT_;
        int off = i - c*MAT_;
        g_Q[0][i] = (c == 0) ? Wself[off] : Wrel[(c-1)*MAT_ + off];
    }
}

// ---------------- scorer norms (constant over t) ----------------
__global__ void k_norm(const float* __restrict__ s_sc, const float* __restrict__ r_sc) {
    int c = blockIdx.x;
    const float* sc = (c == 0) ? s_sc : r_sc + (c-1)*F_;
    float v = sc[threadIdx.x];
    __shared__ float red[256];
    red[threadIdx.x] = v * v;
    __syncthreads();
    for (int o = 128; o > 0; o >>= 1) {
        if (threadIdx.x < o) red[threadIdx.x] += red[threadIdx.x + o];
        __syncthreads();
    }
    if (threadIdx.x == 0) g_denom[c] = sqrtf(red[0]) + 1e-8f;
}

// ---------------- scores ----------------
__global__ __launch_bounds__(256) void k_scores(const float* __restrict__ x,
                                                const float* __restrict__ mask,
                                                const float* __restrict__ s_sc,
                                                const float* __restrict__ r_sc, int t) {
    __shared__ float sc[C_][F_];
    for (int i = threadIdx.x; i < C_*F_; i += blockDim.x) {
        int c = i / F_, f = i - c*F_;
        sc[c][f] = (c == 0) ? s_sc[f] : r_sc[(c-1)*F_ + f];
    }
    __syncthreads();
    int warp = threadIdx.x >> 5, lane = threadIdx.x & 31;
    int n = blockIdx.x * 8 + warp;
    if (n >= N_) return;
    const float* xr = x + ((size_t)t*N_ + n) * F_;
    float acc[C_] = {0.f, 0.f, 0.f, 0.f, 0.f};
    #pragma unroll
    for (int q = 0; q < 8; q++) {
        float xv = xr[lane + q*32];
        #pragma unroll
        for (int c = 0; c < C_; c++) acc[c] += xv * sc[c][lane + q*32];
    }
    #pragma unroll
    for (int c = 0; c < C_; c++) {
        float v = acc[c];
        for (int o = 16; o > 0; o >>= 1) v += __shfl_down_sync(0xffffffffu, v, o);
        if (lane == 0) g_scores[c*N_ + n] = v / g_denom[c] + mask[(size_t)t*N_ + n];
    }
}

// ---------------- top-256 of 20000 via radix select + bitonic sort ----------------
// Exact semantics of jax.lax.top_k: descending values, ties broken by lower index.
extern __shared__ uint32_t s_keys[];   // N_ uint32 keys (80 KB dynamic)
__global__ __launch_bounds__(1024) void k_topk() {
    __shared__ uint32_t hist[256];
    __shared__ uint32_t selKey[256];
    __shared__ int      selIdx[256];
    __shared__ uint32_t s_prefix;
    __shared__ int      s_remaining, s_eqCount, s_idxTh, s_cnt;

    int c = blockIdx.x;
    int tid = threadIdx.x;

    for (int i = tid; i < N_; i += 1024)
        s_keys[i] = f2key(g_scores[c*N_ + i]);
    if (tid == 0) { s_prefix = 0u; s_remaining = FO_; s_idxTh = 0x7FFFFFFF; }
    __syncthreads();

    // ---- 4 MSB-first radix passes on the value key ----
    #pragma unroll
    for (int pass = 3; pass >= 0; pass--) {
        int shift = pass * 8;
        if (tid < 256) hist[tid] = 0;
        __syncthreads();
        uint32_t prefix = s_prefix;
        uint32_t pmask = (pass == 3) ? 0u : (0xFFFFFFFFu << (shift + 8));
        for (int i = tid; i < N_; i += 1024) {
            uint32_t k = s_keys[i];
            if ((k & pmask) == (prefix & pmask))
                atomicAdd(&hist[(k >> shift) & 0xFF], 1u);
        }
        __syncthreads();
        if (tid == 0) {
            int rem = s_remaining;
            uint32_t pfx = s_prefix;
            for (int b = 255; b >= 0; b--) {
                int cnt = (int)hist[b];
                if (cnt >= rem) {
                    pfx |= ((uint32_t)b) << shift;
                    if (pass == 0) s_eqCount = cnt;
                    break;
                }
                rem -= cnt;
            }
            s_remaining = rem;
            s_prefix = pfx;
        }
        __syncthreads();
    }
    uint32_t kth = s_prefix;
    int need = s_remaining;            // how many equal-to-kth elements to take

    // ---- tie resolution: need-th smallest index among key==kth ----
    if (need < s_eqCount) {
        if (tid == 0) { s_prefix = 0u; s_remaining = need; }
        __syncthreads();
        #pragma unroll
        for (int pass = 1; pass >= 0; pass--) {
            int shift = pass * 8;
            if (tid < 256) hist[tid] = 0;
            __syncthreads();
            uint32_t prefixI = s_prefix;
            for (int i = tid; i < N_; i += 1024) {
                if (s_keys[i] == kth) {
                    if (pass == 1 || (((uint32_t)i >> 8) & 0xFF) == ((prefixI >> 8) & 0xFF))
                        atomicAdd(&hist[((uint32_t)i >> shift) & 0xFF], 1u);
                }
            }
            __syncthreads();
            if (tid == 0) {
                int rem = s_remaining;
                uint32_t pfx = s_prefix;
                for (int b = 0; b < 256; b++) {
                    int cnt = (int)hist[b];
                    if (cnt >= rem) { pfx |= ((uint32_t)b) << shift; break; }
                    rem -= cnt;
                }
                s_remaining = rem;
                s_prefix = pfx;
            }
            __syncthreads();
        }
        if (tid == 0) s_idxTh = (int)s_prefix;   // need-th smallest index (inclusive)
    }
    if (tid == 0) s_cnt = 0;
    __syncthreads();
    int idxTh = s_idxTh;

    // ---- compact the exact winners ----
    for (int i = tid; i < N_; i += 1024) {
        uint32_t k = s_keys[i];
        if (k > kth || (k == kth && i <= idxTh)) {
            int p = atomicAdd(&s_cnt, 1);
            selKey[p] = k;
            selIdx[p] = i;
        }
    }
    __syncthreads();

    // ---- bitonic sort 256 elements: descending key, ascending index on tie ----
    for (int k = 2; k <= 256; k <<= 1) {
        for (int j = k >> 1; j > 0; j >>= 1) {
            if (tid < 256) {
                int ixj = tid ^ j;
                if (ixj > tid) {
                    bool desc = ((tid & k) == 0);
                    uint32_t ka = selKey[tid], kb = selKey[ixj];
                    int ia = selIdx[tid], ib = selIdx[ixj];
                    bool aGreater = (ka > kb) || (ka == kb && ia < ib);
                    bool doswap = desc ? !aGreater : aGreater;
                    if (doswap) {
                        selKey[tid] = kb; selKey[ixj] = ka;
                        selIdx[tid] = ib; selIdx[ixj] = ia;
                    }
                }
            }
            __syncthreads();
        }
    }

    if (tid < 256) {
        g_vals[c*FO_ + tid] = key2f(selKey[tid]);
        g_tidx[c*FO_ + tid] = selIdx[tid];
    }
}

// ---------------- build ztT[c][j][k] = x_t[idx][k] * tanh(val_j) ----------------
__global__ void k_zt(const float* __restrict__ x, int t) {
    int c = blockIdx.y, j = blockIdx.x;
    int idx = g_tidx[c*FO_ + j];
    float tv = tanhf(g_vals[c*FO_ + j]);
    const float4* xr = (const float4*)(x + ((size_t)t*N_ + idx) * F_);
    float4 v = xr[threadIdx.x];
    v.x *= tv; v.y *= tv; v.z *= tv; v.w *= tv;
    ((float4*)(g_zt + (size_t)(c*FO_ + j) * F_))[threadIdx.x] = v;
}

// ---------------- cell stage 1 ----------------
__global__ __launch_bounds__(256) void k_cell1(
    const float* sWz, const float* sUz, const float* sbz,
    const float* sWr, const float* sUr, const float* sbr,
    const float* rWz, const float* rUz, const float* rbz,
    const float* rWr, const float* rUr, const float* rbr, int par) {
    int o = blockIdx.z & 1, c = blockIdx.z >> 1;
    const float *W, *U, *B;
    if (o == 0) { W = c ? rWz + (c-1)*MAT_ : sWz; U = c ? rUz + (c-1)*MAT_ : sUz; B = c ? rbz + (c-1)*MAT_ : sbz; }
    else        { W = c ? rWr + (c-1)*MAT_ : sWr; U = c ? rUr + (c-1)*MAT_ : sUr; B = c ? rbr + (c-1)*MAT_ : sbr; }
    const float* Z  = g_zt + c*MAT_;
    const float* Qm = g_Q[par] + c*MAT_;
    float* OUT = (o == 0 ? g_upd : g_rst) + c*MAT_;

    __shared__ float Wt[32][33], Ut[32][33], Zt[32][33], Qt[32][33];
    int tid = threadIdx.x;
    int ty = tid >> 4, tx = tid & 15;
    int i0 = blockIdx.y * 32, j0 = blockIdx.x * 32;
    int lr = tid >> 3, lc = (tid & 7) * 4;
    float a00 = 0.f, a01 = 0.f, a10 = 0.f, a11 = 0.f;
    for (int kb = 0; kb < 256; kb += 32) {
        float4 w4 = *(const float4*)(W  + (size_t)(i0+lr)*256 + kb + lc);
        float4 u4 = *(const float4*)(U  + (size_t)(i0+lr)*256 + kb + lc);
        float4 z4 = *(const float4*)(Z  + (size_t)(j0+lr)*256 + kb + lc);
        float4 q4 = *(const float4*)(Qm + (size_t)(kb+lr)*256 + j0 + lc);
        Wt[lr][lc]=w4.x; Wt[lr][lc+1]=w4.y; Wt[lr][lc+2]=w4.z; Wt[lr][lc+3]=w4.w;
        Ut[lr][lc]=u4.x; Ut[lr][lc+1]=u4.y; Ut[lr][lc+2]=u4.z; Ut[lr][lc+3]=u4.w;
        Zt[lr][lc]=z4.x; Zt[lr][lc+1]=z4.y; Zt[lr][lc+2]=z4.z; Zt[lr][lc+3]=z4.w;
        Qt[lr][lc]=q4.x; Qt[lr][lc+1]=q4.y; Qt[lr][lc+2]=q4.z; Qt[lr][lc+3]=q4.w;
        __syncthreads();
        #pragma unroll
        for (int kk = 0; kk < 32; kk++) {
            float w0 = Wt[ty*2][kk],   w1 = Wt[ty*2+1][kk];
            float u0 = Ut[ty*2][kk],   u1 = Ut[ty*2+1][kk];
            float z0 = Zt[tx*2][kk],   z1 = Zt[tx*2+1][kk];
            float q0 = Qt[kk][tx*2],   q1 = Qt[kk][tx*2+1];
            a00 += w0*z0 + u0*q0;  a01 += w0*z1 + u0*q1;
            a10 += w1*z0 + u1*q0;  a11 += w1*z1 + u1*q1;
        }
        __syncthreads();
    }
    int i = i0 + ty*2, j = j0 + tx*2;
    OUT[(size_t)i*256 + j]         = 1.f/(1.f+expf(-(a00 + B[(size_t)i*256 + j])));
    OUT[(size_t)i*256 + j + 1]     = 1.f/(1.f+expf(-(a01 + B[(size_t)i*256 + j + 1])));
    OUT[(size_t)(i+1)*256 + j]     = 1.f/(1.f+expf(-(a10 + B[(size_t)(i+1)*256 + j])));
    OUT[(size_t)(i+1)*256 + j + 1] = 1.f/(1.f+expf(-(a11 + B[(size_t)(i+1)*256 + j + 1])));
}

// ---------------- cell stage 2 ----------------
__global__ __launch_bounds__(256) void k_cell2(
    const float* sWh, const float* sUh, const float* sbh,
    const float* rWh, const float* rUh, const float* rbh, int par) {
    int c = blockIdx.z;
    const float* W = c ? rWh + (c-1)*MAT_ : sWh;
    const float* U = c ? rUh + (c-1)*MAT_ : sUh;
    const float* B = c ? rbh + (c-1)*MAT_ : sbh;
    const float* Z   = g_zt  + c*MAT_;
    const float* Qin = g_Q[par] + c*MAT_;
    const float* RST = g_rst + c*MAT_;
    const float* UPD = g_upd + c*MAT_;
    float* Qout = g_Q[par ^ 1] + c*MAT_;

    __shared__ float Wt[32][33], Ut[32][33], Zt[32][33], Qt[32][33];
    int tid = threadIdx.x;
    int ty = tid >> 4, tx = tid & 15;
    int i0 = blockIdx.y * 32, j0 = blockIdx.x * 32;
    int lr = tid >> 3, lc = (tid & 7) * 4;
    float a00 = 0.f, a01 = 0.f, a10 = 0.f, a11 = 0.f;
    for (int kb = 0; kb < 256; kb += 32) {
        float4 w4 = *(const float4*)(W   + (size_t)(i0+lr)*256 + kb + lc);
        float4 u4 = *(const float4*)(U   + (size_t)(i0+lr)*256 + kb + lc);
        float4 z4 = *(const float4*)(Z   + (size_t)(j0+lr)*256 + kb + lc);
        float4 q4 = *(const float4*)(Qin + (size_t)(kb+lr)*256 + j0 + lc);
        float4 r4 = *(const float4*)(RST + (size_t)(kb+lr)*256 + j0 + lc);
        Wt[lr][lc]=w4.x; Wt[lr][lc+1]=w4.y; Wt[lr][lc+2]=w4.z; Wt[lr][lc+3]=w4.w;
        Ut[lr][lc]=u4.x; Ut[lr][lc+1]=u4.y; Ut[lr][lc+2]=u4.z; Ut[lr][lc+3]=u4.w;
        Zt[lr][lc]=z4.x; Zt[lr][lc+1]=z4.y; Zt[lr][lc+2]=z4.z; Zt[lr][lc+3]=z4.w;
        Qt[lr][lc]=q4.x*r4.x; Qt[lr][lc+1]=q4.y*r4.y; Qt[lr][lc+2]=q4.z*r4.z; Qt[lr][lc+3]=q4.w*r4.w;
        __syncthreads();
        #pragma unroll
        for (int kk = 0; kk < 32; kk++) {
            float w0 = Wt[ty*2][kk],   w1 = Wt[ty*2+1][kk];
            float u0 = Ut[ty*2][kk],   u1 = Ut[ty*2+1][kk];
            float z0 = Zt[tx*2][kk],   z1 = Zt[tx*2+1][kk];
            float q0 = Qt[kk][tx*2],   q1 = Qt[kk][tx*2+1];
            a00 += w0*z0 + u0*q0;  a01 += w0*z1 + u0*q1;
            a10 += w1*z0 + u1*q0;  a11 += w1*z1 + u1*q1;
        }
        __syncthreads();
    }
    int i = i0 + ty*2, j = j0 + tx*2;
    #pragma unroll
    for (int a = 0; a < 2; a++) {
        #pragma unroll
        for (int b = 0; b < 2; b++) {
            float acc = (a==0) ? (b==0?a00:a01) : (b==0?a10:a11);
            size_t ij = (size_t)(i+a)*256 + (j+b);
            float h = tanhf(acc + B[ij]);
            float u = UPD[ij];
            Qout[ij] = (1.f - u) * Qin[ij] + u * h;
        }
    }
}

// ---------------- big GEMM: x_t[20000,256] @ Q_c[256,256], 128x128 tile, 8x8/thread ----
__global__ __launch_bounds__(256) void k_biggemm(const float* __restrict__ x,
                                                 float* __restrict__ out, int t, int qsel) {
    int c = blockIdx.z;
    const float* Bm = g_Q[qsel] + c*MAT_;
    float* dst = (c == 0) ? out + (size_t)t*N_*FO_ : g_Y + (size_t)(c-1)*N_*FO_;
    int m0 = blockIdx.x * 128;
    int n0 = blockIdx.y * 128;

    __shared__ float As[16][132];  // [k][m], +4 pad keeps 16B row alignment
    __shared__ float Bs[16][132];  // [k][n]
    int tid = threadIdx.x;
    int ty = tid >> 4, tx = tid & 15;

    float acc[8][8];
    #pragma unroll
    for (int i = 0; i < 8; i++)
        #pragma unroll
        for (int j = 0; j < 8; j++) acc[i][j] = 0.f;

    const float* Ag = x + (size_t)t*N_*F_;
    int ar = tid >> 2, akc = (tid & 3) * 4;     // A loader: 64 rows x 16 k, x2
    int bkr = tid >> 4, bnc = (tid & 15) * 4;   // B loader: 16 k x 64 n, x2

    for (int kb = 0; kb < F_; kb += 16) {
        #pragma unroll
        for (int h = 0; h < 2; h++) {
            int row = m0 + ar + h*64;
            float4 a4 = make_float4(0.f, 0.f, 0.f, 0.f);
            if (row < N_)
                a4 = *(const float4*)(Ag + (size_t)row*F_ + kb + akc);
            As[akc  ][ar + h*64] = a4.x;
            As[akc+1][ar + h*64] = a4.y;
            As[akc+2][ar + h*64] = a4.z;
            As[akc+3][ar + h*64] = a4.w;
        }
        #pragma unroll
        for (int h = 0; h < 2; h++) {
            float4 b4 = *(const float4*)(Bm + (size_t)(kb + bkr)*FO_ + n0 + bnc + h*64);
            *(float4*)&Bs[bkr][bnc + h*64] = b4;
        }
        __syncthreads();
        #pragma unroll
        for (int kk = 0; kk < 16; kk++) {
            float a[8], b[8];
            *(float4*)&a[0] = *(float4*)&As[kk][ty*8];
            *(float4*)&a[4] = *(float4*)&As[kk][ty*8 + 4];
            *(float4*)&b[0] = *(float4*)&Bs[kk][tx*8];
            *(float4*)&b[4] = *(float4*)&Bs[kk][tx*8 + 4];
            #pragma unroll
            for (int i = 0; i < 8; i++)
                #pragma unroll
                for (int j = 0; j < 8; j++) acc[i][j] += a[i] * b[j];
        }
        __syncthreads();
    }
    #pragma unroll
    for (int i = 0; i < 8; i++) {
        int gm = m0 + ty*8 + i;
        if (gm < N_) {
            #pragma unroll
            for (int j = 0; j < 8; j += 4) {
                *(float4*)&dst[(size_t)gm*FO_ + n0 + tx*8 + j] =
                    make_float4(acc[i][j], acc[i][j+1], acc[i][j+2], acc[i][j+3]);
            }
        }
    }
}

// ---------------- edges ----------------
__global__ void k_zero_deg() {
    int i = blockIdx.x * blockDim.x + threadIdx.x;
    if (i < R_*N_) g_deg[i] = 0.f;
}
__global__ void k_count(const int* __restrict__ ei, const int* __restrict__ et, int t) {
    int e = blockIdx.x * blockDim.x + threadIdx.x;
    if (e >= E_) return;
    int row = ei[(size_t)t*2*E_ + e];
    int r   = et[(size_t)t*E_ + e];
    atomicAdd(&g_deg[r*N_ + row], 1.f);
}
__global__ void k_dis() {
    int i = blockIdx.x * blockDim.x + threadIdx.x;
    if (i >= R_*N_) return;
    float d = g_deg[i];
    g_dis[i] = (d > 0.f) ? (1.f / sqrtf(d)) : 0.f;
}
__global__ __launch_bounds__(256) void k_agg(const int* __restrict__ ei,
                                             const int* __restrict__ et,
                                             float* __restrict__ out, int t) {
    int g = blockIdx.x * blockDim.x + threadIdx.x;
    int e = g >> 5;
    int lane = g & 31;
    if (e >= E_) return;
    int row = ei[(size_t)t*2*E_ + e];
    int col = ei[(size_t)t*2*E_ + E_ + e];
    int r   = et[(size_t)t*E_ + e];
    float norm = g_dis[r*N_ + row] * g_dis[r*N_ + col];
    if (norm == 0.f) return;
    const float4* src = (const float4*)(g_Y + ((size_t)r*N_ + col) * 256);
    float* dstrow = out + (size_t)t*N_*256 + (size_t)row*256;
    #pragma unroll
    for (int q = 0; q < 2; q++) {
        float4 v = src[lane + q*32];
        int base = (lane + q*32) * 4;
        atomicAdd(dstrow + base + 0, v.x * norm);
        atomicAdd(dstrow + base + 1, v.y * norm);
        atomicAdd(dstrow + base + 2, v.z * norm);
        atomicAdd(dstrow + base + 3, v.w * norm);
    }
}
__global__ void k_relu(float* __restrict__ out, int t) {
    int i = blockIdx.x * blockDim.x + threadIdx.x;
    if (i >= N_*256/4) return;
    float4* p = (float4*)(out + (size_t)t*N_*256);
    float4 v = p[i];
    v.x = fmaxf(v.x, 0.f); v.y = fmaxf(v.y, 0.f);
    v.z = fmaxf(v.z, 0.f); v.w = fmaxf(v.w, 0.f);
    p[i] = v;
}

// ---------------- launcher ----------------
extern "C" void kernel_launch(void* const* d_in, const int* in_sizes, int n_in,
                              void* d_out, int out_size) {
    const float* x       = (const float*)d_in[0];
    const float* mask    = (const float*)d_in[1];
    const float* Wself   = (const float*)d_in[2];
    const float* Wrel    = (const float*)d_in[3];
    const float* sWz     = (const float*)d_in[4];
    const float* sUz     = (const float*)d_in[5];
    const float* sbz     = (const float*)d_in[6];
    const float* sWr     = (const float*)d_in[7];
    const float* sUr     = (const float*)d_in[8];
    const float* sbr     = (const float*)d_in[9];
    const float* sWh     = (const float*)d_in[10];
    const float* sUh     = (const float*)d_in[11];
    const float* sbh     = (const float*)d_in[12];
    const float* s_sc    = (const float*)d_in[13];
    const float* rWz     = (const float*)d_in[14];
    const float* rUz     = (const float*)d_in[15];
    const float* rbz     = (const float*)d_in[16];
    const float* rWr     = (const float*)d_in[17];
    const float* rUr     = (const float*)d_in[18];
    const float* rbr     = (const float*)d_in[19];
    const float* rWh     = (const float*)d_in[20];
    const float* rUh     = (const float*)d_in[21];
    const float* rbh     = (const float*)d_in[22];
    const float* r_sc    = (const float*)d_in[23];
    const int*   ei      = (const int*)d_in[24];
    const int*   et      = (const int*)d_in[25];
    float* out = (float*)d_out;

    static bool attr_set = false;
    if (!attr_set) {
        cudaFuncSetAttribute(k_topk, cudaFuncAttributeMaxDynamicSharedMemorySize,
                             N_ * (int)sizeof(uint32_t));
        attr_set = true;
    }

    k_init<<<(C_*MAT_ + 255)/256, 256>>>(Wself, Wrel);
    k_norm<<<C_, 256>>>(s_sc, r_sc);

    for (int t = 0; t < T_; t++) {
        int par = t & 1;   // input parity; updated Q goes to par^1
        k_scores<<<2500, 256>>>(x, mask, s_sc, r_sc, t);
        k_topk<<<C_, 1024, N_ * sizeof(uint32_t)>>>();
        k_zt<<<dim3(FO_, C_), 64>>>(x, t);
        k_cell1<<<dim3(8, 8, 2*C_), 256>>>(sWz, sUz, sbz, sWr, sUr, sbr,
                                           rWz, rUz, rbz, rWr, rUr, rbr, par);
        k_cell2<<<dim3(8, 8, C_), 256>>>(sWh, sUh, sbh, rWh, rUh, rbh, par);
        k_biggemm<<<dim3((N_ + 127)/128, FO_/128, C_), 256>>>(x, out, t, par ^ 1);
        k_zero_deg<<<(R_*N_ + 255)/256, 256>>>();
        k_count<<<(E_ + 255)/256, 256>>>(ei, et, t);
        k_dis<<<(R_*N_ + 255)/256, 256>>>();
        k_agg<<<(E_*32 + 255)/256, 256>>>(ei, et, out, t);
        k_relu<<<(N_*256/4 + 255)/256, 256>>>(out, t);
    }
}

// round 3
// speedup vs baseline: 3.0051x; 1.8088x over previous
#include <cuda_runtime.h>
#include <math.h>
#include <stdint.h>

#define T_ 3
#define N_ 20000
#define F_ 256
#define FO_ 256
#define E_ 320000
#define R_ 4
#define C_ 5            // cells: 0 = self, 1..4 = relations
#define MAT_ (F_*FO_)   // 65536

// ---------------- scratch (static device globals; no allocs allowed) ----------------
__device__ float g_scores[C_*N_];
__device__ float g_vals  [C_*FO_];
__device__ int   g_tidx  [C_*FO_];
__device__ float g_zt    [C_*MAT_];
__device__ float g_upd   [C_*MAT_];
__device__ float g_rst   [C_*MAT_];
__device__ float g_Q  [2][C_*MAT_];
__device__ float g_Y     [R_*N_*FO_]; // xt @ Qr[r], layout [r][n][f]
__device__ int   g_degI  [R_*N_];
__device__ float g_dis   [R_*N_];
__device__ float g_denom [C_];
// CSR-by-destination-row scratch
__device__ int      g_cnt [N_];
__device__ int      g_off [N_+1];
__device__ int      g_fill[N_];
__device__ uint32_t g_epack[E_];   // (col << 2) | relation

__device__ __forceinline__ uint32_t f2key(float f) {
    uint32_t u = __float_as_uint(f);
    return (u & 0x80000000u) ? ~u : (u | 0x80000000u);
}
__device__ __forceinline__ float key2f(uint32_t k) {
    return (k & 0x80000000u) ? __uint_as_float(k & 0x7FFFFFFFu) : __uint_as_float(~k);
}
__device__ __forceinline__ float cvt_tf32(float f) {
    uint32_t r;
    asm("cvt.rna.tf32.f32 %0, %1;" : "=r"(r) : "f"(f));
    return __uint_as_float(r);
}

// ---------------- init ----------------
__global__ void k_init(const float* __restrict__ Wself, const float* __restrict__ Wrel) {
    int i = blockIdx.x * blockDim.x + threadIdx.x;
    if (i < C_*MAT_) {
        int c = i / MAT_;
        int off = i - c*MAT_;
        g_Q[0][i] = (c == 0) ? Wself[off] : Wrel[(c-1)*MAT_ + off];
    }
}

__global__ void k_norm(const float* __restrict__ s_sc, const float* __restrict__ r_sc) {
    int c = blockIdx.x;
    const float* sc = (c == 0) ? s_sc : r_sc + (c-1)*F_;
    float v = sc[threadIdx.x];
    __shared__ float red[256];
    red[threadIdx.x] = v * v;
    __syncthreads();
    for (int o = 128; o > 0; o >>= 1) {
        if (threadIdx.x < o) red[threadIdx.x] += red[threadIdx.x + o];
        __syncthreads();
    }
    if (threadIdx.x == 0) g_denom[c] = sqrtf(red[0]) + 1e-8f;
}

// ---------------- scores ----------------
__global__ __launch_bounds__(256) void k_scores(const float* __restrict__ x,
                                                const float* __restrict__ mask,
                                                const float* __restrict__ s_sc,
                                                const float* __restrict__ r_sc, int t) {
    __shared__ float sc[C_][F_];
    for (int i = threadIdx.x; i < C_*F_; i += blockDim.x) {
        int c = i / F_, f = i - c*F_;
        sc[c][f] = (c == 0) ? s_sc[f] : r_sc[(c-1)*F_ + f];
    }
    __syncthreads();
    int warp = threadIdx.x >> 5, lane = threadIdx.x & 31;
    int n = blockIdx.x * 8 + warp;
    if (n >= N_) return;
    const float* xr = x + ((size_t)t*N_ + n) * F_;
    float acc[C_] = {0.f, 0.f, 0.f, 0.f, 0.f};
    #pragma unroll
    for (int q = 0; q < 8; q++) {
        float xv = xr[lane + q*32];
        #pragma unroll
        for (int c = 0; c < C_; c++) acc[c] += xv * sc[c][lane + q*32];
    }
    #pragma unroll
    for (int c = 0; c < C_; c++) {
        float v = acc[c];
        for (int o = 16; o > 0; o >>= 1) v += __shfl_down_sync(0xffffffffu, v, o);
        if (lane == 0) g_scores[c*N_ + n] = v / g_denom[c] + mask[(size_t)t*N_ + n];
    }
}

// ---------------- top-256 via radix select + bitonic sort ----------------
extern __shared__ uint32_t s_keys[];
__global__ __launch_bounds__(1024) void k_topk() {
    __shared__ uint32_t hist[256];
    __shared__ uint32_t selKey[256];
    __shared__ int      selIdx[256];
    __shared__ uint32_t s_prefix;
    __shared__ int      s_remaining, s_eqCount, s_idxTh, s_cnt;

    int c = blockIdx.x;
    int tid = threadIdx.x;

    for (int i = tid; i < N_; i += 1024)
        s_keys[i] = f2key(g_scores[c*N_ + i]);
    if (tid == 0) { s_prefix = 0u; s_remaining = FO_; s_idxTh = 0x7FFFFFFF; }
    __syncthreads();

    #pragma unroll
    for (int pass = 3; pass >= 0; pass--) {
        int shift = pass * 8;
        if (tid < 256) hist[tid] = 0;
        __syncthreads();
        uint32_t prefix = s_prefix;
        uint32_t pmask = (pass == 3) ? 0u : (0xFFFFFFFFu << (shift + 8));
        for (int i = tid; i < N_; i += 1024) {
            uint32_t k = s_keys[i];
            if ((k & pmask) == (prefix & pmask))
                atomicAdd(&hist[(k >> shift) & 0xFF], 1u);
        }
        __syncthreads();
        if (tid == 0) {
            int rem = s_remaining;
            uint32_t pfx = s_prefix;
            for (int b = 255; b >= 0; b--) {
                int cnt = (int)hist[b];
                if (cnt >= rem) {
                    pfx |= ((uint32_t)b) << shift;
                    if (pass == 0) s_eqCount = cnt;
                    break;
                }
                rem -= cnt;
            }
            s_remaining = rem;
            s_prefix = pfx;
        }
        __syncthreads();
    }
    uint32_t kth = s_prefix;
    int need = s_remaining;

    if (need < s_eqCount) {
        if (tid == 0) { s_prefix = 0u; s_remaining = need; }
        __syncthreads();
        #pragma unroll
        for (int pass = 1; pass >= 0; pass--) {
            int shift = pass * 8;
            if (tid < 256) hist[tid] = 0;
            __syncthreads();
            uint32_t prefixI = s_prefix;
            for (int i = tid; i < N_; i += 1024) {
                if (s_keys[i] == kth) {
                    if (pass == 1 || (((uint32_t)i >> 8) & 0xFF) == ((prefixI >> 8) & 0xFF))
                        atomicAdd(&hist[((uint32_t)i >> shift) & 0xFF], 1u);
                }
            }
            __syncthreads();
            if (tid == 0) {
                int rem = s_remaining;
                uint32_t pfx = s_prefix;
                for (int b = 0; b < 256; b++) {
                    int cnt = (int)hist[b];
                    if (cnt >= rem) { pfx |= ((uint32_t)b) << shift; break; }
                    rem -= cnt;
                }
                s_remaining = rem;
                s_prefix = pfx;
            }
            __syncthreads();
        }
        if (tid == 0) s_idxTh = (int)s_prefix;
    }
    if (tid == 0) s_cnt = 0;
    __syncthreads();
    int idxTh = s_idxTh;

    for (int i = tid; i < N_; i += 1024) {
        uint32_t k = s_keys[i];
        if (k > kth || (k == kth && i <= idxTh)) {
            int p = atomicAdd(&s_cnt, 1);
            selKey[p] = k;
            selIdx[p] = i;
        }
    }
    __syncthreads();

    for (int k = 2; k <= 256; k <<= 1) {
        for (int j = k >> 1; j > 0; j >>= 1) {
            if (tid < 256) {
                int ixj = tid ^ j;
                if (ixj > tid) {
                    bool desc = ((tid & k) == 0);
                    uint32_t ka = selKey[tid], kb = selKey[ixj];
                    int ia = selIdx[tid], ib = selIdx[ixj];
                    bool aGreater = (ka > kb) || (ka == kb && ia < ib);
                    bool doswap = desc ? !aGreater : aGreater;
                    if (doswap) {
                        selKey[tid] = kb; selKey[ixj] = ka;
                        selIdx[tid] = ib; selIdx[ixj] = ia;
                    }
                }
            }
            __syncthreads();
        }
    }

    if (tid < 256) {
        g_vals[c*FO_ + tid] = key2f(selKey[tid]);
        g_tidx[c*FO_ + tid] = selIdx[tid];
    }
}

// ---------------- zt ----------------
__global__ void k_zt(const float* __restrict__ x, int t) {
    int c = blockIdx.y, j = blockIdx.x;
    int idx = g_tidx[c*FO_ + j];
    float tv = tanhf(g_vals[c*FO_ + j]);
    const float4* xr = (const float4*)(x + ((size_t)t*N_ + idx) * F_);
    float4 v = xr[threadIdx.x];
    v.x *= tv; v.y *= tv; v.z *= tv; v.w *= tv;
    ((float4*)(g_zt + (size_t)(c*FO_ + j) * F_))[threadIdx.x] = v;
}

// ---------------- cell stage 1 ----------------
__global__ __launch_bounds__(256) void k_cell1(
    const float* sWz, const float* sUz, const float* sbz,
    const float* sWr, const float* sUr, const float* sbr,
    const float* rWz, const float* rUz, const float* rbz,
    const float* rWr, const float* rUr, const float* rbr, int par) {
    int o = blockIdx.z & 1, c = blockIdx.z >> 1;
    const float *W, *U, *B;
    if (o == 0) { W = c ? rWz + (c-1)*MAT_ : sWz; U = c ? rUz + (c-1)*MAT_ : sUz; B = c ? rbz + (c-1)*MAT_ : sbz; }
    else        { W = c ? rWr + (c-1)*MAT_ : sWr; U = c ? rUr + (c-1)*MAT_ : sUr; B = c ? rbr + (c-1)*MAT_ : sbr; }
    const float* Z  = g_zt + c*MAT_;
    const float* Qm = g_Q[par] + c*MAT_;
    float* OUT = (o == 0 ? g_upd : g_rst) + c*MAT_;

    __shared__ float Wt[32][33], Ut[32][33], Zt[32][33], Qt[32][33];
    int tid = threadIdx.x;
    int ty = tid >> 4, tx = tid & 15;
    int i0 = blockIdx.y * 32, j0 = blockIdx.x * 32;
    int lr = tid >> 3, lc = (tid & 7) * 4;
    float a00 = 0.f, a01 = 0.f, a10 = 0.f, a11 = 0.f;
    for (int kb = 0; kb < 256; kb += 32) {
        float4 w4 = *(const float4*)(W  + (size_t)(i0+lr)*256 + kb + lc);
        float4 u4 = *(const float4*)(U  + (size_t)(i0+lr)*256 + kb + lc);
        float4 z4 = *(const float4*)(Z  + (size_t)(j0+lr)*256 + kb + lc);
        float4 q4 = *(const float4*)(Qm + (size_t)(kb+lr)*256 + j0 + lc);
        Wt[lr][lc]=w4.x; Wt[lr][lc+1]=w4.y; Wt[lr][lc+2]=w4.z; Wt[lr][lc+3]=w4.w;
        Ut[lr][lc]=u4.x; Ut[lr][lc+1]=u4.y; Ut[lr][lc+2]=u4.z; Ut[lr][lc+3]=u4.w;
        Zt[lr][lc]=z4.x; Zt[lr][lc+1]=z4.y; Zt[lr][lc+2]=z4.z; Zt[lr][lc+3]=z4.w;
        Qt[lr][lc]=q4.x; Qt[lr][lc+1]=q4.y; Qt[lr][lc+2]=q4.z; Qt[lr][lc+3]=q4.w;
        __syncthreads();
        #pragma unroll
        for (int kk = 0; kk < 32; kk++) {
            float w0 = Wt[ty*2][kk],   w1 = Wt[ty*2+1][kk];
            float u0 = Ut[ty*2][kk],   u1 = Ut[ty*2+1][kk];
            float z0 = Zt[tx*2][kk],   z1 = Zt[tx*2+1][kk];
            float q0 = Qt[kk][tx*2],   q1 = Qt[kk][tx*2+1];
            a00 += w0*z0 + u0*q0;  a01 += w0*z1 + u0*q1;
            a10 += w1*z0 + u1*q0;  a11 += w1*z1 + u1*q1;
        }
        __syncthreads();
    }
    int i = i0 + ty*2, j = j0 + tx*2;
    OUT[(size_t)i*256 + j]         = 1.f/(1.f+expf(-(a00 + B[(size_t)i*256 + j])));
    OUT[(size_t)i*256 + j + 1]     = 1.f/(1.f+expf(-(a01 + B[(size_t)i*256 + j + 1])));
    OUT[(size_t)(i+1)*256 + j]     = 1.f/(1.f+expf(-(a10 + B[(size_t)(i+1)*256 + j])));
    OUT[(size_t)(i+1)*256 + j + 1] = 1.f/(1.f+expf(-(a11 + B[(size_t)(i+1)*256 + j + 1])));
}

// ---------------- cell stage 2 ----------------
__global__ __launch_bounds__(256) void k_cell2(
    const float* sWh, const float* sUh, const float* sbh,
    const float* rWh, const float* rUh, const float* rbh, int par) {
    int c = blockIdx.z;
    const float* W = c ? rWh + (c-1)*MAT_ : sWh;
    const float* U = c ? rUh + (c-1)*MAT_ : sUh;
    const float* B = c ? rbh + (c-1)*MAT_ : sbh;
    const float* Z   = g_zt  + c*MAT_;
    const float* Qin = g_Q[par] + c*MAT_;
    const float* RST = g_rst + c*MAT_;
    const float* UPD = g_upd + c*MAT_;
    float* Qout = g_Q[par ^ 1] + c*MAT_;

    __shared__ float Wt[32][33], Ut[32][33], Zt[32][33], Qt[32][33];
    int tid = threadIdx.x;
    int ty = tid >> 4, tx = tid & 15;
    int i0 = blockIdx.y * 32, j0 = blockIdx.x * 32;
    int lr = tid >> 3, lc = (tid & 7) * 4;
    float a00 = 0.f, a01 = 0.f, a10 = 0.f, a11 = 0.f;
    for (int kb = 0; kb < 256; kb += 32) {
        float4 w4 = *(const float4*)(W   + (size_t)(i0+lr)*256 + kb + lc);
        float4 u4 = *(const float4*)(U   + (size_t)(i0+lr)*256 + kb + lc);
        float4 z4 = *(const float4*)(Z   + (size_t)(j0+lr)*256 + kb + lc);
        float4 q4 = *(const float4*)(Qin + (size_t)(kb+lr)*256 + j0 + lc);
        float4 r4 = *(const float4*)(RST + (size_t)(kb+lr)*256 + j0 + lc);
        Wt[lr][lc]=w4.x; Wt[lr][lc+1]=w4.y; Wt[lr][lc+2]=w4.z; Wt[lr][lc+3]=w4.w;
        Ut[lr][lc]=u4.x; Ut[lr][lc+1]=u4.y; Ut[lr][lc+2]=u4.z; Ut[lr][lc+3]=u4.w;
        Zt[lr][lc]=z4.x; Zt[lr][lc+1]=z4.y; Zt[lr][lc+2]=z4.z; Zt[lr][lc+3]=z4.w;
        Qt[lr][lc]=q4.x*r4.x; Qt[lr][lc+1]=q4.y*r4.y; Qt[lr][lc+2]=q4.z*r4.z; Qt[lr][lc+3]=q4.w*r4.w;
        __syncthreads();
        #pragma unroll
        for (int kk = 0; kk < 32; kk++) {
            float w0 = Wt[ty*2][kk],   w1 = Wt[ty*2+1][kk];
            float u0 = Ut[ty*2][kk],   u1 = Ut[ty*2+1][kk];
            float z0 = Zt[tx*2][kk],   z1 = Zt[tx*2+1][kk];
            float q0 = Qt[kk][tx*2],   q1 = Qt[kk][tx*2+1];
            a00 += w0*z0 + u0*q0;  a01 += w0*z1 + u0*q1;
            a10 += w1*z0 + u1*q0;  a11 += w1*z1 + u1*q1;
        }
        __syncthreads();
    }
    int i = i0 + ty*2, j = j0 + tx*2;
    #pragma unroll
    for (int a = 0; a < 2; a++) {
        #pragma unroll
        for (int b = 0; b < 2; b++) {
            float acc = (a==0) ? (b==0?a00:a01) : (b==0?a10:a11);
            size_t ij = (size_t)(i+a)*256 + (j+b);
            float h = tanhf(acc + B[ij]);
            float u = UPD[ij];
            Qout[ij] = (1.f - u) * Qin[ij] + u * h;
        }
    }
}

// ---------------- big GEMM via TF32 tensor cores ----------------
// x_t[20000,256] @ Q_c[256,256]; 128x128 block tile, BK=16, 8 warps, 32x64 warp tile
__global__ __launch_bounds__(256) void k_biggemm_tf32(const float* __restrict__ x,
                                                      float* __restrict__ out, int t, int qsel) {
    int c = blockIdx.z;
    const float* Bm = g_Q[qsel] + c*MAT_;
    float* dst = (c == 0) ? out + (size_t)t*N_*FO_ : g_Y + (size_t)(c-1)*N_*FO_;
    int m0 = blockIdx.x * 128;
    int n0 = blockIdx.y * 128;

    __shared__ float As[16][132];   // [k][m]
    __shared__ float Bs[16][132];   // [k][n]
    int tid = threadIdx.x, wid = tid >> 5, lane = tid & 31;
    int wm = wid >> 1, wn = wid & 1;       // warp coords: 4 x 2
    int grp = lane >> 2, tg = lane & 3;

    float d[2][8][4];
    #pragma unroll
    for (int mt = 0; mt < 2; mt++)
        #pragma unroll
        for (int nt = 0; nt < 8; nt++)
            #pragma unroll
            for (int q = 0; q < 4; q++) d[mt][nt][q] = 0.f;

    const float* Ag = x + (size_t)t*N_*F_;
    int ar = tid >> 2, akc = (tid & 3) * 4;
    int bkr = tid >> 4, bnc = (tid & 15) * 4;

    for (int kb = 0; kb < F_; kb += 16) {
        #pragma unroll
        for (int h = 0; h < 2; h++) {
            int row = m0 + ar + h*64;
            float4 a4 = make_float4(0.f, 0.f, 0.f, 0.f);
            if (row < N_)
                a4 = *(const float4*)(Ag + (size_t)row*F_ + kb + akc);
            As[akc  ][ar + h*64] = cvt_tf32(a4.x);
            As[akc+1][ar + h*64] = cvt_tf32(a4.y);
            As[akc+2][ar + h*64] = cvt_tf32(a4.z);
            As[akc+3][ar + h*64] = cvt_tf32(a4.w);
        }
        #pragma unroll
        for (int h = 0; h < 2; h++) {
            float4 b4 = *(const float4*)(Bm + (size_t)(kb + bkr)*FO_ + n0 + bnc + h*64);
            Bs[bkr][bnc + h*64    ] = cvt_tf32(b4.x);
            Bs[bkr][bnc + h*64 + 1] = cvt_tf32(b4.y);
            Bs[bkr][bnc + h*64 + 2] = cvt_tf32(b4.z);
            Bs[bkr][bnc + h*64 + 3] = cvt_tf32(b4.w);
        }
        __syncthreads();
        #pragma unroll
        for (int kc = 0; kc < 2; kc++) {
            int k0 = kc * 8;
            uint32_t a[2][4];
            #pragma unroll
            for (int mt = 0; mt < 2; mt++) {
                int mb = wm*32 + mt*16;
                a[mt][0] = __float_as_uint(As[k0 + tg    ][mb + grp    ]);
                a[mt][1] = __float_as_uint(As[k0 + tg    ][mb + grp + 8]);
                a[mt][2] = __float_as_uint(As[k0 + tg + 4][mb + grp    ]);
                a[mt][3] = __float_as_uint(As[k0 + tg + 4][mb + grp + 8]);
            }
            #pragma unroll
            for (int nt = 0; nt < 8; nt++) {
                int nb = wn*64 + nt*8;
                uint32_t b0 = __float_as_uint(Bs[k0 + tg    ][nb + grp]);
                uint32_t b1 = __float_as_uint(Bs[k0 + tg + 4][nb + grp]);
                #pragma unroll
                for (int mt = 0; mt < 2; mt++) {
                    asm volatile(
                        "mma.sync.aligned.m16n8k8.row.col.f32.tf32.tf32.f32 "
                        "{%0,%1,%2,%3}, {%4,%5,%6,%7}, {%8,%9}, {%0,%1,%2,%3};"
                        : "+f"(d[mt][nt][0]), "+f"(d[mt][nt][1]),
                          "+f"(d[mt][nt][2]), "+f"(d[mt][nt][3])
                        : "r"(a[mt][0]), "r"(a[mt][1]), "r"(a[mt][2]), "r"(a[mt][3]),
                          "r"(b0), "r"(b1));
                }
            }
        }
        __syncthreads();
    }
    #pragma unroll
    for (int mt = 0; mt < 2; mt++) {
        #pragma unroll
        for (int nt = 0; nt < 8; nt++) {
            int r0 = m0 + wm*32 + mt*16 + grp;
            int col = n0 + wn*64 + nt*8 + 2*tg;
            if (r0 < N_)
                *(float2*)&dst[(size_t)r0*FO_ + col] = make_float2(d[mt][nt][0], d[mt][nt][1]);
            int r1 = r0 + 8;
            if (r1 < N_)
                *(float2*)&dst[(size_t)r1*FO_ + col] = make_float2(d[mt][nt][2], d[mt][nt][3]);
        }
    }
}

// ---------------- edges: CSR by destination row ----------------
__global__ void k_zero() {
    int i = blockIdx.x * blockDim.x + threadIdx.x;
    if (i < R_*N_) g_degI[i] = 0;
    if (i < N_) g_cnt[i] = 0;
}
__global__ void k_edge(const int* __restrict__ ei, const int* __restrict__ et, int t) {
    int e = blockIdx.x * blockDim.x + threadIdx.x;
    if (e >= E_) return;
    int row = ei[(size_t)t*2*E_ + e];
    int r   = et[(size_t)t*E_ + e];
    atomicAdd(&g_degI[r*N_ + row], 1);
    atomicAdd(&g_cnt[row], 1);
}
__global__ void k_dis() {
    int i = blockIdx.x * blockDim.x + threadIdx.x;
    if (i >= R_*N_) return;
    int d = g_degI[i];
    g_dis[i] = (d > 0) ? (1.f / sqrtf((float)d)) : 0.f;
}
// single block: exclusive prefix sum of g_cnt -> g_off; zero g_fill
__global__ __launch_bounds__(1024) void k_scan() {
    __shared__ int part[1024];
    int tid = threadIdx.x;
    const int CH = (N_ + 1023) / 1024;   // 20
    int base = tid * CH;
    int s = 0;
    for (int i = 0; i < CH; i++) {
        int idx = base + i;
        if (idx < N_) s += g_cnt[idx];
    }
    part[tid] = s;
    __syncthreads();
    for (int o = 1; o < 1024; o <<= 1) {
        int v = (tid >= o) ? part[tid - o] : 0;
        __syncthreads();
        part[tid] += v;
        __syncthreads();
    }
    int run = (tid == 0) ? 0 : part[tid - 1];
    for (int i = 0; i < CH; i++) {
        int idx = base + i;
        if (idx < N_) {
            g_off[idx] = run;
            run += g_cnt[idx];
            g_fill[idx] = 0;
        }
    }
    if (tid == 0) g_off[N_] = E_;
}
__global__ void k_scatter(const int* __restrict__ ei, const int* __restrict__ et, int t) {
    int e = blockIdx.x * blockDim.x + threadIdx.x;
    if (e >= E_) return;
    int row = ei[(size_t)t*2*E_ + e];
    int col = ei[(size_t)t*2*E_ + E_ + e];
    int r   = et[(size_t)t*E_ + e];
    int pos = g_off[row] + atomicAdd(&g_fill[row], 1);
    g_epack[pos] = ((uint32_t)col << 2) | (uint32_t)r;
}
// one warp per destination row: gather msgs, add gemm output, relu, single write
__global__ __launch_bounds__(256) void k_agg_csr(float* __restrict__ out, int t) {
    int warp = threadIdx.x >> 5, lane = threadIdx.x & 31;
    int row = blockIdx.x * 8 + warp;
    if (row >= N_) return;
    float disrow[R_];
    #pragma unroll
    for (int r = 0; r < R_; r++) disrow[r] = g_dis[r*N_ + row];
    float4 a0 = make_float4(0.f, 0.f, 0.f, 0.f);
    float4 a1 = make_float4(0.f, 0.f, 0.f, 0.f);
    int beg = g_off[row], end = g_off[row + 1];
    for (int p = beg; p < end; p++) {
        uint32_t pk = g_epack[p];
        int r = pk & 3;
        int col = pk >> 2;
        float norm = disrow[r] * g_dis[r*N_ + col];
        if (norm != 0.f) {
            const float4* src = (const float4*)(g_Y + ((size_t)r*N_ + col) * FO_);
            float4 v0 = src[lane];
            float4 v1 = src[lane + 32];
            a0.x += v0.x*norm; a0.y += v0.y*norm; a0.z += v0.z*norm; a0.w += v0.w*norm;
            a1.x += v1.x*norm; a1.y += v1.y*norm; a1.z += v1.z*norm; a1.w += v1.w*norm;
        }
    }
    float4* dst = (float4*)(out + (size_t)t*N_*FO_ + (size_t)row*FO_);
    float4 o0 = dst[lane];
    float4 o1 = dst[lane + 32];
    o0.x = fmaxf(o0.x + a0.x, 0.f); o0.y = fmaxf(o0.y + a0.y, 0.f);
    o0.z = fmaxf(o0.z + a0.z, 0.f); o0.w = fmaxf(o0.w + a0.w, 0.f);
    o1.x = fmaxf(o1.x + a1.x, 0.f); o1.y = fmaxf(o1.y + a1.y, 0.f);
    o1.z = fmaxf(o1.z + a1.z, 0.f); o1.w = fmaxf(o1.w + a1.w, 0.f);
    dst[lane] = o0;
    dst[lane + 32] = o1;
}

// ---------------- launcher ----------------
extern "C" void kernel_launch(void* const* d_in, const int* in_sizes, int n_in,
                              void* d_out, int out_size) {
    const float* x       = (const float*)d_in[0];
    const float* mask    = (const float*)d_in[1];
    const float* Wself   = (const float*)d_in[2];
    const float* Wrel    = (const float*)d_in[3];
    const float* sWz     = (const float*)d_in[4];
    const float* sUz     = (const float*)d_in[5];
    const float* sbz     = (const float*)d_in[6];
    const float* sWr     = (const float*)d_in[7];
    const float* sUr     = (const float*)d_in[8];
    const float* sbr     = (const float*)d_in[9];
    const float* sWh     = (const float*)d_in[10];
    const float* sUh     = (const float*)d_in[11];
    const float* sbh     = (const float*)d_in[12];
    const float* s_sc    = (const float*)d_in[13];
    const float* rWz     = (const float*)d_in[14];
    const float* rUz     = (const float*)d_in[15];
    const float* rbz     = (const float*)d_in[16];
    const float* rWr     = (const float*)d_in[17];
    const float* rUr     = (const float*)d_in[18];
    const float* rbr     = (const float*)d_in[19];
    const float* rWh     = (const float*)d_in[20];
    const float* rUh     = (const float*)d_in[21];
    const float* rbh     = (const float*)d_in[22];
    const float* r_sc    = (const float*)d_in[23];
    const int*   ei      = (const int*)d_in[24];
    const int*   et      = (const int*)d_in[25];
    float* out = (float*)d_out;

    static bool attr_set = false;
    if (!attr_set) {
        cudaFuncSetAttribute(k_topk, cudaFuncAttributeMaxDynamicSharedMemorySize,
                             N_ * (int)sizeof(uint32_t));
        attr_set = true;
    }

    k_init<<<(C_*MAT_ + 255)/256, 256>>>(Wself, Wrel);
    k_norm<<<C_, 256>>>(s_sc, r_sc);

    for (int t = 0; t < T_; t++) {
        int par = t & 1;
        k_scores<<<2500, 256>>>(x, mask, s_sc, r_sc, t);
        k_topk<<<C_, 1024, N_ * sizeof(uint32_t)>>>();
        k_zt<<<dim3(FO_, C_), 64>>>(x, t);
        k_cell1<<<dim3(8, 8, 2*C_), 256>>>(sWz, sUz, sbz, sWr, sUr, sbr,
                                           rWz, rUz, rbz, rWr, rUr, rbr, par);
        k_cell2<<<dim3(8, 8, C_), 256>>>(sWh, sUh, sbh, rWh, rUh, rbh, par);
        k_biggemm_tf32<<<dim3((N_ + 127)/128, FO_/128, C_), 256>>>(x, out, t, par ^ 1);
        k_zero<<<(R_*N_ + 255)/256, 256>>>();
        k_edge<<<(E_ + 255)/256, 256>>>(ei, et, t);
        k_dis<<<(R_*N_ + 255)/256, 256>>>();
        k_scan<<<1, 1024>>>();
        k_scatter<<<(E_ + 255)/256, 256>>>(ei, et, t);
        k_agg_csr<<<(N_ + 7)/8, 256>>>(out, t);
    }
}

// round 4
// speedup vs baseline: 3.5023x; 1.1654x over previous
#include <cuda_runtime.h>
#include <math.h>
#include <stdint.h>

#define T_ 3
#define N_ 20000
#define F_ 256
#define FO_ 256
#define E_ 320000
#define R_ 4
#define C_ 5            // cells: 0 = self, 1..4 = relations
#define MAT_ (F_*FO_)   // 65536

// ---------------- scratch (static device globals; no allocs allowed) ----------------
__device__ float g_scores[T_*C_*N_];
__device__ float g_vals  [T_*C_*FO_];
__device__ int   g_tidx  [T_*C_*FO_];
__device__ float g_zt    [T_*C_*MAT_];
__device__ float g_upd   [C_*MAT_];
__device__ float g_rst   [C_*MAT_];
__device__ float g_Q  [2][C_*MAT_];
__device__ float g_Y     [R_*N_*FO_];      // xt @ Qr[r], layout [r][n][f]
__device__ int   g_degI  [T_*R_*N_];
__device__ float g_dis   [T_*R_*N_];
__device__ float g_denom [C_];
// CSR-by-destination-row scratch (per t)
__device__ int      g_cnt [T_*N_];
__device__ int      g_off [T_*(N_+1)];
__device__ int      g_fill[T_*N_];
__device__ uint32_t g_epack[T_*E_];        // (col << 2) | relation

__device__ __forceinline__ uint32_t f2key(float f) {
    uint32_t u = __float_as_uint(f);
    return (u & 0x80000000u) ? ~u : (u | 0x80000000u);
}
__device__ __forceinline__ float key2f(uint32_t k) {
    return (k & 0x80000000u) ? __uint_as_float(k & 0x7FFFFFFFu) : __uint_as_float(~k);
}
__device__ __forceinline__ float cvt_tf32(float f) {
    uint32_t r;
    asm("cvt.rna.tf32.f32 %0, %1;" : "=r"(r) : "f"(f));
    return __uint_as_float(r);
}
__device__ __forceinline__ float sigmoidf_(float v) { return 1.f / (1.f + expf(-v)); }

__device__ __forceinline__ void mma_tf32(float* d, const uint32_t* a, uint32_t b0, uint32_t b1) {
    asm volatile(
        "mma.sync.aligned.m16n8k8.row.col.f32.tf32.tf32.f32 "
        "{%0,%1,%2,%3}, {%4,%5,%6,%7}, {%8,%9}, {%0,%1,%2,%3};"
        : "+f"(d[0]), "+f"(d[1]), "+f"(d[2]), "+f"(d[3])
        : "r"(a[0]), "r"(a[1]), "r"(a[2]), "r"(a[3]), "r"(b0), "r"(b1));
}

// ---------------- init ----------------
__global__ void k_init(const float* __restrict__ Wself, const float* __restrict__ Wrel) {
    int i = blockIdx.x * blockDim.x + threadIdx.x;
    if (i < C_*MAT_) {
        int c = i / MAT_;
        int off = i - c*MAT_;
        g_Q[0][i] = (c == 0) ? Wself[off] : Wrel[(c-1)*MAT_ + off];
    }
}

__global__ void k_norm(const float* __restrict__ s_sc, const float* __restrict__ r_sc) {
    int c = blockIdx.x;
    const float* sc = (c == 0) ? s_sc : r_sc + (c-1)*F_;
    float v = sc[threadIdx.x];
    __shared__ float red[256];
    red[threadIdx.x] = v * v;
    __syncthreads();
    for (int o = 128; o > 0; o >>= 1) {
        if (threadIdx.x < o) red[threadIdx.x] += red[threadIdx.x + o];
        __syncthreads();
    }
    if (threadIdx.x == 0) g_denom[c] = sqrtf(red[0]) + 1e-8f;
}

// ---------------- scores for ALL t ----------------
__global__ __launch_bounds__(256) void k_scores(const float* __restrict__ x,
                                                const float* __restrict__ mask,
                                                const float* __restrict__ s_sc,
                                                const float* __restrict__ r_sc) {
    int t = blockIdx.y;
    __shared__ float sc[C_][F_];
    for (int i = threadIdx.x; i < C_*F_; i += blockDim.x) {
        int c = i / F_, f = i - c*F_;
        sc[c][f] = (c == 0) ? s_sc[f] : r_sc[(c-1)*F_ + f];
    }
    __syncthreads();
    int warp = threadIdx.x >> 5, lane = threadIdx.x & 31;
    int n = blockIdx.x * 8 + warp;
    if (n >= N_) return;
    const float* xr = x + ((size_t)t*N_ + n) * F_;
    float acc[C_] = {0.f, 0.f, 0.f, 0.f, 0.f};
    #pragma unroll
    for (int q = 0; q < 8; q++) {
        float xv = xr[lane + q*32];
        #pragma unroll
        for (int c = 0; c < C_; c++) acc[c] += xv * sc[c][lane + q*32];
    }
    #pragma unroll
    for (int c = 0; c < C_; c++) {
        float v = acc[c];
        for (int o = 16; o > 0; o >>= 1) v += __shfl_down_sync(0xffffffffu, v, o);
        if (lane == 0)
            g_scores[(size_t)(t*C_ + c)*N_ + n] = v / g_denom[c] + mask[(size_t)t*N_ + n];
    }
}

// ---------------- top-256 of 20000, grid = T*C blocks, parallel bin scans ----------------
extern __shared__ uint32_t s_keys[];
__global__ __launch_bounds__(1024) void k_topk() {
    __shared__ int      hist[256];
    __shared__ int      sfx[256];
    __shared__ uint32_t selKey[256];
    __shared__ int      selIdx[256];
    __shared__ uint32_t s_prefix;
    __shared__ int      s_remaining, s_eqCount, s_idxTh, s_cnt;

    int tc = blockIdx.x;           // t*C + c
    int tid = threadIdx.x;
    const float* sc = g_scores + (size_t)tc * N_;

    if (tid < 256) hist[tid] = 0;
    if (tid == 0) { s_prefix = 0u; s_remaining = FO_; s_idxTh = 0x7FFFFFFF; s_eqCount = FO_; }
    __syncthreads();

    // load keys + MSB histogram in one sweep
    for (int i = tid; i < N_; i += 1024) {
        uint32_t k = f2key(sc[i]);
        s_keys[i] = k;
        atomicAdd(&hist[k >> 24], 1);
    }
    __syncthreads();

    // 4 MSB-first radix passes; bin selection via parallel suffix scan
    #pragma unroll
    for (int pass = 3; pass >= 0; pass--) {
        int shift = pass * 8;
        if (pass < 3) {
            if (tid < 256) hist[tid] = 0;
            __syncthreads();
            uint32_t prefix = s_prefix;
            uint32_t pmask = 0xFFFFFFFFu << (shift + 8);
            for (int i = tid; i < N_; i += 1024) {
                uint32_t k = s_keys[i];
                if ((k & pmask) == (prefix & pmask))
                    atomicAdd(&hist[(k >> shift) & 0xFF], 1);
            }
            __syncthreads();
        }
        // inclusive suffix sums over 256 bins
        if (tid < 256) sfx[tid] = hist[tid];
        __syncthreads();
        #pragma unroll
        for (int o = 1; o < 256; o <<= 1) {
            int v = 0;
            if (tid < 256) v = sfx[tid] + ((tid + o < 256) ? sfx[tid + o] : 0);
            __syncthreads();
            if (tid < 256) sfx[tid] = v;
            __syncthreads();
        }
        int rem = s_remaining;
        __syncthreads();
        if (tid < 256) {
            int s  = sfx[tid];
            int sn = (tid < 255) ? sfx[tid + 1] : 0;
            if (s >= rem && sn < rem) {          // unique winning bin
                s_prefix |= ((uint32_t)tid) << shift;
                s_remaining = rem - sn;
                if (pass == 0) s_eqCount = hist[tid];
            }
        }
        __syncthreads();
    }
    uint32_t kth = s_prefix;
    int need = s_remaining;

    // tie resolution (rare): need-th smallest index among key==kth, serial scans OK
    if (need < s_eqCount) {
        if (tid == 0) { s_prefix = 0u; s_remaining = need; }
        __syncthreads();
        #pragma unroll
        for (int pass = 1; pass >= 0; pass--) {
            int shift = pass * 8;
            if (tid < 256) hist[tid] = 0;
            __syncthreads();
            uint32_t prefixI = s_prefix;
            for (int i = tid; i < N_; i += 1024) {
                if (s_keys[i] == kth) {
                    if (pass == 1 || (((uint32_t)i >> 8) & 0xFF) == ((prefixI >> 8) & 0xFF))
                        atomicAdd(&hist[((uint32_t)i >> shift) & 0xFF], 1);
                }
            }
            __syncthreads();
            if (tid == 0) {
                int rem = s_remaining;
                uint32_t pfx = s_prefix;
                for (int b = 0; b < 256; b++) {
                    int cnt = hist[b];
                    if (cnt >= rem) { pfx |= ((uint32_t)b) << shift; break; }
                    rem -= cnt;
                }
                s_remaining = rem;
                s_prefix = pfx;
            }
            __syncthreads();
        }
        if (tid == 0) s_idxTh = (int)s_prefix;
    }
    if (tid == 0) s_cnt = 0;
    __syncthreads();
    int idxTh = s_idxTh;

    // compact winners
    for (int i = tid; i < N_; i += 1024) {
        uint32_t k = s_keys[i];
        if (k > kth || (k == kth && i <= idxTh)) {
            int p = atomicAdd(&s_cnt, 1);
            selKey[p] = k;
            selIdx[p] = i;
        }
    }
    __syncthreads();

    // bitonic sort 256: descending key, ascending index on tie
    for (int k = 2; k <= 256; k <<= 1) {
        for (int j = k >> 1; j > 0; j >>= 1) {
            if (tid < 256) {
                int ixj = tid ^ j;
                if (ixj > tid) {
                    bool desc = ((tid & k) == 0);
                    uint32_t ka = selKey[tid], kb = selKey[ixj];
                    int ia = selIdx[tid], ib = selIdx[ixj];
                    bool aGreater = (ka > kb) || (ka == kb && ia < ib);
                    bool doswap = desc ? !aGreater : aGreater;
                    if (doswap) {
                        selKey[tid] = kb; selKey[ixj] = ka;
                        selIdx[tid] = ib; selIdx[ixj] = ia;
                    }
                }
            }
            __syncthreads();
        }
    }

    if (tid < 256) {
        g_vals[(size_t)tc*FO_ + tid] = key2f(selKey[tid]);
        g_tidx[(size_t)tc*FO_ + tid] = selIdx[tid];
    }
}

// ---------------- zt for ALL t ----------------
__global__ void k_zt(const float* __restrict__ x) {
    int c = blockIdx.y, j = blockIdx.x, t = blockIdx.z;
    int tc = t*C_ + c;
    int idx = g_tidx[(size_t)tc*FO_ + j];
    float tv = tanhf(g_vals[(size_t)tc*FO_ + j]);
    const float4* xr = (const float4*)(x + ((size_t)t*N_ + idx) * F_);
    float4 v = xr[threadIdx.x];
    v.x *= tv; v.y *= tv; v.z *= tv; v.w *= tv;
    ((float4*)(g_zt + ((size_t)tc*FO_ + j) * F_))[threadIdx.x] = v;
}

// ================= TF32 cell GEMMs: 64x64 tile, 4 warps (2x2), warp tile 32x32 =====
// d[mt 2][nt 4][4]; K=512 fused: phase0 = W@zt (zt stored [n][k]), phase1 = U@Qmod ([k][n])

#define CELL_MMA_STEP()                                                         \
    _Pragma("unroll")                                                           \
    for (int kc = 0; kc < 2; kc++) {                                            \
        int k0 = kc * 8;                                                        \
        uint32_t afr[2][4];                                                     \
        _Pragma("unroll")                                                       \
        for (int mt = 0; mt < 2; mt++) {                                        \
            int mb = wm*32 + mt*16;                                             \
            afr[mt][0] = __float_as_uint(As[k0 + tg    ][mb + grp    ]);        \
            afr[mt][1] = __float_as_uint(As[k0 + tg    ][mb + grp + 8]);        \
            afr[mt][2] = __float_as_uint(As[k0 + tg + 4][mb + grp    ]);        \
            afr[mt][3] = __float_as_uint(As[k0 + tg + 4][mb + grp + 8]);        \
        }                                                                       \
        _Pragma("unroll")                                                       \
        for (int nt = 0; nt < 4; nt++) {                                        \
            int nb = wn*32 + nt*8;                                              \
            uint32_t b0 = __float_as_uint(Bs[k0 + tg    ][nb + grp]);           \
            uint32_t b1 = __float_as_uint(Bs[k0 + tg + 4][nb + grp]);           \
            _Pragma("unroll")                                                   \
            for (int mt = 0; mt < 2; mt++)                                      \
                mma_tf32(d[mt][nt], afr[mt], b0, b1);                           \
        }                                                                       \
    }

__global__ __launch_bounds__(128) void k_cell1_tf32(
    const float* sWz, const float* sUz, const float* sbz,
    const float* sWr, const float* sUr, const float* sbr,
    const float* rWz, const float* rUz, const float* rbz,
    const float* rWr, const float* rUr, const float* rbr, int par, int t) {
    int o = blockIdx.z & 1, c = blockIdx.z >> 1;
    const float *W, *U, *B;
    if (o == 0) { W = c ? rWz + (c-1)*MAT_ : sWz; U = c ? rUz + (c-1)*MAT_ : sUz; B = c ? rbz + (c-1)*MAT_ : sbz; }
    else        { W = c ? rWr + (c-1)*MAT_ : sWr; U = c ? rUr + (c-1)*MAT_ : sUr; B = c ? rbr + (c-1)*MAT_ : sbr; }
    const float* Z  = g_zt + (size_t)(t*C_ + c)*MAT_;
    const float* Qm = g_Q[par] + c*MAT_;
    float* OUT = (o == 0 ? g_upd : g_rst) + c*MAT_;

    __shared__ float As[16][68], Bs[16][68];
    int tid = threadIdx.x, lane = tid & 31, wid = tid >> 5;
    int wm = wid >> 1, wn = wid & 1;
    int grp = lane >> 2, tg = lane & 3;
    int i0 = blockIdx.y * 64, j0 = blockIdx.x * 64;

    float d[2][4][4];
    #pragma unroll
    for (int mt = 0; mt < 2; mt++)
        #pragma unroll
        for (int nt = 0; nt < 4; nt++)
            #pragma unroll
            for (int q = 0; q < 4; q++) d[mt][nt][q] = 0.f;

    int ar = tid >> 1, ac = (tid & 1) * 8;     // 64 rows x 16 k (transpose store)
    int qk = tid >> 3, qn = (tid & 7) * 8;     // 16 k x 64 n (direct store)

    // phase 0: W @ zt   (zt stored [n][k] -> transpose into Bs[k][n])
    for (int kb = 0; kb < 256; kb += 16) {
        float4 a4 = *(const float4*)(W + (size_t)(i0+ar)*256 + kb + ac);
        float4 a5 = *(const float4*)(W + (size_t)(i0+ar)*256 + kb + ac + 4);
        As[ac  ][ar]=cvt_tf32(a4.x); As[ac+1][ar]=cvt_tf32(a4.y);
        As[ac+2][ar]=cvt_tf32(a4.z); As[ac+3][ar]=cvt_tf32(a4.w);
        As[ac+4][ar]=cvt_tf32(a5.x); As[ac+5][ar]=cvt_tf32(a5.y);
        As[ac+6][ar]=cvt_tf32(a5.z); As[ac+7][ar]=cvt_tf32(a5.w);
        float4 b4 = *(const float4*)(Z + (size_t)(j0+ar)*256 + kb + ac);
        float4 b5 = *(const float4*)(Z + (size_t)(j0+ar)*256 + kb + ac + 4);
        Bs[ac  ][ar]=cvt_tf32(b4.x); Bs[ac+1][ar]=cvt_tf32(b4.y);
        Bs[ac+2][ar]=cvt_tf32(b4.z); Bs[ac+3][ar]=cvt_tf32(b4.w);
        Bs[ac+4][ar]=cvt_tf32(b5.x); Bs[ac+5][ar]=cvt_tf32(b5.y);
        Bs[ac+6][ar]=cvt_tf32(b5.z); Bs[ac+7][ar]=cvt_tf32(b5.w);
        __syncthreads();
        CELL_MMA_STEP();
        __syncthreads();
    }
    // phase 1: U @ Q   (Q stored [k][n] -> direct rows)
    for (int kb = 0; kb < 256; kb += 16) {
        float4 a4 = *(const float4*)(U + (size_t)(i0+ar)*256 + kb + ac);
        float4 a5 = *(const float4*)(U + (size_t)(i0+ar)*256 + kb + ac + 4);
        As[ac  ][ar]=cvt_tf32(a4.x); As[ac+1][ar]=cvt_tf32(a4.y);
        As[ac+2][ar]=cvt_tf32(a4.z); As[ac+3][ar]=cvt_tf32(a4.w);
        As[ac+4][ar]=cvt_tf32(a5.x); As[ac+5][ar]=cvt_tf32(a5.y);
        As[ac+6][ar]=cvt_tf32(a5.z); As[ac+7][ar]=cvt_tf32(a5.w);
        float4 b4 = *(const float4*)(Qm + (size_t)(kb+qk)*256 + j0 + qn);
        float4 b5 = *(const float4*)(Qm + (size_t)(kb+qk)*256 + j0 + qn + 4);
        Bs[qk][qn  ]=cvt_tf32(b4.x); Bs[qk][qn+1]=cvt_tf32(b4.y);
        Bs[qk][qn+2]=cvt_tf32(b4.z); Bs[qk][qn+3]=cvt_tf32(b4.w);
        Bs[qk][qn+4]=cvt_tf32(b5.x); Bs[qk][qn+5]=cvt_tf32(b5.y);
        Bs[qk][qn+6]=cvt_tf32(b5.z); Bs[qk][qn+7]=cvt_tf32(b5.w);
        __syncthreads();
        CELL_MMA_STEP();
        __syncthreads();
    }

    #pragma unroll
    for (int mt = 0; mt < 2; mt++) {
        #pragma unroll
        for (int nt = 0; nt < 4; nt++) {
            int r0 = i0 + wm*32 + mt*16 + grp;
            int col = j0 + wn*32 + nt*8 + 2*tg;
            float2 bi0 = *(const float2*)(B + (size_t)r0*256 + col);
            *(float2*)&OUT[(size_t)r0*256 + col] =
                make_float2(sigmoidf_(d[mt][nt][0] + bi0.x), sigmoidf_(d[mt][nt][1] + bi0.y));
            int r1 = r0 + 8;
            float2 bi1 = *(const float2*)(B + (size_t)r1*256 + col);
            *(float2*)&OUT[(size_t)r1*256 + col] =
                make_float2(sigmoidf_(d[mt][nt][2] + bi1.x), sigmoidf_(d[mt][nt][3] + bi1.y));
        }
    }
}

__global__ __launch_bounds__(128) void k_cell2_tf32(
    const float* sWh, const float* sUh, const float* sbh,
    const float* rWh, const float* rUh, const float* rbh, int par, int t) {
    int c = blockIdx.z;
    const float* W = c ? rWh + (c-1)*MAT_ : sWh;
    const float* U = c ? rUh + (c-1)*MAT_ : sUh;
    const float* B = c ? rbh + (c-1)*MAT_ : sbh;
    const float* Z   = g_zt + (size_t)(t*C_ + c)*MAT_;
    const float* Qin = g_Q[par] + c*MAT_;
    const float* RST = g_rst + c*MAT_;
    const float* UPD = g_upd + c*MAT_;
    float* Qout = g_Q[par ^ 1] + c*MAT_;

    __shared__ float As[16][68], Bs[16][68];
    int tid = threadIdx.x, lane = tid & 31, wid = tid >> 5;
    int wm = wid >> 1, wn = wid & 1;
    int grp = lane >> 2, tg = lane & 3;
    int i0 = blockIdx.y * 64, j0 = blockIdx.x * 64;

    float d[2][4][4];
    #pragma unroll
    for (int mt = 0; mt < 2; mt++)
        #pragma unroll
        for (int nt = 0; nt < 4; nt++)
            #pragma unroll
            for (int q = 0; q < 4; q++) d[mt][nt][q] = 0.f;

    int ar = tid >> 1, ac = (tid & 1) * 8;
    int qk = tid >> 3, qn = (tid & 7) * 8;

    for (int kb = 0; kb < 256; kb += 16) {
        float4 a4 = *(const float4*)(W + (size_t)(i0+ar)*256 + kb + ac);
        float4 a5 = *(const float4*)(W + (size_t)(i0+ar)*256 + kb + ac + 4);
        As[ac  ][ar]=cvt_tf32(a4.x); As[ac+1][ar]=cvt_tf32(a4.y);
        As[ac+2][ar]=cvt_tf32(a4.z); As[ac+3][ar]=cvt_tf32(a4.w);
        As[ac+4][ar]=cvt_tf32(a5.x); As[ac+5][ar]=cvt_tf32(a5.y);
        As[ac+6][ar]=cvt_tf32(a5.z); As[ac+7][ar]=cvt_tf32(a5.w);
        float4 b4 = *(const float4*)(Z + (size_t)(j0+ar)*256 + kb + ac);
        float4 b5 = *(const float4*)(Z + (size_t)(j0+ar)*256 + kb + ac + 4);
        Bs[ac  ][ar]=cvt_tf32(b4.x); Bs[ac+1][ar]=cvt_tf32(b4.y);
        Bs[ac+2][ar]=cvt_tf32(b4.z); Bs[ac+3][ar]=cvt_tf32(b4.w);
        Bs[ac+4][ar]=cvt_tf32(b5.x); Bs[ac+5][ar]=cvt_tf32(b5.y);
        Bs[ac+6][ar]=cvt_tf32(b5.z); Bs[ac+7][ar]=cvt_tf32(b5.w);
        __syncthreads();
        CELL_MMA_STEP();
        __syncthreads();
    }
    for (int kb = 0; kb < 256; kb += 16) {
        float4 a4 = *(const float4*)(U + (size_t)(i0+ar)*256 + kb + ac);
        float4 a5 = *(const float4*)(U + (size_t)(i0+ar)*256 + kb + ac + 4);
        As[ac  ][ar]=cvt_tf32(a4.x); As[ac+1][ar]=cvt_tf32(a4.y);
        As[ac+2][ar]=cvt_tf32(a4.z); As[ac+3][ar]=cvt_tf32(a4.w);
        As[ac+4][ar]=cvt_tf32(a5.x); As[ac+5][ar]=cvt_tf32(a5.y);
        As[ac+6][ar]=cvt_tf32(a5.z); As[ac+7][ar]=cvt_tf32(a5.w);
        float4 b4 = *(const float4*)(Qin + (size_t)(kb+qk)*256 + j0 + qn);
        float4 b5 = *(const float4*)(Qin + (size_t)(kb+qk)*256 + j0 + qn + 4);
        float4 r4 = *(const float4*)(RST + (size_t)(kb+qk)*256 + j0 + qn);
        float4 r5 = *(const float4*)(RST + (size_t)(kb+qk)*256 + j0 + qn + 4);
        Bs[qk][qn  ]=cvt_tf32(b4.x*r4.x); Bs[qk][qn+1]=cvt_tf32(b4.y*r4.y);
        Bs[qk][qn+2]=cvt_tf32(b4.z*r4.z); Bs[qk][qn+3]=cvt_tf32(b4.w*r4.w);
        Bs[qk][qn+4]=cvt_tf32(b5.x*r5.x); Bs[qk][qn+5]=cvt_tf32(b5.y*r5.y);
        Bs[qk][qn+6]=cvt_tf32(b5.z*r5.z); Bs[qk][qn+7]=cvt_tf32(b5.w*r5.w);
        __syncthreads();
        CELL_MMA_STEP();
        __syncthreads();
    }

    #pragma unroll
    for (int mt = 0; mt < 2; mt++) {
        #pragma unroll
        for (int nt = 0; nt < 4; nt++) {
            #pragma unroll
            for (int half = 0; half < 2; half++) {
                int r = i0 + wm*32 + mt*16 + grp + half*8;
                int col = j0 + wn*32 + nt*8 + 2*tg;
                float d0 = d[mt][nt][half*2], d1 = d[mt][nt][half*2 + 1];
                float2 bi = *(const float2*)(B + (size_t)r*256 + col);
                float2 up = *(const float2*)(UPD + (size_t)r*256 + col);
                float2 qi = *(const float2*)(Qin + (size_t)r*256 + col);
                float h0 = tanhf(d0 + bi.x), h1 = tanhf(d1 + bi.y);
                *(float2*)&Qout[(size_t)r*256 + col] =
                    make_float2((1.f - up.x)*qi.x + up.x*h0,
                                (1.f - up.y)*qi.y + up.y*h1);
            }
        }
    }
}

// ---------------- big GEMM via TF32 tensor cores (unchanged from R3) ----------------
__global__ __launch_bounds__(256) void k_biggemm_tf32(const float* __restrict__ x,
                                                      float* __restrict__ out, int t, int qsel) {
    int c = blockIdx.z;
    const float* Bm = g_Q[qsel] + c*MAT_;
    float* dst = (c == 0) ? out + (size_t)t*N_*FO_ : g_Y + (size_t)(c-1)*N_*FO_;
    int m0 = blockIdx.x * 128;
    int n0 = blockIdx.y * 128;

    __shared__ float As[16][132];
    __shared__ float Bs[16][132];
    int tid = threadIdx.x, wid = tid >> 5, lane = tid & 31;
    int wm = wid >> 1, wn = wid & 1;
    int grp = lane >> 2, tg = lane & 3;

    float d[2][8][4];
    #pragma unroll
    for (int mt = 0; mt < 2; mt++)
        #pragma unroll
        for (int nt = 0; nt < 8; nt++)
            #pragma unroll
            for (int q = 0; q < 4; q++) d[mt][nt][q] = 0.f;

    const float* Ag = x + (size_t)t*N_*F_;
    int ar = tid >> 2, akc = (tid & 3) * 4;
    int bkr = tid >> 4, bnc = (tid & 15) * 4;

    for (int kb = 0; kb < F_; kb += 16) {
        #pragma unroll
        for (int h = 0; h < 2; h++) {
            int row = m0 + ar + h*64;
            float4 a4 = make_float4(0.f, 0.f, 0.f, 0.f);
            if (row < N_)
                a4 = *(const float4*)(Ag + (size_t)row*F_ + kb + akc);
            As[akc  ][ar + h*64] = cvt_tf32(a4.x);
            As[akc+1][ar + h*64] = cvt_tf32(a4.y);
            As[akc+2][ar + h*64] = cvt_tf32(a4.z);
            As[akc+3][ar + h*64] = cvt_tf32(a4.w);
        }
        #pragma unroll
        for (int h = 0; h < 2; h++) {
            float4 b4 = *(const float4*)(Bm + (size_t)(kb + bkr)*FO_ + n0 + bnc + h*64);
            Bs[bkr][bnc + h*64    ] = cvt_tf32(b4.x);
            Bs[bkr][bnc + h*64 + 1] = cvt_tf32(b4.y);
            Bs[bkr][bnc + h*64 + 2] = cvt_tf32(b4.z);
            Bs[bkr][bnc + h*64 + 3] = cvt_tf32(b4.w);
        }
        __syncthreads();
        #pragma unroll
        for (int kc = 0; kc < 2; kc++) {
            int k0 = kc * 8;
            uint32_t a[2][4];
            #pragma unroll
            for (int mt = 0; mt < 2; mt++) {
                int mb = wm*32 + mt*16;
                a[mt][0] = __float_as_uint(As[k0 + tg    ][mb + grp    ]);
                a[mt][1] = __float_as_uint(As[k0 + tg    ][mb + grp + 8]);
                a[mt][2] = __float_as_uint(As[k0 + tg + 4][mb + grp    ]);
                a[mt][3] = __float_as_uint(As[k0 + tg + 4][mb + grp + 8]);
            }
            #pragma unroll
            for (int nt = 0; nt < 8; nt++) {
                int nb = wn*64 + nt*8;
                uint32_t b0 = __float_as_uint(Bs[k0 + tg    ][nb + grp]);
                uint32_t b1 = __float_as_uint(Bs[k0 + tg + 4][nb + grp]);
                #pragma unroll
                for (int mt = 0; mt < 2; mt++)
                    mma_tf32(d[mt][nt], a[mt], b0, b1);
            }
        }
        __syncthreads();
    }
    #pragma unroll
    for (int mt = 0; mt < 2; mt++) {
        #pragma unroll
        for (int nt = 0; nt < 8; nt++) {
            int r0 = m0 + wm*32 + mt*16 + grp;
            int col = n0 + wn*64 + nt*8 + 2*tg;
            if (r0 < N_)
                *(float2*)&dst[(size_t)r0*FO_ + col] = make_float2(d[mt][nt][0], d[mt][nt][1]);
            int r1 = r0 + 8;
            if (r1 < N_)
                *(float2*)&dst[(size_t)r1*FO_ + col] = make_float2(d[mt][nt][2], d[mt][nt][3]);
        }
    }
}

// ---------------- edges: CSR by destination row, ALL t upfront ----------------
__global__ void k_zeroE() {
    int i = blockIdx.x * blockDim.x + threadIdx.x;
    if (i < T_*R_*N_) g_degI[i] = 0;
    if (i < T_*N_) g_cnt[i] = 0;
}
__global__ void k_edge(const int* __restrict__ ei, const int* __restrict__ et) {
    int t = blockIdx.y;
    int e = blockIdx.x * blockDim.x + threadIdx.x;
    if (e >= E_) return;
    int row = ei[(size_t)t*2*E_ + e];
    int r   = et[(size_t)t*E_ + e];
    atomicAdd(&g_degI[(t*R_ + r)*N_ + row], 1);
    atomicAdd(&g_cnt[t*N_ + row], 1);
}
__global__ void k_dis() {
    int i = blockIdx.x * blockDim.x + threadIdx.x;
    if (i >= T_*R_*N_) return;
    int d = g_degI[i];
    g_dis[i] = (d > 0) ? (1.f / sqrtf((float)d)) : 0.f;
}
__global__ __launch_bounds__(1024) void k_scan() {
    __shared__ int part[1024];
    int t = blockIdx.x;
    const int* cnt = g_cnt + t*N_;
    int* off = g_off + t*(N_+1);
    int* fill = g_fill + t*N_;
    int tid = threadIdx.x;
    const int CH = (N_ + 1023) / 1024;
    int base = tid * CH;
    int s = 0;
    for (int i = 0; i < CH; i++) {
        int idx = base + i;
        if (idx < N_) s += cnt[idx];
    }
    part[tid] = s;
    __syncthreads();
    for (int o = 1; o < 1024; o <<= 1) {
        int v = (tid >= o) ? part[tid - o] : 0;
        __syncthreads();
        part[tid] += v;
        __syncthreads();
    }
    int run = (tid == 0) ? 0 : part[tid - 1];
    for (int i = 0; i < CH; i++) {
        int idx = base + i;
        if (idx < N_) {
            off[idx] = run;
            run += cnt[idx];
            fill[idx] = 0;
        }
    }
    if (tid == 0) off[N_] = E_;
}
__global__ void k_scatter(const int* __restrict__ ei, const int* __restrict__ et) {
    int t = blockIdx.y;
    int e = blockIdx.x * blockDim.x + threadIdx.x;
    if (e >= E_) return;
    int row = ei[(size_t)t*2*E_ + e];
    int col = ei[(size_t)t*2*E_ + E_ + e];
    int r   = et[(size_t)t*E_ + e];
    int pos = g_off[t*(N_+1) + row] + atomicAdd(&g_fill[t*N_ + row], 1);
    g_epack[(size_t)t*E_ + pos] = ((uint32_t)col << 2) | (uint32_t)r;
}
__global__ __launch_bounds__(256) void k_agg_csr(float* __restrict__ out, int t) {
    int warp = threadIdx.x >> 5, lane = threadIdx.x & 31;
    int row = blockIdx.x * 8 + warp;
    if (row >= N_) return;
    const float* dis = g_dis + (size_t)t*R_*N_;
    float disrow[R_];
    #pragma unroll
    for (int r = 0; r < R_; r++) disrow[r] = dis[r*N_ + row];
    float4 a0 = make_float4(0.f, 0.f, 0.f, 0.f);
    float4 a1 = make_float4(0.f, 0.f, 0.f, 0.f);
    int beg = g_off[t*(N_+1) + row], end = g_off[t*(N_+1) + row + 1];
    const uint32_t* ep = g_epack + (size_t)t*E_;
    for (int p = beg; p < end; p++) {
        uint32_t pk = ep[p];
        int r = pk & 3;
        int col = pk >> 2;
        float norm = disrow[r] * dis[r*N_ + col];
        if (norm != 0.f) {
            const float4* src = (const float4*)(g_Y + ((size_t)r*N_ + col) * FO_);
            float4 v0 = src[lane];
            float4 v1 = src[lane + 32];
            a0.x += v0.x*norm; a0.y += v0.y*norm; a0.z += v0.z*norm; a0.w += v0.w*norm;
            a1.x += v1.x*norm; a1.y += v1.y*norm; a1.z += v1.z*norm; a1.w += v1.w*norm;
        }
    }
    float4* dst = (float4*)(out + (size_t)t*N_*FO_ + (size_t)row*FO_);
    float4 o0 = dst[lane];
    float4 o1 = dst[lane + 32];
    o0.x = fmaxf(o0.x + a0.x, 0.f); o0.y = fmaxf(o0.y + a0.y, 0.f);
    o0.z = fmaxf(o0.z + a0.z, 0.f); o0.w = fmaxf(o0.w + a0.w, 0.f);
    o1.x = fmaxf(o1.x + a1.x, 0.f); o1.y = fmaxf(o1.y + a1.y, 0.f);
    o1.z = fmaxf(o1.z + a1.z, 0.f); o1.w = fmaxf(o1.w + a1.w, 0.f);
    dst[lane] = o0;
    dst[lane + 32] = o1;
}

// ---------------- launcher ----------------
extern "C" void kernel_launch(void* const* d_in, const int* in_sizes, int n_in,
                              void* d_out, int out_size) {
    const float* x       = (const float*)d_in[0];
    const float* mask    = (const float*)d_in[1];
    const float* Wself   = (const float*)d_in[2];
    const float* Wrel    = (const float*)d_in[3];
    const float* sWz     = (const float*)d_in[4];
    const float* sUz     = (const float*)d_in[5];
    const float* sbz     = (const float*)d_in[6];
    const float* sWr     = (const float*)d_in[7];
    const float* sUr     = (const float*)d_in[8];
    const float* sbr     = (const float*)d_in[9];
    const float* sWh     = (const float*)d_in[10];
    const float* sUh     = (const float*)d_in[11];
    const float* sbh     = (const float*)d_in[12];
    const float* s_sc    = (const float*)d_in[13];
    const float* rWz     = (const float*)d_in[14];
    const float* rUz     = (const float*)d_in[15];
    const float* rbz     = (const float*)d_in[16];
    const float* rWr     = (const float*)d_in[17];
    const float* rUr     = (const float*)d_in[18];
    const float* rbr     = (const float*)d_in[19];
    const float* rWh     = (const float*)d_in[20];
    const float* rUh     = (const float*)d_in[21];
    const float* rbh     = (const float*)d_in[22];
    const float* r_sc    = (const float*)d_in[23];
    const int*   ei      = (const int*)d_in[24];
    const int*   et      = (const int*)d_in[25];
    float* out = (float*)d_out;

    static bool attr_set = false;
    if (!attr_set) {
        cudaFuncSetAttribute(k_topk, cudaFuncAttributeMaxDynamicSharedMemorySize,
                             N_ * (int)sizeof(uint32_t));
        attr_set = true;
    }

    // input-only stages, hoisted out of the t-loop
    k_init<<<(C_*MAT_ + 255)/256, 256>>>(Wself, Wrel);
    k_norm<<<C_, 256>>>(s_sc, r_sc);
    k_scores<<<dim3(2500, T_), 256>>>(x, mask, s_sc, r_sc);
    k_topk<<<T_*C_, 1024, N_ * sizeof(uint32_t)>>>();
    k_zt<<<dim3(FO_, C_, T_), 64>>>(x);
    k_zeroE<<<(T_*R_*N_ + 255)/256, 256>>>();
    k_edge<<<dim3((E_ + 255)/256, T_), 256>>>(ei, et);
    k_dis<<<(T_*R_*N_ + 255)/256, 256>>>();
    k_scan<<<T_, 1024>>>();
    k_scatter<<<dim3((E_ + 255)/256, T_), 256>>>(ei, et);

    // sequential recurrence
    for (int t = 0; t < T_; t++) {
        int par = t & 1;
        k_cell1_tf32<<<dim3(4, 4, 2*C_), 128>>>(sWz, sUz, sbz, sWr, sUr, sbr,
                                                rWz, rUz, rbz, rWr, rUr, rbr, par, t);
        k_cell2_tf32<<<dim3(4, 4, C_), 128>>>(sWh, sUh, sbh, rWh, rUh, rbh, par, t);
        k_biggemm_tf32<<<dim3((N_ + 127)/128, FO_/128, C_), 256>>>(x, out, t, par ^ 1);
        k_agg_csr<<<(N_ + 7)/8, 256>>>(out, t);
    }
}

// round 6
// speedup vs baseline: 3.7954x; 1.0837x over previous
#include <cuda_runtime.h>
#include <math.h>
#include <stdint.h>

#define T_ 3
#define N_ 20000
#define F_ 256
#define FO_ 256
#define E_ 320000
#define R_ 4
#define C_ 5            // cells: 0 = self, 1..4 = relations
#define MAT_ (F_*FO_)   // 65536

// ---------------- scratch (static device globals; no allocs allowed) ----------------
__device__ float g_scores[T_*C_*N_];
__device__ float g_vals  [T_*C_*FO_];
__device__ int   g_tidx  [T_*C_*FO_];
__device__ float g_zt    [T_*C_*MAT_];
__device__ float g_upd   [C_*MAT_];
__device__ float g_rst   [C_*MAT_];
__device__ float g_Q  [2][C_*MAT_];    // fp32 state, [f][o]
__device__ float g_Qc    [C_*MAT_];    // tf32-rounded copy of post-update Q (GEMM B operand)
__device__ float g_xc    [T_*N_*F_];   // tf32-rounded copy of x (GEMM A operand)
__device__ float g_Y     [R_*N_*FO_];
__device__ int   g_degI  [T_*R_*N_];
__device__ float g_dis   [T_*R_*N_];
__device__ float g_denom [C_];
__device__ int      g_cnt [T_*N_];
__device__ int      g_off [T_*(N_+1)];
__device__ int      g_fill[T_*N_];
__device__ uint32_t g_epack[T_*E_];

extern __shared__ unsigned char s_dyn[];

__device__ __forceinline__ uint32_t f2key(float f) {
    uint32_t u = __float_as_uint(f);
    return (u & 0x80000000u) ? ~u : (u | 0x80000000u);
}
__device__ __forceinline__ float key2f(uint32_t k) {
    return (k & 0x80000000u) ? __uint_as_float(k & 0x7FFFFFFFu) : __uint_as_float(~k);
}
__device__ __forceinline__ float cvt_tf32(float f) {
    uint32_t r;
    asm("cvt.rna.tf32.f32 %0, %1;" : "=r"(r) : "f"(f));
    return __uint_as_float(r);
}
__device__ __forceinline__ float sigmoidf_(float v) { return 1.f / (1.f + expf(-v)); }

__device__ __forceinline__ void mma_tf32(float* d, const uint32_t* a, uint32_t b0, uint32_t b1) {
    asm volatile(
        "mma.sync.aligned.m16n8k8.row.col.f32.tf32.tf32.f32 "
        "{%0,%1,%2,%3}, {%4,%5,%6,%7}, {%8,%9}, {%0,%1,%2,%3};"
        : "+f"(d[0]), "+f"(d[1]), "+f"(d[2]), "+f"(d[3])
        : "r"(a[0]), "r"(a[1]), "r"(a[2]), "r"(a[3]), "r"(b0), "r"(b1));
}

__device__ __forceinline__ uint32_t smem_u32(const void* p) {
    uint32_t a;
    asm("{ .reg .u64 t; cvta.to.shared.u64 t, %1; cvt.u32.u64 %0, t; }" : "=r"(a) : "l"(p));
    return a;
}
__device__ __forceinline__ void cp_async16(uint32_t dst, const void* src) {
    asm volatile("cp.async.ca.shared.global [%0], [%1], 16;" :: "r"(dst), "l"(src) : "memory");
}
#define CP_COMMIT()  asm volatile("cp.async.commit_group;" ::: "memory")
#define CP_WAIT(n)   asm volatile("cp.async.wait_group %0;" :: "n"(n) : "memory")

// ---------------- init ----------------
__global__ void k_init(const float* __restrict__ Wself, const float* __restrict__ Wrel) {
    int i = blockIdx.x * blockDim.x + threadIdx.x;
    if (i < C_*MAT_) {
        int c = i / MAT_;
        int off = i - c*MAT_;
        g_Q[0][i] = (c == 0) ? Wself[off] : Wrel[(c-1)*MAT_ + off];
    }
}

// convert x -> tf32-rounded copy (one-time)
__global__ void k_xcvt(const float* __restrict__ x) {
    int i = blockIdx.x * blockDim.x + threadIdx.x;
    if (i < T_*N_*F_/4) {
        float4 v = ((const float4*)x)[i];
        v.x = cvt_tf32(v.x); v.y = cvt_tf32(v.y);
        v.z = cvt_tf32(v.z); v.w = cvt_tf32(v.w);
        ((float4*)g_xc)[i] = v;
    }
}

__global__ void k_norm(const float* __restrict__ s_sc, const float* __restrict__ r_sc) {
    int c = blockIdx.x;
    const float* sc = (c == 0) ? s_sc : r_sc + (c-1)*F_;
    float v = sc[threadIdx.x];
    __shared__ float red[256];
    red[threadIdx.x] = v * v;
    __syncthreads();
    for (int o = 128; o > 0; o >>= 1) {
        if (threadIdx.x < o) red[threadIdx.x] += red[threadIdx.x + o];
        __syncthreads();
    }
    if (threadIdx.x == 0) g_denom[c] = sqrtf(red[0]) + 1e-8f;
}

// ---------------- scores for ALL t ----------------
__global__ __launch_bounds__(256) void k_scores(const float* __restrict__ x,
                                                const float* __restrict__ mask,
                                                const float* __restrict__ s_sc,
                                                const float* __restrict__ r_sc) {
    int t = blockIdx.y;
    __shared__ float sc[C_][F_];
    for (int i = threadIdx.x; i < C_*F_; i += blockDim.x) {
        int c = i / F_, f = i - c*F_;
        sc[c][f] = (c == 0) ? s_sc[f] : r_sc[(c-1)*F_ + f];
    }
    __syncthreads();
    int warp = threadIdx.x >> 5, lane = threadIdx.x & 31;
    int n = blockIdx.x * 8 + warp;
    if (n >= N_) return;
    const float* xr = x + ((size_t)t*N_ + n) * F_;
    float acc[C_] = {0.f, 0.f, 0.f, 0.f, 0.f};
    #pragma unroll
    for (int q = 0; q < 8; q++) {
        float xv = xr[lane + q*32];
        #pragma unroll
        for (int c = 0; c < C_; c++) acc[c] += xv * sc[c][lane + q*32];
    }
    #pragma unroll
    for (int c = 0; c < C_; c++) {
        float v = acc[c];
        for (int o = 16; o > 0; o >>= 1) v += __shfl_down_sync(0xffffffffu, v, o);
        if (lane == 0)
            g_scores[(size_t)(t*C_ + c)*N_ + n] = v / g_denom[c] + mask[(size_t)t*N_ + n];
    }
}

// ---------------- top-256 (radix select + bitonic), grid = T*C blocks ----------------
__global__ __launch_bounds__(1024) void k_topk() {
    uint32_t* s_keys = (uint32_t*)s_dyn;
    __shared__ int      hist[256];
    __shared__ int      sfx[256];
    __shared__ uint32_t selKey[256];
    __shared__ int      selIdx[256];
    __shared__ uint32_t s_prefix;
    __shared__ int      s_remaining, s_eqCount, s_idxTh, s_cnt;

    int tc = blockIdx.x;
    int tid = threadIdx.x;
    const float* sc = g_scores + (size_t)tc * N_;

    if (tid < 256) hist[tid] = 0;
    if (tid == 0) { s_prefix = 0u; s_remaining = FO_; s_idxTh = 0x7FFFFFFF; s_eqCount = FO_; }
    __syncthreads();

    for (int i = tid; i < N_; i += 1024) {
        uint32_t k = f2key(sc[i]);
        s_keys[i] = k;
        atomicAdd(&hist[k >> 24], 1);
    }
    __syncthreads();

    #pragma unroll
    for (int pass = 3; pass >= 0; pass--) {
        int shift = pass * 8;
        if (pass < 3) {
            if (tid < 256) hist[tid] = 0;
            __syncthreads();
            uint32_t prefix = s_prefix;
            uint32_t pmask = 0xFFFFFFFFu << (shift + 8);
            for (int i = tid; i < N_; i += 1024) {
                uint32_t k = s_keys[i];
                if ((k & pmask) == (prefix & pmask))
                    atomicAdd(&hist[(k >> shift) & 0xFF], 1);
            }
            __syncthreads();
        }
        if (tid < 256) sfx[tid] = hist[tid];
        __syncthreads();
        #pragma unroll
        for (int o = 1; o < 256; o <<= 1) {
            int v = 0;
            if (tid < 256) v = sfx[tid] + ((tid + o < 256) ? sfx[tid + o] : 0);
            __syncthreads();
            if (tid < 256) sfx[tid] = v;
            __syncthreads();
        }
        int rem = s_remaining;
        __syncthreads();
        if (tid < 256) {
            int s  = sfx[tid];
            int sn = (tid < 255) ? sfx[tid + 1] : 0;
            if (s >= rem && sn < rem) {
                s_prefix |= ((uint32_t)tid) << shift;
                s_remaining = rem - sn;
                if (pass == 0) s_eqCount = hist[tid];
            }
        }
        __syncthreads();
    }
    uint32_t kth = s_prefix;
    int need = s_remaining;

    if (need < s_eqCount) {
        if (tid == 0) { s_prefix = 0u; s_remaining = need; }
        __syncthreads();
        #pragma unroll
        for (int pass = 1; pass >= 0; pass--) {
            int shift = pass * 8;
            if (tid < 256) hist[tid] = 0;
            __syncthreads();
            uint32_t prefixI = s_prefix;
            for (int i = tid; i < N_; i += 1024) {
                if (s_keys[i] == kth) {
                    if (pass == 1 || (((uint32_t)i >> 8) & 0xFF) == ((prefixI >> 8) & 0xFF))
                        atomicAdd(&hist[((uint32_t)i >> shift) & 0xFF], 1);
                }
            }
            __syncthreads();
            if (tid == 0) {
                int rem = s_remaining;
                uint32_t pfx = s_prefix;
                for (int b = 0; b < 256; b++) {
                    int cnt = hist[b];
                    if (cnt >= rem) { pfx |= ((uint32_t)b) << shift; break; }
                    rem -= cnt;
                }
                s_remaining = rem;
                s_prefix = pfx;
            }
            __syncthreads();
        }
        if (tid == 0) s_idxTh = (int)s_prefix;
    }
    if (tid == 0) s_cnt = 0;
    __syncthreads();
    int idxTh = s_idxTh;

    for (int i = tid; i < N_; i += 1024) {
        uint32_t k = s_keys[i];
        if (k > kth || (k == kth && i <= idxTh)) {
            int p = atomicAdd(&s_cnt, 1);
            selKey[p] = k;
            selIdx[p] = i;
        }
    }
    __syncthreads();

    for (int k = 2; k <= 256; k <<= 1) {
        for (int j = k >> 1; j > 0; j >>= 1) {
            if (tid < 256) {
                int ixj = tid ^ j;
                if (ixj > tid) {
                    bool desc = ((tid & k) == 0);
                    uint32_t ka = selKey[tid], kb = selKey[ixj];
                    int ia = selIdx[tid], ib = selIdx[ixj];
                    bool aGreater = (ka > kb) || (ka == kb && ia < ib);
                    bool doswap = desc ? !aGreater : aGreater;
                    if (doswap) {
                        selKey[tid] = kb; selKey[ixj] = ka;
                        selIdx[tid] = ib; selIdx[ixj] = ia;
                    }
                }
            }
            __syncthreads();
        }
    }

    if (tid < 256) {
        g_vals[(size_t)tc*FO_ + tid] = key2f(selKey[tid]);
        g_tidx[(size_t)tc*FO_ + tid] = selIdx[tid];
    }
}

// ---------------- zt for ALL t ----------------
__global__ void k_zt(const float* __restrict__ x) {
    int c = blockIdx.y, j = blockIdx.x, t = blockIdx.z;
    int tc = t*C_ + c;
    int idx = g_tidx[(size_t)tc*FO_ + j];
    float tv = tanhf(g_vals[(size_t)tc*FO_ + j]);
    const float4* xr = (const float4*)(x + ((size_t)t*N_ + idx) * F_);
    float4 v = xr[threadIdx.x];
    v.x *= tv; v.y *= tv; v.z *= tv; v.w *= tv;
    ((float4*)(g_zt + ((size_t)tc*FO_ + j) * F_))[threadIdx.x] = v;
}

// ================= TF32 cell GEMMs (legacy mma, small) =====
#define CELL_MMA_STEP()                                                         \
    _Pragma("unroll")                                                           \
    for (int kc = 0; kc < 2; kc++) {                                            \
        int k0 = kc * 8;                                                        \
        uint32_t afr[2][4];                                                     \
        _Pragma("unroll")                                                       \
        for (int mt = 0; mt < 2; mt++) {                                        \
            int mb = wm*32 + mt*16;                                             \
            afr[mt][0] = __float_as_uint(As[k0 + tg    ][mb + grp    ]);        \
            afr[mt][1] = __float_as_uint(As[k0 + tg    ][mb + grp + 8]);        \
            afr[mt][2] = __float_as_uint(As[k0 + tg + 4][mb + grp    ]);        \
            afr[mt][3] = __float_as_uint(As[k0 + tg + 4][mb + grp + 8]);        \
        }                                                                       \
        _Pragma("unroll")                                                       \
        for (int nt = 0; nt < 4; nt++) {                                        \
            int nb = wn*32 + nt*8;                                              \
            uint32_t b0 = __float_as_uint(Bs[k0 + tg    ][nb + grp]);           \
            uint32_t b1 = __float_as_uint(Bs[k0 + tg + 4][nb + grp]);           \
            _Pragma("unroll")                                                   \
            for (int mt = 0; mt < 2; mt++)                                      \
                mma_tf32(d[mt][nt], afr[mt], b0, b1);                           \
        }                                                                       \
    }

__global__ __launch_bounds__(128) void k_cell1_tf32(
    const float* sWz, const float* sUz, const float* sbz,
    const float* sWr, const float* sUr, const float* sbr,
    const float* rWz, const float* rUz, const float* rbz,
    const float* rWr, const float* rUr, const float* rbr, int par, int t) {
    int o = blockIdx.z & 1, c = blockIdx.z >> 1;
    const float *W, *U, *B;
    if (o == 0) { W = c ? rWz + (c-1)*MAT_ : sWz; U = c ? rUz + (c-1)*MAT_ : sUz; B = c ? rbz + (c-1)*MAT_ : sbz; }
    else        { W = c ? rWr + (c-1)*MAT_ : sWr; U = c ? rUr + (c-1)*MAT_ : sUr; B = c ? rbr + (c-1)*MAT_ : sbr; }
    const float* Z  = g_zt + (size_t)(t*C_ + c)*MAT_;
    const float* Qm = g_Q[par] + c*MAT_;
    float* OUT = (o == 0 ? g_upd : g_rst) + c*MAT_;

    __shared__ float As[16][68], Bs[16][68];
    int tid = threadIdx.x, lane = tid & 31, wid = tid >> 5;
    int wm = wid >> 1, wn = wid & 1;
    int grp = lane >> 2, tg = lane & 3;
    int i0 = blockIdx.y * 64, j0 = blockIdx.x * 64;

    float d[2][4][4];
    #pragma unroll
    for (int mt = 0; mt < 2; mt++)
        #pragma unroll
        for (int nt = 0; nt < 4; nt++)
            #pragma unroll
            for (int q = 0; q < 4; q++) d[mt][nt][q] = 0.f;

    int ar = tid >> 1, ac = (tid & 1) * 8;
    int qk = tid >> 3, qn = (tid & 7) * 8;

    for (int kb = 0; kb < 256; kb += 16) {
        float4 a4 = *(const float4*)(W + (size_t)(i0+ar)*256 + kb + ac);
        float4 a5 = *(const float4*)(W + (size_t)(i0+ar)*256 + kb + ac + 4);
        As[ac  ][ar]=cvt_tf32(a4.x); As[ac+1][ar]=cvt_tf32(a4.y);
        As[ac+2][ar]=cvt_tf32(a4.z); As[ac+3][ar]=cvt_tf32(a4.w);
        As[ac+4][ar]=cvt_tf32(a5.x); As[ac+5][ar]=cvt_tf32(a5.y);
        As[ac+6][ar]=cvt_tf32(a5.z); As[ac+7][ar]=cvt_tf32(a5.w);
        float4 b4 = *(const float4*)(Z + (size_t)(j0+ar)*256 + kb + ac);
        float4 b5 = *(const float4*)(Z + (size_t)(j0+ar)*256 + kb + ac + 4);
        Bs[ac  ][ar]=cvt_tf32(b4.x); Bs[ac+1][ar]=cvt_tf32(b4.y);
        Bs[ac+2][ar]=cvt_tf32(b4.z); Bs[ac+3][ar]=cvt_tf32(b4.w);
        Bs[ac+4][ar]=cvt_tf32(b5.x); Bs[ac+5][ar]=cvt_tf32(b5.y);
        Bs[ac+6][ar]=cvt_tf32(b5.z); Bs[ac+7][ar]=cvt_tf32(b5.w);
        __syncthreads();
        CELL_MMA_STEP();
        __syncthreads();
    }
    for (int kb = 0; kb < 256; kb += 16) {
        float4 a4 = *(const float4*)(U + (size_t)(i0+ar)*256 + kb + ac);
        float4 a5 = *(const float4*)(U + (size_t)(i0+ar)*256 + kb + ac + 4);
        As[ac  ][ar]=cvt_tf32(a4.x); As[ac+1][ar]=cvt_tf32(a4.y);
        As[ac+2][ar]=cvt_tf32(a4.z); As[ac+3][ar]=cvt_tf32(a4.w);
        As[ac+4][ar]=cvt_tf32(a5.x); As[ac+5][ar]=cvt_tf32(a5.y);
        As[ac+6][ar]=cvt_tf32(a5.z); As[ac+7][ar]=cvt_tf32(a5.w);
        float4 b4 = *(const float4*)(Qm + (size_t)(kb+qk)*256 + j0 + qn);
        float4 b5 = *(const float4*)(Qm + (size_t)(kb+qk)*256 + j0 + qn + 4);
        Bs[qk][qn  ]=cvt_tf32(b4.x); Bs[qk][qn+1]=cvt_tf32(b4.y);
        Bs[qk][qn+2]=cvt_tf32(b4.z); Bs[qk][qn+3]=cvt_tf32(b4.w);
        Bs[qk][qn+4]=cvt_tf32(b5.x); Bs[qk][qn+5]=cvt_tf32(b5.y);
        Bs[qk][qn+6]=cvt_tf32(b5.z); Bs[qk][qn+7]=cvt_tf32(b5.w);
        __syncthreads();
        CELL_MMA_STEP();
        __syncthreads();
    }

    #pragma unroll
    for (int mt = 0; mt < 2; mt++) {
        #pragma unroll
        for (int nt = 0; nt < 4; nt++) {
            int r0 = i0 + wm*32 + mt*16 + grp;
            int col = j0 + wn*32 + nt*8 + 2*tg;
            float2 bi0 = *(const float2*)(B + (size_t)r0*256 + col);
            *(float2*)&OUT[(size_t)r0*256 + col] =
                make_float2(sigmoidf_(d[mt][nt][0] + bi0.x), sigmoidf_(d[mt][nt][1] + bi0.y));
            int r1 = r0 + 8;
            float2 bi1 = *(const float2*)(B + (size_t)r1*256 + col);
            *(float2*)&OUT[(size_t)r1*256 + col] =
                make_float2(sigmoidf_(d[mt][nt][2] + bi1.x), sigmoidf_(d[mt][nt][3] + bi1.y));
        }
    }
}

__global__ __launch_bounds__(128) void k_cell2_tf32(
    const float* sWh, const float* sUh, const float* sbh,
    const float* rWh, const float* rUh, const float* rbh, int par, int t) {
    int c = blockIdx.z;
    const float* W = c ? rWh + (c-1)*MAT_ : sWh;
    const float* U = c ? rUh + (c-1)*MAT_ : sUh;
    const float* B = c ? rbh + (c-1)*MAT_ : sbh;
    const float* Z   = g_zt + (size_t)(t*C_ + c)*MAT_;
    const float* Qin = g_Q[par] + c*MAT_;
    const float* RST = g_rst + c*MAT_;
    const float* UPD = g_upd + c*MAT_;
    float* Qout = g_Q[par ^ 1] + c*MAT_;
    float* Qc   = g_Qc + c*MAT_;

    __shared__ float As[16][68], Bs[16][68];
    int tid = threadIdx.x, lane = tid & 31, wid = tid >> 5;
    int wm = wid >> 1, wn = wid & 1;
    int grp = lane >> 2, tg = lane & 3;
    int i0 = blockIdx.y * 64, j0 = blockIdx.x * 64;

    float d[2][4][4];
    #pragma unroll
    for (int mt = 0; mt < 2; mt++)
        #pragma unroll
        for (int nt = 0; nt < 4; nt++)
            #pragma unroll
            for (int q = 0; q < 4; q++) d[mt][nt][q] = 0.f;

    int ar = tid >> 1, ac = (tid & 1) * 8;
    int qk = tid >> 3, qn = (tid & 7) * 8;

    for (int kb = 0; kb < 256; kb += 16) {
        float4 a4 = *(const float4*)(W + (size_t)(i0+ar)*256 + kb + ac);
        float4 a5 = *(const float4*)(W + (size_t)(i0+ar)*256 + kb + ac + 4);
        As[ac  ][ar]=cvt_tf32(a4.x); As[ac+1][ar]=cvt_tf32(a4.y);
        As[ac+2][ar]=cvt_tf32(a4.z); As[ac+3][ar]=cvt_tf32(a4.w);
        As[ac+4][ar]=cvt_tf32(a5.x); As[ac+5][ar]=cvt_tf32(a5.y);
        As[ac+6][ar]=cvt_tf32(a5.z); As[ac+7][ar]=cvt_tf32(a5.w);
        float4 b4 = *(const float4*)(Z + (size_t)(j0+ar)*256 + kb + ac);
        float4 b5 = *(const float4*)(Z + (size_t)(j0+ar)*256 + kb + ac + 4);
        Bs[ac  ][ar]=cvt_tf32(b4.x); Bs[ac+1][ar]=cvt_tf32(b4.y);
        Bs[ac+2][ar]=cvt_tf32(b4.z); Bs[ac+3][ar]=cvt_tf32(b4.w);
        Bs[ac+4][ar]=cvt_tf32(b5.x); Bs[ac+5][ar]=cvt_tf32(b5.y);
        Bs[ac+6][ar]=cvt_tf32(b5.z); Bs[ac+7][ar]=cvt_tf32(b5.w);
        __syncthreads();
        CELL_MMA_STEP();
        __syncthreads();
    }
    for (int kb = 0; kb < 256; kb += 16) {
        float4 a4 = *(const float4*)(U + (size_t)(i0+ar)*256 + kb + ac);
        float4 a5 = *(const float4*)(U + (size_t)(i0+ar)*256 + kb + ac + 4);
        As[ac  ][ar]=cvt_tf32(a4.x); As[ac+1][ar]=cvt_tf32(a4.y);
        As[ac+2][ar]=cvt_tf32(a4.z); As[ac+3][ar]=cvt_tf32(a4.w);
        As[ac+4][ar]=cvt_tf32(a5.x); As[ac+5][ar]=cvt_tf32(a5.y);
        As[ac+6][ar]=cvt_tf32(a5.z); As[ac+7][ar]=cvt_tf32(a5.w);
        float4 b4 = *(const float4*)(Qin + (size_t)(kb+qk)*256 + j0 + qn);
        float4 b5 = *(const float4*)(Qin + (size_t)(kb+qk)*256 + j0 + qn + 4);
        float4 r4 = *(const float4*)(RST + (size_t)(kb+qk)*256 + j0 + qn);
        float4 r5 = *(const float4*)(RST + (size_t)(kb+qk)*256 + j0 + qn + 4);
        Bs[qk][qn  ]=cvt_tf32(b4.x*r4.x); Bs[qk][qn+1]=cvt_tf32(b4.y*r4.y);
        Bs[qk][qn+2]=cvt_tf32(b4.z*r4.z); Bs[qk][qn+3]=cvt_tf32(b4.w*r4.w);
        Bs[qk][qn+4]=cvt_tf32(b5.x*r5.x); Bs[qk][qn+5]=cvt_tf32(b5.y*r5.y);
        Bs[qk][qn+6]=cvt_tf32(b5.z*r5.z); Bs[qk][qn+7]=cvt_tf32(b5.w*r5.w);
        __syncthreads();
        CELL_MMA_STEP();
        __syncthreads();
    }

    #pragma unroll
    for (int mt = 0; mt < 2; mt++) {
        #pragma unroll
        for (int nt = 0; nt < 4; nt++) {
            #pragma unroll
            for (int half = 0; half < 2; half++) {
                int r = i0 + wm*32 + mt*16 + grp + half*8;
                int col = j0 + wn*32 + nt*8 + 2*tg;
                float d0 = d[mt][nt][half*2], d1 = d[mt][nt][half*2 + 1];
                float2 bi = *(const float2*)(B + (size_t)r*256 + col);
                float2 up = *(const float2*)(UPD + (size_t)r*256 + col);
                float2 qi = *(const float2*)(Qin + (size_t)r*256 + col);
                float h0 = tanhf(d0 + bi.x), h1 = tanhf(d1 + bi.y);
                float v0 = (1.f - up.x)*qi.x + up.x*h0;
                float v1 = (1.f - up.y)*qi.y + up.y*h1;
                *(float2*)&Qout[(size_t)r*256 + col] = make_float2(v0, v1);
                *(float2*)&Qc[(size_t)r*256 + col] = make_float2(cvt_tf32(v0), cvt_tf32(v1));
            }
        }
    }
}

// ---------------- big GEMM: 128x256 tile, cp.async double-buffered, tf32 mma ----------------
// A = g_xc (tf32-rounded x), B = g_Qc (tf32-rounded post-update Q, [k][n] layout).
// smem per stage: A[128][20] (10240 B) + B[16][264] (16896 B); 2 stages = 54272 B.
#define GA_PAD 20
#define GB_PAD 264
#define G_STAGE (128*GA_PAD*4 + 16*GB_PAD*4)
#define G_SMEM  (2*G_STAGE)

__global__ __launch_bounds__(256) void k_biggemm_cp(float* __restrict__ out, int t) {
    const int c = blockIdx.z;
    const float* Ag = g_xc + (size_t)t*N_*F_;
    const float* Bg = g_Qc + (size_t)c*MAT_;
    float* dst = (c == 0) ? out + (size_t)t*N_*FO_ : g_Y + (size_t)(c-1)*N_*FO_;
    const int m0 = blockIdx.x * 128;

    float* smf = (float*)s_dyn;
    uint32_t smb = smem_u32(s_dyn);
    int tid = threadIdx.x, wid = tid >> 5, lane = tid & 31;
    int wm = wid >> 2, wn = wid & 3;          // 2 x 4 warps, warp tile 64x64
    int grp = lane >> 2, tg = lane & 3;

    float d[4][8][4];
    #pragma unroll
    for (int mt = 0; mt < 4; mt++)
        #pragma unroll
        for (int nt = 0; nt < 8; nt++)
            #pragma unroll
            for (int q = 0; q < 4; q++) d[mt][nt][q] = 0.f;

    // loader assignments
    // A: 512 chunks of 16B (128 rows x 4), 2 per thread
    // B: 1024 chunks of 16B (16 krows x 64), 4 per thread
    auto load_stage = [&](int stg, int kb) {
        uint32_t sa = smb + stg*G_STAGE;
        uint32_t sb = sa + 128*GA_PAD*4;
        #pragma unroll
        for (int i = 0; i < 2; i++) {
            int idx = tid + i*256;
            int row = idx >> 2, ch = idx & 3;
            int gr = m0 + row;
            uint32_t dsta = sa + (uint32_t)(row*GA_PAD + ch*4)*4;
            if (gr < N_) {
                cp_async16(dsta, Ag + (size_t)gr*F_ + kb + ch*4);
            } else {
                *(float4*)(s_dyn + (dsta - smb)) = make_float4(0.f, 0.f, 0.f, 0.f);
            }
        }
        #pragma unroll
        for (int i = 0; i < 4; i++) {
            int idx = tid + i*256;
            int kr = idx >> 6, nch = idx & 63;
            uint32_t dstb = sb + (uint32_t)(kr*GB_PAD + nch*4)*4;
            cp_async16(dstb, Bg + (size_t)(kb + kr)*FO_ + nch*4);
        }
        CP_COMMIT();
    };

    load_stage(0, 0);

    #pragma unroll 1
    for (int step = 0; step < 16; step++) {
        if (step + 1 < 16) load_stage((step + 1) & 1, (step + 1) * 16);
        if (step + 1 < 16) { CP_WAIT(1); } else { CP_WAIT(0); }
        __syncthreads();

        const float* As = smf + ((step & 1) ? G_STAGE/4 : 0);
        const float* Bs = As + 128*GA_PAD;

        #pragma unroll
        for (int kc = 0; kc < 2; kc++) {
            int k0 = kc * 8;
            uint32_t a[4][4];
            #pragma unroll
            for (int mt = 0; mt < 4; mt++) {
                int mb = wm*64 + mt*16;
                a[mt][0] = __float_as_uint(As[(mb + grp    )*GA_PAD + k0 + tg    ]);
                a[mt][1] = __float_as_uint(As[(mb + grp + 8)*GA_PAD + k0 + tg    ]);
                a[mt][2] = __float_as_uint(As[(mb + grp    )*GA_PAD + k0 + tg + 4]);
                a[mt][3] = __float_as_uint(As[(mb + grp + 8)*GA_PAD + k0 + tg + 4]);
            }
            #pragma unroll
            for (int nt = 0; nt < 8; nt++) {
                int nb = wn*64 + nt*8;
                uint32_t b0 = __float_as_uint(Bs[(k0 + tg    )*GB_PAD + nb + grp]);
                uint32_t b1 = __float_as_uint(Bs[(k0 + tg + 4)*GB_PAD + nb + grp]);
                #pragma unroll
                for (int mt = 0; mt < 4; mt++)
                    mma_tf32(d[mt][nt], a[mt], b0, b1);
            }
        }
        __syncthreads();
    }

    #pragma unroll
    for (int mt = 0; mt < 4; mt++) {
        #pragma unroll
        for (int nt = 0; nt < 8; nt++) {
            int r0 = m0 + wm*64 + mt*16 + grp;
            int col = wn*64 + nt*8 + 2*tg;
            if (r0 < N_)
                *(float2*)&dst[(size_t)r0*FO_ + col] = make_float2(d[mt][nt][0], d[mt][nt][1]);
            int r1 = r0 + 8;
            if (r1 < N_)
                *(float2*)&dst[(size_t)r1*FO_ + col] = make_float2(d[mt][nt][2], d[mt][nt][3]);
        }
    }
}

// ---------------- edges: CSR by destination row, ALL t upfront ----------------
__global__ void k_zeroE() {
    int i = blockIdx.x * blockDim.x + threadIdx.x;
    if (i < T_*R_*N_) g_degI[i] = 0;
    if (i < T_*N_) g_cnt[i] = 0;
}
__global__ void k_edge(const int* __restrict__ ei, const int* __restrict__ et) {
    int t = blockIdx.y;
    int e = blockIdx.x * blockDim.x + threadIdx.x;
    if (e >= E_) return;
    int row = ei[(size_t)t*2*E_ + e];
    int r   = et[(size_t)t*E_ + e];
    atomicAdd(&g_degI[(t*R_ + r)*N_ + row], 1);
    atomicAdd(&g_cnt[t*N_ + row], 1);
}
__global__ void k_dis() {
    int i = blockIdx.x * blockDim.x + threadIdx.x;
    if (i >= T_*R_*N_) return;
    int d = g_degI[i];
    g_dis[i] = (d > 0) ? (1.f / sqrtf((float)d)) : 0.f;
}
__global__ __launch_bounds__(1024) void k_scan() {
    __shared__ int part[1024];
    int t = blockIdx.x;
    const int* cnt = g_cnt + t*N_;
    int* off = g_off + t*(N_+1);
    int* fill = g_fill + t*N_;
    int tid = threadIdx.x;
    const int CH = (N_ + 1023) / 1024;
    int base = tid * CH;
    int s = 0;
    for (int i = 0; i < CH; i++) {
        int idx = base + i;
        if (idx < N_) s += cnt[idx];
    }
    part[tid] = s;
    __syncthreads();
    for (int o = 1; o < 1024; o <<= 1) {
        int v = (tid >= o) ? part[tid - o] : 0;
        __syncthreads();
        part[tid] += v;
        __syncthreads();
    }
    int run = (tid == 0) ? 0 : part[tid - 1];
    for (int i = 0; i < CH; i++) {
        int idx = base + i;
        if (idx < N_) {
            off[idx] = run;
            run += cnt[idx];
            fill[idx] = 0;
        }
    }
    if (tid == 0) off[N_] = E_;
}
__global__ void k_scatter(const int* __restrict__ ei, const int* __restrict__ et) {
    int t = blockIdx.y;
    int e = blockIdx.x * blockDim.x + threadIdx.x;
    if (e >= E_) return;
    int row = ei[(size_t)t*2*E_ + e];
    int col = ei[(size_t)t*2*E_ + E_ + e];
    int r   = et[(size_t)t*E_ + e];
    int pos = g_off[t*(N_+1) + row] + atomicAdd(&g_fill[t*N_ + row], 1);
    g_epack[(size_t)t*E_ + pos] = ((uint32_t)col << 2) | (uint32_t)r;
}
__global__ __launch_bounds__(256) void k_agg_csr(float* __restrict__ out, int t) {
    int warp = threadIdx.x >> 5, lane = threadIdx.x & 31;
    int row = blockIdx.x * 8 + warp;
    if (row >= N_) return;
    const float* dis = g_dis + (size_t)t*R_*N_;
    float disrow[R_];
    #pragma unroll
    for (int r = 0; r < R_; r++) disrow[r] = dis[r*N_ + row];
    float4 a0 = make_float4(0.f, 0.f, 0.f, 0.f);
    float4 a1 = make_float4(0.f, 0.f, 0.f, 0.f);
    int beg = g_off[t*(N_+1) + row], end = g_off[t*(N_+1) + row + 1];
    const uint32_t* ep = g_epack + (size_t)t*E_;
    for (int p = beg; p < end; p++) {
        uint32_t pk = ep[p];
        int r = pk & 3;
        int col = pk >> 2;
        float norm = disrow[r] * dis[r*N_ + col];
        if (norm != 0.f) {
            const float4* src = (const float4*)(g_Y + ((size_t)r*N_ + col) * FO_);
            float4 v0 = src[lane];
            float4 v1 = src[lane + 32];
            a0.x += v0.x*norm; a0.y += v0.y*norm; a0.z += v0.z*norm; a0.w += v0.w*norm;
            a1.x += v1.x*norm; a1.y += v1.y*norm; a1.z += v1.z*norm; a1.w += v1.w*norm;
        }
    }
    float4* dst = (float4*)(out + (size_t)t*N_*FO_ + (size_t)row*FO_);
    float4 o0 = dst[lane];
    float4 o1 = dst[lane + 32];
    o0.x = fmaxf(o0.x + a0.x, 0.f); o0.y = fmaxf(o0.y + a0.y, 0.f);
    o0.z = fmaxf(o0.z + a0.z, 0.f); o0.w = fmaxf(o0.w + a0.w, 0.f);
    o1.x = fmaxf(o1.x + a1.x, 0.f); o1.y = fmaxf(o1.y + a1.y, 0.f);
    o1.z = fmaxf(o1.z + a1.z, 0.f); o1.w = fmaxf(o1.w + a1.w, 0.f);
    dst[lane] = o0;
    dst[lane + 32] = o1;
}

// ---------------- launcher ----------------
extern "C" void kernel_launch(void* const* d_in, const int* in_sizes, int n_in,
                              void* d_out, int out_size) {
    const float* x       = (const float*)d_in[0];
    const float* mask    = (const float*)d_in[1];
    const float* Wself   = (const float*)d_in[2];
    const float* Wrel    = (const float*)d_in[3];
    const float* sWz     = (const float*)d_in[4];
    const float* sUz     = (const float*)d_in[5];
    const float* sbz     = (const float*)d_in[6];
    const float* sWr     = (const float*)d_in[7];
    const float* sUr     = (const float*)d_in[8];
    const float* sbr     = (const float*)d_in[9];
    const float* sWh     = (const float*)d_in[10];
    const float* sUh     = (const float*)d_in[11];
    const float* sbh     = (const float*)d_in[12];
    const float* s_sc    = (const float*)d_in[13];
    const float* rWz     = (const float*)d_in[14];
    const float* rUz     = (const float*)d_in[15];
    const float* rbz     = (const float*)d_in[16];
    const float* rWr     = (const float*)d_in[17];
    const float* rUr     = (const float*)d_in[18];
    const float* rbr     = (const float*)d_in[19];
    const float* rWh     = (const float*)d_in[20];
    const float* rUh     = (const float*)d_in[21];
    const float* rbh     = (const float*)d_in[22];
    const float* r_sc    = (const float*)d_in[23];
    const int*   ei      = (const int*)d_in[24];
    const int*   et      = (const int*)d_in[25];
    float* out = (float*)d_out;

    static bool attr_set = false;
    if (!attr_set) {
        cudaFuncSetAttribute(k_topk, cudaFuncAttributeMaxDynamicSharedMemorySize,
                             N_ * (int)sizeof(uint32_t));
        cudaFuncSetAttribute(k_biggemm_cp, cudaFuncAttributeMaxDynamicSharedMemorySize,
                             G_SMEM);
        attr_set = true;
    }

    // input-only stages, hoisted out of the t-loop
    k_init<<<(C_*MAT_ + 255)/256, 256>>>(Wself, Wrel);
    k_xcvt<<<(T_*N_*F_/4 + 255)/256, 256>>>(x);
    k_norm<<<C_, 256>>>(s_sc, r_sc);
    k_scores<<<dim3(2500, T_), 256>>>(x, mask, s_sc, r_sc);
    k_topk<<<T_*C_, 1024, N_ * sizeof(uint32_t)>>>();
    k_zt<<<dim3(FO_, C_, T_), 64>>>(x);
    k_zeroE<<<(T_*R_*N_ + 255)/256, 256>>>();
    k_edge<<<dim3((E_ + 255)/256, T_), 256>>>(ei, et);
    k_dis<<<(T_*R_*N_ + 255)/256, 256>>>();
    k_scan<<<T_, 1024>>>();
    k_scatter<<<dim3((E_ + 255)/256, T_), 256>>>(ei, et);

    // sequential recurrence
    for (int t = 0; t < T_; t++) {
        int par = t & 1;
        k_cell1_tf32<<<dim3(4, 4, 2*C_), 128>>>(sWz, sUz, sbz, sWr, sUr, sbr,
                                                rWz, rUz, rbz, rWr, rUr, rbr, par, t);
        k_cell2_tf32<<<dim3(4, 4, C_), 128>>>(sWh, sUh, sbh, rWh, rUh, rbh, par, t);
        k_biggemm_cp<<<dim3((N_ + 127)/128, 1, C_), 256, G_SMEM>>>(out, t);
        k_agg_csr<<<(N_ + 7)/8, 256>>>(out, t);
    }
}

// round 7
// speedup vs baseline: 3.8657x; 1.0185x over previous
#include <cuda_runtime.h>
#include <math.h>
#include <stdint.h>

#define T_ 3
#define N_ 20000
#define F_ 256
#define FO_ 256
#define E_ 320000
#define R_ 4
#define C_ 5
#define MAT_ (F_*FO_)

// ---------------- scratch ----------------
__device__ float g_scores[T_*C_*N_];
__device__ float g_vals  [T_*C_*FO_];
__device__ int   g_tidx  [T_*C_*FO_];
__device__ float g_zt    [T_*C_*MAT_];
__device__ float g_upd   [C_*MAT_];
__device__ float g_rst   [C_*MAT_];
__device__ float g_Q  [2][C_*MAT_];
__device__ float g_Qc    [C_*MAT_];
__device__ float g_xc    [T_*N_*F_];
__device__ float g_Y     [R_*N_*FO_];
__device__ int   g_degI  [T_*R_*N_];
__device__ float g_dis   [T_*R_*N_];
__device__ float g_denom [C_];
__device__ int      g_cnt [T_*N_];
__device__ int      g_off [T_*(N_+1)];
__device__ int      g_fill[T_*N_];
__device__ uint32_t g_epack[T_*E_];

extern __shared__ unsigned char s_dyn[];

__device__ __forceinline__ uint32_t f2key(float f) {
    uint32_t u = __float_as_uint(f);
    return (u & 0x80000000u) ? ~u : (u | 0x80000000u);
}
__device__ __forceinline__ float key2f(uint32_t k) {
    return (k & 0x80000000u) ? __uint_as_float(k & 0x7FFFFFFFu) : __uint_as_float(~k);
}
__device__ __forceinline__ float cvt_tf32(float f) {
    uint32_t r;
    asm("cvt.rna.tf32.f32 %0, %1;" : "=r"(r) : "f"(f));
    return __uint_as_float(r);
}
__device__ __forceinline__ float sigmoidf_(float v) { return 1.f / (1.f + expf(-v)); }

__device__ __forceinline__ void mma_tf32(float* d, const uint32_t* a, uint32_t b0, uint32_t b1) {
    asm volatile(
        "mma.sync.aligned.m16n8k8.row.col.f32.tf32.tf32.f32 "
        "{%0,%1,%2,%3}, {%4,%5,%6,%7}, {%8,%9}, {%0,%1,%2,%3};"
        : "+f"(d[0]), "+f"(d[1]), "+f"(d[2]), "+f"(d[3])
        : "r"(a[0]), "r"(a[1]), "r"(a[2]), "r"(a[3]), "r"(b0), "r"(b1));
}
__device__ __forceinline__ uint32_t smem_u32(const void* p) {
    uint32_t a;
    asm("{ .reg .u64 t; cvta.to.shared.u64 t, %1; cvt.u32.u64 %0, t; }" : "=r"(a) : "l"(p));
    return a;
}
__device__ __forceinline__ void cp_async16(uint32_t dst, const void* src) {
    asm volatile("cp.async.ca.shared.global [%0], [%1], 16;" :: "r"(dst), "l"(src) : "memory");
}
#define CP_COMMIT()  asm volatile("cp.async.commit_group;" ::: "memory")
#define CP_WAIT(n)   asm volatile("cp.async.wait_group %0;" :: "n"(n) : "memory")

// ================== PREAMBLE (merged) ==================
#define PB_INIT  ((C_*MAT_)/256)                 // 1280
#define PB_XCVT  ((T_*N_*F_/4)/256)              // 15000
#define PB_ZERO  (((T_*R_*N_)+255)/256)          // 938
#define PB_TOTAL (PB_INIT + PB_XCVT + PB_ZERO + C_)

__global__ __launch_bounds__(256) void k_prep(const float* __restrict__ Wself,
                                              const float* __restrict__ Wrel,
                                              const float* __restrict__ x,
                                              const float* __restrict__ s_sc,
                                              const float* __restrict__ r_sc) {
    int b = blockIdx.x, tid = threadIdx.x;
    if (b < PB_INIT) {
        int i = b*256 + tid;
        int c = i / MAT_, off = i - c*MAT_;
        g_Q[0][i] = (c == 0) ? Wself[off] : Wrel[(c-1)*MAT_ + off];
    } else if (b < PB_INIT + PB_XCVT) {
        int i = (b - PB_INIT)*256 + tid;
        float4 v = ((const float4*)x)[i];
        v.x = cvt_tf32(v.x); v.y = cvt_tf32(v.y);
        v.z = cvt_tf32(v.z); v.w = cvt_tf32(v.w);
        ((float4*)g_xc)[i] = v;
    } else if (b < PB_INIT + PB_XCVT + PB_ZERO) {
        int i = (b - PB_INIT - PB_XCVT)*256 + tid;
        if (i < T_*R_*N_) g_degI[i] = 0;
        if (i < T_*N_) g_cnt[i] = 0;
    } else {
        int c = b - (PB_INIT + PB_XCVT + PB_ZERO);
        const float* sc = (c == 0) ? s_sc : r_sc + (c-1)*F_;
        float v = sc[tid];
        __shared__ float red[256];
        red[tid] = v * v;
        __syncthreads();
        for (int o = 128; o > 0; o >>= 1) {
            if (tid < o) red[tid] += red[tid + o];
            __syncthreads();
        }
        if (tid == 0) g_denom[c] = sqrtf(red[0]) + 1e-8f;
    }
}

// scores (7500 blocks) + edge count (3750 blocks)
__global__ __launch_bounds__(256) void k_scores_edge(const float* __restrict__ x,
                                                     const float* __restrict__ mask,
                                                     const float* __restrict__ s_sc,
                                                     const float* __restrict__ r_sc,
                                                     const int* __restrict__ ei,
                                                     const int* __restrict__ et) {
    int b = blockIdx.x, tid = threadIdx.x;
    if (b < 7500) {
        int t = b / 2500, blk = b - t*2500;
        __shared__ float sc[C_][F_];
        for (int i = tid; i < C_*F_; i += 256) {
            int c = i / F_, f = i - c*F_;
            sc[c][f] = (c == 0) ? s_sc[f] : r_sc[(c-1)*F_ + f];
        }
        __syncthreads();
        int warp = tid >> 5, lane = tid & 31;
        int n = blk * 8 + warp;
        if (n >= N_) return;
        const float* xr = x + ((size_t)t*N_ + n) * F_;
        float acc[C_] = {0.f, 0.f, 0.f, 0.f, 0.f};
        #pragma unroll
        for (int q = 0; q < 8; q++) {
            float xv = xr[lane + q*32];
            #pragma unroll
            for (int c = 0; c < C_; c++) acc[c] += xv * sc[c][lane + q*32];
        }
        #pragma unroll
        for (int c = 0; c < C_; c++) {
            float v = acc[c];
            for (int o = 16; o > 0; o >>= 1) v += __shfl_down_sync(0xffffffffu, v, o);
            if (lane == 0)
                g_scores[(size_t)(t*C_ + c)*N_ + n] = v / g_denom[c] + mask[(size_t)t*N_ + n];
        }
    } else {
        int idx = b - 7500;           // 0..3749
        int t = idx / 1250;
        int e = (idx - t*1250)*256 + tid;
        if (e >= E_) return;
        int row = ei[(size_t)t*2*E_ + e];
        int r   = et[(size_t)t*E_ + e];
        atomicAdd(&g_degI[(t*R_ + r)*N_ + row], 1);
        atomicAdd(&g_cnt[t*N_ + row], 1);
    }
}

// ================== topk + scan + dis (merged, 1024 threads) ==================
__device__ void topk_body(int tc) {
    uint32_t* s_keys = (uint32_t*)s_dyn;
    __shared__ int      hist[256];
    __shared__ int      sfx[256];
    __shared__ uint32_t selKey[256];
    __shared__ int      selIdx[256];
    __shared__ uint32_t s_prefix;
    __shared__ int      s_remaining, s_eqCount, s_idxTh, s_cnt;

    int tid = threadIdx.x;
    const float* sc = g_scores + (size_t)tc * N_;

    if (tid < 256) hist[tid] = 0;
    if (tid == 0) { s_prefix = 0u; s_remaining = FO_; s_idxTh = 0x7FFFFFFF; s_eqCount = FO_; }
    __syncthreads();

    for (int i = tid; i < N_; i += 1024) {
        uint32_t k = f2key(sc[i]);
        s_keys[i] = k;
        atomicAdd(&hist[k >> 24], 1);
    }
    __syncthreads();

    #pragma unroll
    for (int pass = 3; pass >= 0; pass--) {
        int shift = pass * 8;
        if (pass < 3) {
            if (tid < 256) hist[tid] = 0;
            __syncthreads();
            uint32_t prefix = s_prefix;
            uint32_t pmask = 0xFFFFFFFFu << (shift + 8);
            for (int i = tid; i < N_; i += 1024) {
                uint32_t k = s_keys[i];
                if ((k & pmask) == (prefix & pmask))
                    atomicAdd(&hist[(k >> shift) & 0xFF], 1);
            }
            __syncthreads();
        }
        if (tid < 256) sfx[tid] = hist[tid];
        __syncthreads();
        #pragma unroll
        for (int o = 1; o < 256; o <<= 1) {
            int v = 0;
            if (tid < 256) v = sfx[tid] + ((tid + o < 256) ? sfx[tid + o] : 0);
            __syncthreads();
            if (tid < 256) sfx[tid] = v;
            __syncthreads();
        }
        int rem = s_remaining;
        __syncthreads();
        if (tid < 256) {
            int s  = sfx[tid];
            int sn = (tid < 255) ? sfx[tid + 1] : 0;
            if (s >= rem && sn < rem) {
                s_prefix |= ((uint32_t)tid) << shift;
                s_remaining = rem - sn;
                if (pass == 0) s_eqCount = hist[tid];
            }
        }
        __syncthreads();
    }
    uint32_t kth = s_prefix;
    int need = s_remaining;

    if (need < s_eqCount) {
        if (tid == 0) { s_prefix = 0u; s_remaining = need; }
        __syncthreads();
        #pragma unroll
        for (int pass = 1; pass >= 0; pass--) {
            int shift = pass * 8;
            if (tid < 256) hist[tid] = 0;
            __syncthreads();
            uint32_t prefixI = s_prefix;
            for (int i = tid; i < N_; i += 1024) {
                if (s_keys[i] == kth) {
                    if (pass == 1 || (((uint32_t)i >> 8) & 0xFF) == ((prefixI >> 8) & 0xFF))
                        atomicAdd(&hist[((uint32_t)i >> shift) & 0xFF], 1);
                }
            }
            __syncthreads();
            if (tid == 0) {
                int rem = s_remaining;
                uint32_t pfx = s_prefix;
                for (int bb = 0; bb < 256; bb++) {
                    int cnt = hist[bb];
                    if (cnt >= rem) { pfx |= ((uint32_t)bb) << shift; break; }
                    rem -= cnt;
                }
                s_remaining = rem;
                s_prefix = pfx;
            }
            __syncthreads();
        }
        if (tid == 0) s_idxTh = (int)s_prefix;
    }
    if (tid == 0) s_cnt = 0;
    __syncthreads();
    int idxTh = s_idxTh;

    for (int i = tid; i < N_; i += 1024) {
        uint32_t k = s_keys[i];
        if (k > kth || (k == kth && i <= idxTh)) {
            int p = atomicAdd(&s_cnt, 1);
            selKey[p] = k;
            selIdx[p] = i;
        }
    }
    __syncthreads();

    for (int k = 2; k <= 256; k <<= 1) {
        for (int j = k >> 1; j > 0; j >>= 1) {
            if (tid < 256) {
                int ixj = tid ^ j;
                if (ixj > tid) {
                    bool desc = ((tid & k) == 0);
                    uint32_t ka = selKey[tid], kb = selKey[ixj];
                    int ia = selIdx[tid], ib = selIdx[ixj];
                    bool aGreater = (ka > kb) || (ka == kb && ia < ib);
                    bool doswap = desc ? !aGreater : aGreater;
                    if (doswap) {
                        selKey[tid] = kb; selKey[ixj] = ka;
                        selIdx[tid] = ib; selIdx[ixj] = ia;
                    }
                }
            }
            __syncthreads();
        }
    }

    if (tid < 256) {
        g_vals[(size_t)tc*FO_ + tid] = key2f(selKey[tid]);
        g_tidx[(size_t)tc*FO_ + tid] = selIdx[tid];
    }
}

__device__ void scan_body(int t) {
    __shared__ int part[1024];
    const int* cnt = g_cnt + t*N_;
    int* off = g_off + t*(N_+1);
    int* fill = g_fill + t*N_;
    int tid = threadIdx.x;
    const int CH = (N_ + 1023) / 1024;
    int base = tid * CH;
    int s = 0;
    for (int i = 0; i < CH; i++) {
        int idx = base + i;
        if (idx < N_) s += cnt[idx];
    }
    part[tid] = s;
    __syncthreads();
    for (int o = 1; o < 1024; o <<= 1) {
        int v = (tid >= o) ? part[tid - o] : 0;
        __syncthreads();
        part[tid] += v;
        __syncthreads();
    }
    int run = (tid == 0) ? 0 : part[tid - 1];
    for (int i = 0; i < CH; i++) {
        int idx = base + i;
        if (idx < N_) {
            off[idx] = run;
            run += cnt[idx];
            fill[idx] = 0;
        }
    }
    if (tid == 0) off[N_] = E_;
}

#define SEL_DIS_BLOCKS (((T_*R_*N_)+1023)/1024)   // 235
__global__ __launch_bounds__(1024) void k_sel() {
    int b = blockIdx.x;
    if (b < T_*C_) {
        topk_body(b);
    } else if (b < T_*C_ + T_) {
        scan_body(b - T_*C_);
    } else {
        int i = (b - T_*C_ - T_)*1024 + threadIdx.x;
        if (i < T_*R_*N_) {
            int d = g_degI[i];
            g_dis[i] = (d > 0) ? (1.f / sqrtf((float)d)) : 0.f;
        }
    }
}

// ================== zt + scatter (merged, 256 threads) ==================
#define ZT_BLOCKS ((T_*C_*FO_)/4)     // 960
__global__ __launch_bounds__(256) void k_zt_scatter(const float* __restrict__ x,
                                                    const int* __restrict__ ei,
                                                    const int* __restrict__ et) {
    int b = blockIdx.x, tid = threadIdx.x;
    if (b < ZT_BLOCKS) {
        int sub = tid >> 6, l = tid & 63;
        int jct = b*4 + sub;
        int j = jct & 255;
        int cc = jct >> 8;
        int c = cc % C_, t = cc / C_;
        int tc = t*C_ + c;
        int idx = g_tidx[(size_t)tc*FO_ + j];
        float tv = tanhf(g_vals[(size_t)tc*FO_ + j]);
        const float4* xr = (const float4*)(x + ((size_t)t*N_ + idx) * F_);
        float4 v = xr[l];
        v.x *= tv; v.y *= tv; v.z *= tv; v.w *= tv;
        ((float4*)(g_zt + ((size_t)tc*FO_ + j) * F_))[l] = v;
    } else {
        int idx = b - ZT_BLOCKS;
        int t = idx / 1250;
        int e = (idx - t*1250)*256 + tid;
        if (e >= E_) return;
        int row = ei[(size_t)t*2*E_ + e];
        int col = ei[(size_t)t*2*E_ + E_ + e];
        int r   = et[(size_t)t*E_ + e];
        int pos = g_off[t*(N_+1) + row] + atomicAdd(&g_fill[t*N_ + row], 1);
        g_epack[(size_t)t*E_ + pos] = ((uint32_t)col << 2) | (uint32_t)r;
    }
}

// ================== cell bodies (256 threads, 2x4 warps, warp tile 32x16) ==================
#define CELL_MMA8(As, Bs)                                                       \
    _Pragma("unroll")                                                           \
    for (int kc = 0; kc < 2; kc++) {                                            \
        int k0 = kc * 8;                                                        \
        uint32_t afr[2][4];                                                     \
        _Pragma("unroll")                                                       \
        for (int mt = 0; mt < 2; mt++) {                                        \
            int mb = wm*32 + mt*16;                                             \
            afr[mt][0] = __float_as_uint(As[k0 + tg    ][mb + grp    ]);        \
            afr[mt][1] = __float_as_uint(As[k0 + tg    ][mb + grp + 8]);        \
            afr[mt][2] = __float_as_uint(As[k0 + tg + 4][mb + grp    ]);        \
            afr[mt][3] = __float_as_uint(As[k0 + tg + 4][mb + grp + 8]);        \
        }                                                                       \
        _Pragma("unroll")                                                       \
        for (int nt = 0; nt < 2; nt++) {                                        \
            int nb = wn*16 + nt*8;                                              \
            uint32_t b0 = __float_as_uint(Bs[k0 + tg    ][nb + grp]);           \
            uint32_t b1 = __float_as_uint(Bs[k0 + tg + 4][nb + grp]);           \
            _Pragma("unroll")                                                   \
            for (int mt = 0; mt < 2; mt++)                                      \
                mma_tf32(d[mt][nt], afr[mt], b0, b1);                           \
        }                                                                       \
    }

__device__ void cell1_body(const float* W, const float* U, const float* B,
                           const float* Z, const float* Qm, float* OUT, int x16) {
    __shared__ float As[16][68], Bs[16][68];
    int tid = threadIdx.x, lane = tid & 31, wid = tid >> 5;
    int wm = wid >> 2, wn = wid & 3;
    int grp = lane >> 2, tg = lane & 3;
    int i0 = (x16 >> 2) * 64, j0 = (x16 & 3) * 64;

    float d[2][2][4];
    #pragma unroll
    for (int mt = 0; mt < 2; mt++)
        #pragma unroll
        for (int nt = 0; nt < 2; nt++)
            #pragma unroll
            for (int q = 0; q < 4; q++) d[mt][nt][q] = 0.f;

    int ar = tid >> 2, ac = (tid & 3) * 4;     // 64 rows x 16 k
    int qk = tid >> 4, qn = (tid & 15) * 4;    // 16 k x 64 n

    for (int kb = 0; kb < 256; kb += 16) {
        float4 a4 = *(const float4*)(W + (size_t)(i0+ar)*256 + kb + ac);
        As[ac  ][ar]=cvt_tf32(a4.x); As[ac+1][ar]=cvt_tf32(a4.y);
        As[ac+2][ar]=cvt_tf32(a4.z); As[ac+3][ar]=cvt_tf32(a4.w);
        float4 b4 = *(const float4*)(Z + (size_t)(j0+ar)*256 + kb + ac);
        Bs[ac  ][ar]=cvt_tf32(b4.x); Bs[ac+1][ar]=cvt_tf32(b4.y);
        Bs[ac+2][ar]=cvt_tf32(b4.z); Bs[ac+3][ar]=cvt_tf32(b4.w);
        __syncthreads();
        CELL_MMA8(As, Bs);
        __syncthreads();
    }
    for (int kb = 0; kb < 256; kb += 16) {
        float4 a4 = *(const float4*)(U + (size_t)(i0+ar)*256 + kb + ac);
        As[ac  ][ar]=cvt_tf32(a4.x); As[ac+1][ar]=cvt_tf32(a4.y);
        As[ac+2][ar]=cvt_tf32(a4.z); As[ac+3][ar]=cvt_tf32(a4.w);
        float4 b4 = *(const float4*)(Qm + (size_t)(kb+qk)*256 + j0 + qn);
        Bs[qk][qn  ]=cvt_tf32(b4.x); Bs[qk][qn+1]=cvt_tf32(b4.y);
        Bs[qk][qn+2]=cvt_tf32(b4.z); Bs[qk][qn+3]=cvt_tf32(b4.w);
        __syncthreads();
        CELL_MMA8(As, Bs);
        __syncthreads();
    }

    #pragma unroll
    for (int mt = 0; mt < 2; mt++) {
        #pragma unroll
        for (int nt = 0; nt < 2; nt++) {
            int r0 = i0 + wm*32 + mt*16 + grp;
            int col = j0 + wn*16 + nt*8 + 2*tg;
            float2 bi0 = *(const float2*)(B + (size_t)r0*256 + col);
            *(float2*)&OUT[(size_t)r0*256 + col] =
                make_float2(sigmoidf_(d[mt][nt][0] + bi0.x), sigmoidf_(d[mt][nt][1] + bi0.y));
            int r1 = r0 + 8;
            float2 bi1 = *(const float2*)(B + (size_t)r1*256 + col);
            *(float2*)&OUT[(size_t)r1*256 + col] =
                make_float2(sigmoidf_(d[mt][nt][2] + bi1.x), sigmoidf_(d[mt][nt][3] + bi1.y));
        }
    }
}

__device__ void cell2_body(const float* W, const float* U, const float* B,
                           const float* Z, const float* Qin, const float* RST,
                           const float* UPD, float* Qout, float* Qc, int x16) {
    __shared__ float As[16][68], Bs[16][68];
    int tid = threadIdx.x, lane = tid & 31, wid = tid >> 5;
    int wm = wid >> 2, wn = wid & 3;
    int grp = lane >> 2, tg = lane & 3;
    int i0 = (x16 >> 2) * 64, j0 = (x16 & 3) * 64;

    float d[2][2][4];
    #pragma unroll
    for (int mt = 0; mt < 2; mt++)
        #pragma unroll
        for (int nt = 0; nt < 2; nt++)
            #pragma unroll
            for (int q = 0; q < 4; q++) d[mt][nt][q] = 0.f;

    int ar = tid >> 2, ac = (tid & 3) * 4;
    int qk = tid >> 4, qn = (tid & 15) * 4;

    for (int kb = 0; kb < 256; kb += 16) {
        float4 a4 = *(const float4*)(W + (size_t)(i0+ar)*256 + kb + ac);
        As[ac  ][ar]=cvt_tf32(a4.x); As[ac+1][ar]=cvt_tf32(a4.y);
        As[ac+2][ar]=cvt_tf32(a4.z); As[ac+3][ar]=cvt_tf32(a4.w);
        float4 b4 = *(const float4*)(Z + (size_t)(j0+ar)*256 + kb + ac);
        Bs[ac  ][ar]=cvt_tf32(b4.x); Bs[ac+1][ar]=cvt_tf32(b4.y);
        Bs[ac+2][ar]=cvt_tf32(b4.z); Bs[ac+3][ar]=cvt_tf32(b4.w);
        __syncthreads();
        CELL_MMA8(As, Bs);
        __syncthreads();
    }
    for (int kb = 0; kb < 256; kb += 16) {
        float4 a4 = *(const float4*)(U + (size_t)(i0+ar)*256 + kb + ac);
        As[ac  ][ar]=cvt_tf32(a4.x); As[ac+1][ar]=cvt_tf32(a4.y);
        As[ac+2][ar]=cvt_tf32(a4.z); As[ac+3][ar]=cvt_tf32(a4.w);
        float4 b4 = *(const float4*)(Qin + (size_t)(kb+qk)*256 + j0 + qn);
        float4 r4 = *(const float4*)(RST + (size_t)(kb+qk)*256 + j0 + qn);
        Bs[qk][qn  ]=cvt_tf32(b4.x*r4.x); Bs[qk][qn+1]=cvt_tf32(b4.y*r4.y);
        Bs[qk][qn+2]=cvt_tf32(b4.z*r4.z); Bs[qk][qn+3]=cvt_tf32(b4.w*r4.w);
        __syncthreads();
        CELL_MMA8(As, Bs);
        __syncthreads();
    }

    #pragma unroll
    for (int mt = 0; mt < 2; mt++) {
        #pragma unroll
        for (int nt = 0; nt < 2; nt++) {
            #pragma unroll
            for (int half = 0; half < 2; half++) {
                int r = i0 + wm*32 + mt*16 + grp + half*8;
                int col = j0 + wn*16 + nt*8 + 2*tg;
                float d0 = d[mt][nt][half*2], d1 = d[mt][nt][half*2 + 1];
                float2 bi = *(const float2*)(B + (size_t)r*256 + col);
                float2 up = *(const float2*)(UPD + (size_t)r*256 + col);
                float2 qi = *(const float2*)(Qin + (size_t)r*256 + col);
                float h0 = tanhf(d0 + bi.x), h1 = tanhf(d1 + bi.y);
                float v0 = (1.f - up.x)*qi.x + up.x*h0;
                float v1 = (1.f - up.y)*qi.y + up.y*h1;
                *(float2*)&Qout[(size_t)r*256 + col] = make_float2(v0, v1);
                *(float2*)&Qc[(size_t)r*256 + col] = make_float2(cvt_tf32(v0), cvt_tf32(v1));
            }
        }
    }
}

__device__ __forceinline__ void cell1_sel(
    int o, int c,
    const float* sWz, const float* sUz, const float* sbz,
    const float* sWr, const float* sUr, const float* sbr,
    const float* rWz, const float* rUz, const float* rbz,
    const float* rWr, const float* rUr, const float* rbr,
    int par, int t, int x16) {
    const float *W, *U, *B;
    if (o == 0) { W = c ? rWz + (c-1)*MAT_ : sWz; U = c ? rUz + (c-1)*MAT_ : sUz; B = c ? rbz + (c-1)*MAT_ : sbz; }
    else        { W = c ? rWr + (c-1)*MAT_ : sWr; U = c ? rUr + (c-1)*MAT_ : sUr; B = c ? rbr + (c-1)*MAT_ : sbr; }
    cell1_body(W, U, B, g_zt + (size_t)(t*C_ + c)*MAT_, g_Q[par] + c*MAT_,
               (o == 0 ? g_upd : g_rst) + c*MAT_, x16);
}

// ================== big GEMM body ==================
#define GA_PAD 20
#define GB_PAD 264
#define G_STAGE (128*GA_PAD*4 + 16*GB_PAD*4)
#define G_SMEM  (2*G_STAGE)

__device__ void gemm_body(float* __restrict__ out, int t, int c, int m0) {
    const float* Ag = g_xc + (size_t)t*N_*F_;
    const float* Bg = g_Qc + (size_t)c*MAT_;
    float* dst = (c == 0) ? out + (size_t)t*N_*FO_ : g_Y + (size_t)(c-1)*N_*FO_;

    float* smf = (float*)s_dyn;
    uint32_t smb = smem_u32(s_dyn);
    int tid = threadIdx.x, wid = tid >> 5, lane = tid & 31;
    int wm = wid >> 2, wn = wid & 3;
    int grp = lane >> 2, tg = lane & 3;

    float d[4][8][4];
    #pragma unroll
    for (int mt = 0; mt < 4; mt++)
        #pragma unroll
        for (int nt = 0; nt < 8; nt++)
            #pragma unroll
            for (int q = 0; q < 4; q++) d[mt][nt][q] = 0.f;

    auto load_stage = [&](int stg, int kb) {
        uint32_t sa = smb + stg*G_STAGE;
        uint32_t sb = sa + 128*GA_PAD*4;
        #pragma unroll
        for (int i = 0; i < 2; i++) {
            int idx = tid + i*256;
            int row = idx >> 2, ch = idx & 3;
            int gr = m0 + row;
            uint32_t dsta = sa + (uint32_t)(row*GA_PAD + ch*4)*4;
            if (gr < N_) {
                cp_async16(dsta, Ag + (size_t)gr*F_ + kb + ch*4);
            } else {
                *(float4*)(s_dyn + (dsta - smb)) = make_float4(0.f, 0.f, 0.f, 0.f);
            }
        }
        #pragma unroll
        for (int i = 0; i < 4; i++) {
            int idx = tid + i*256;
            int kr = idx >> 6, nch = idx & 63;
            uint32_t dstb = sb + (uint32_t)(kr*GB_PAD + nch*4)*4;
            cp_async16(dstb, Bg + (size_t)(kb + kr)*FO_ + nch*4);
        }
        CP_COMMIT();
    };

    load_stage(0, 0);

    #pragma unroll 1
    for (int step = 0; step < 16; step++) {
        if (step + 1 < 16) load_stage((step + 1) & 1, (step + 1) * 16);
        if (step + 1 < 16) { CP_WAIT(1); } else { CP_WAIT(0); }
        __syncthreads();

        const float* As = smf + ((step & 1) ? G_STAGE/4 : 0);
        const float* Bs = As + 128*GA_PAD;

        #pragma unroll
        for (int kc = 0; kc < 2; kc++) {
            int k0 = kc * 8;
            uint32_t a[4][4];
            #pragma unroll
            for (int mt = 0; mt < 4; mt++) {
                int mb = wm*64 + mt*16;
                a[mt][0] = __float_as_uint(As[(mb + grp    )*GA_PAD + k0 + tg    ]);
                a[mt][1] = __float_as_uint(As[(mb + grp + 8)*GA_PAD + k0 + tg    ]);
                a[mt][2] = __float_as_uint(As[(mb + grp    )*GA_PAD + k0 + tg + 4]);
                a[mt][3] = __float_as_uint(As[(mb + grp + 8)*GA_PAD + k0 + tg + 4]);
            }
            #pragma unroll
            for (int nt = 0; nt < 8; nt++) {
                int nb = wn*64 + nt*8;
                uint32_t b0 = __float_as_uint(Bs[(k0 + tg    )*GB_PAD + nb + grp]);
                uint32_t b1 = __float_as_uint(Bs[(k0 + tg + 4)*GB_PAD + nb + grp]);
                #pragma unroll
                for (int mt = 0; mt < 4; mt++)
                    mma_tf32(d[mt][nt], a[mt], b0, b1);
            }
        }
        __syncthreads();
    }

    #pragma unroll
    for (int mt = 0; mt < 4; mt++) {
        #pragma unroll
        for (int nt = 0; nt < 8; nt++) {
            int r0 = m0 + wm*64 + mt*16 + grp;
            int col = wn*64 + nt*8 + 2*tg;
            if (r0 < N_)
                *(float2*)&dst[(size_t)r0*FO_ + col] = make_float2(d[mt][nt][0], d[mt][nt][1]);
            int r1 = r0 + 8;
            if (r1 < N_)
                *(float2*)&dst[(size_t)r1*FO_ + col] = make_float2(d[mt][nt][2], d[mt][nt][3]);
        }
    }
}

// ================== agg body ==================
__device__ void agg_body(float* __restrict__ out, int t, int blk) {
    int warp = threadIdx.x >> 5, lane = threadIdx.x & 31;
    int row = blk * 8 + warp;
    if (row >= N_) return;
    const float* dis = g_dis + (size_t)t*R_*N_;
    float disrow[R_];
    #pragma unroll
    for (int r = 0; r < R_; r++) disrow[r] = dis[r*N_ + row];
    float4 a0 = make_float4(0.f, 0.f, 0.f, 0.f);
    float4 a1 = make_float4(0.f, 0.f, 0.f, 0.f);
    int beg = g_off[t*(N_+1) + row], end = g_off[t*(N_+1) + row + 1];
    const uint32_t* ep = g_epack + (size_t)t*E_;
    for (int p = beg; p < end; p++) {
        uint32_t pk = ep[p];
        int r = pk & 3;
        int col = pk >> 2;
        float norm = disrow[r] * dis[r*N_ + col];
        if (norm != 0.f) {
            const float4* src = (const float4*)(g_Y + ((size_t)r*N_ + col) * FO_);
            float4 v0 = src[lane];
            float4 v1 = src[lane + 32];
            a0.x += v0.x*norm; a0.y += v0.y*norm; a0.z += v0.z*norm; a0.w += v0.w*norm;
            a1.x += v1.x*norm; a1.y += v1.y*norm; a1.z += v1.z*norm; a1.w += v1.w*norm;
        }
    }
    float4* dst = (float4*)(out + (size_t)t*N_*FO_ + (size_t)row*FO_);
    float4 o0 = dst[lane];
    float4 o1 = dst[lane + 32];
    o0.x = fmaxf(o0.x + a0.x, 0.f); o0.y = fmaxf(o0.y + a0.y, 0.f);
    o0.z = fmaxf(o0.z + a0.z, 0.f); o0.w = fmaxf(o0.w + a0.w, 0.f);
    o1.x = fmaxf(o1.x + a1.x, 0.f); o1.y = fmaxf(o1.y + a1.y, 0.f);
    o1.z = fmaxf(o1.z + a1.z, 0.f); o1.w = fmaxf(o1.w + a1.w, 0.f);
    dst[lane] = o0;
    dst[lane + 32] = o1;
}

// ================== merged per-t kernels ==================
__global__ __launch_bounds__(256) void k_gemm_cell1(
    float* __restrict__ out, int t,
    const float* sWz, const float* sUz, const float* sbz,
    const float* sWr, const float* sUr, const float* sbr,
    const float* rWz, const float* rUz, const float* rbz,
    const float* rWr, const float* rUr, const float* rbr,
    int parNext, int tNext, int doCell) {
    int z = blockIdx.z;
    if (z < C_) {
        gemm_body(out, t, z, blockIdx.x * 128);
    } else {
        if (!doCell || blockIdx.x >= 16) return;
        int u = z - C_;
        cell1_sel(u & 1, u >> 1, sWz, sUz, sbz, sWr, sUr, sbr,
                  rWz, rUz, rbz, rWr, rUr, rbr, parNext, tNext, blockIdx.x);
    }
}

__global__ __launch_bounds__(256) void k_agg_cell2(
    float* __restrict__ out, int t,
    const float* sWh, const float* sUh, const float* sbh,
    const float* rWh, const float* rUh, const float* rbh,
    int parNext, int tNext, int doCell) {
    int x = blockIdx.x;
    if (x < 2500) {
        agg_body(out, t, x);
    } else {
        if (!doCell) return;
        int u = x - 2500;     // 0..79
        int c = u >> 4, x16 = u & 15;
        const float* W = c ? rWh + (c-1)*MAT_ : sWh;
        const float* U = c ? rUh + (c-1)*MAT_ : sUh;
        const float* B = c ? rbh + (c-1)*MAT_ : sbh;
        cell2_body(W, U, B, g_zt + (size_t)(tNext*C_ + c)*MAT_,
                   g_Q[parNext] + c*MAT_, g_rst + c*MAT_, g_upd + c*MAT_,
                   g_Q[parNext ^ 1] + c*MAT_, g_Qc + c*MAT_, x16);
    }
}

// standalone cell launches for t=0
__global__ __launch_bounds__(256) void k_cell1_only(
    const float* sWz, const float* sUz, const float* sbz,
    const float* sWr, const float* sUr, const float* sbr,
    const float* rWz, const float* rUz, const float* rbz,
    const float* rWr, const float* rUr, const float* rbr,
    int par, int t) {
    int u = blockIdx.z;
    cell1_sel(u & 1, u >> 1, sWz, sUz, sbz, sWr, sUr, sbr,
              rWz, rUz, rbz, rWr, rUr, rbr, par, t, blockIdx.x);
}
__global__ __launch_bounds__(256) void k_cell2_only(
    const float* sWh, const float* sUh, const float* sbh,
    const float* rWh, const float* rUh, const float* rbh,
    int par, int t) {
    int c = blockIdx.z;
    const float* W = c ? rWh + (c-1)*MAT_ : sWh;
    const float* U = c ? rUh + (c-1)*MAT_ : sUh;
    const float* B = c ? rbh + (c-1)*MAT_ : sbh;
    cell2_body(W, U, B, g_zt + (size_t)(t*C_ + c)*MAT_,
               g_Q[par] + c*MAT_, g_rst + c*MAT_, g_upd + c*MAT_,
               g_Q[par ^ 1] + c*MAT_, g_Qc + c*MAT_, blockIdx.x);
}

// ================== launcher ==================
extern "C" void kernel_launch(void* const* d_in, const int* in_sizes, int n_in,
                              void* d_out, int out_size) {
    const float* x       = (const float*)d_in[0];
    const float* mask    = (const float*)d_in[1];
    const float* Wself   = (const float*)d_in[2];
    const float* Wrel    = (const float*)d_in[3];
    const float* sWz     = (const float*)d_in[4];
    const float* sUz     = (const float*)d_in[5];
    const float* sbz     = (const float*)d_in[6];
    const float* sWr     = (const float*)d_in[7];
    const float* sUr     = (const float*)d_in[8];
    const float* sbr     = (const float*)d_in[9];
    const float* sWh     = (const float*)d_in[10];
    const float* sUh     = (const float*)d_in[11];
    const float* sbh     = (const float*)d_in[12];
    const float* s_sc    = (const float*)d_in[13];
    const float* rWz     = (const float*)d_in[14];
    const float* rUz     = (const float*)d_in[15];
    const float* rbz     = (const float*)d_in[16];
    const float* rWr     = (const float*)d_in[17];
    const float* rUr     = (const float*)d_in[18];
    const float* rbr     = (const float*)d_in[19];
    const float* rWh     = (const float*)d_in[20];
    const float* rUh     = (const float*)d_in[21];
    const float* rbh     = (const float*)d_in[22];
    const float* r_sc    = (const float*)d_in[23];
    const int*   ei      = (const int*)d_in[24];
    const int*   et      = (const int*)d_in[25];
    float* out = (float*)d_out;

    static bool attr_set = false;
    if (!attr_set) {
        cudaFuncSetAttribute(k_sel, cudaFuncAttributeMaxDynamicSharedMemorySize,
                             N_ * (int)sizeof(uint32_t));
        cudaFuncSetAttribute(k_gemm_cell1, cudaFuncAttributeMaxDynamicSharedMemorySize,
                             G_SMEM);
        attr_set = true;
    }

    // preamble (4 launches)
    k_prep<<<PB_TOTAL, 256>>>(Wself, Wrel, x, s_sc, r_sc);
    k_scores_edge<<<7500 + 3750, 256>>>(x, mask, s_sc, r_sc, ei, et);
    k_sel<<<T_*C_ + T_ + SEL_DIS_BLOCKS, 1024, N_ * sizeof(uint32_t)>>>();
    k_zt_scatter<<<ZT_BLOCKS + 3750, 256>>>(x, ei, et);

    // t = 0 cells (standalone)
    k_cell1_only<<<dim3(16, 1, 2*C_), 256>>>(sWz, sUz, sbz, sWr, sUr, sbr,
                                             rWz, rUz, rbz, rWr, rUr, rbr, 0, 0);
    k_cell2_only<<<dim3(16, 1, C_), 256>>>(sWh, sUh, sbh, rWh, rUh, rbh, 0, 0);

    // pipelined recurrence: gemm(t) || cell1(t+1), agg(t) || cell2(t+1)
    for (int t = 0; t < T_; t++) {
        int doCell = (t + 1 < T_) ? 1 : 0;
        int parN = (t + 1) & 1;
        k_gemm_cell1<<<dim3((N_ + 127)/128, 1, C_ + 2*C_), 256, G_SMEM>>>(
            out, t, sWz, sUz, sbz, sWr, sUr, sbr,
            rWz, rUz, rbz, rWr, rUr, rbr, parN, t + 1, doCell);
        k_agg_cell2<<<2500 + 80, 256>>>(
            out, t, sWh, sUh, sbh, rWh, rUh, rbh, parN, t + 1, doCell);
    }
}

// round 8
// speedup vs baseline: 4.1787x; 1.0810x over previous
#include <cuda_runtime.h>
#include <math.h>
#include <stdint.h>

#define T_ 3
#define N_ 20000
#define F_ 256
#define FO_ 256
#define E_ 320000
#define R_ 4
#define C_ 5
#define MAT_ (F_*FO_)

// ---------------- scratch ----------------
__device__ float g_scores[T_*C_*N_];
__device__ float g_vals  [T_*C_*FO_];
__device__ int   g_tidx  [T_*C_*FO_];
__device__ float g_zt    [T_*C_*MAT_];
__device__ float g_upd   [C_*MAT_];
__device__ float g_rst   [C_*MAT_];
__device__ float g_Q  [2][C_*MAT_];
__device__ float g_Qc    [C_*MAT_];
__device__ float g_xc    [T_*N_*F_];
__device__ float g_Y     [R_*N_*FO_];
__device__ int   g_degI  [T_*R_*N_];
__device__ float g_dis   [T_*R_*N_];
__device__ float g_denom [C_];
__device__ int      g_cnt [T_*N_];
__device__ int      g_off [T_*(N_+1)];
__device__ int      g_fill[T_*N_];
__device__ uint32_t g_epack[T_*E_];

extern __shared__ unsigned char s_dyn[];

__device__ __forceinline__ uint32_t f2key(float f) {
    uint32_t u = __float_as_uint(f);
    return (u & 0x80000000u) ? ~u : (u | 0x80000000u);
}
__device__ __forceinline__ float key2f(uint32_t k) {
    return (k & 0x80000000u) ? __uint_as_float(k & 0x7FFFFFFFu) : __uint_as_float(~k);
}
__device__ __forceinline__ float cvt_tf32(float f) {
    uint32_t r;
    asm("cvt.rna.tf32.f32 %0, %1;" : "=r"(r) : "f"(f));
    return __uint_as_float(r);
}
__device__ __forceinline__ float sigmoidf_(float v) { return 1.f / (1.f + expf(-v)); }

__device__ __forceinline__ void mma_tf32(float* d, const uint32_t* a, uint32_t b0, uint32_t b1) {
    asm volatile(
        "mma.sync.aligned.m16n8k8.row.col.f32.tf32.tf32.f32 "
        "{%0,%1,%2,%3}, {%4,%5,%6,%7}, {%8,%9}, {%0,%1,%2,%3};"
        : "+f"(d[0]), "+f"(d[1]), "+f"(d[2]), "+f"(d[3])
        : "r"(a[0]), "r"(a[1]), "r"(a[2]), "r"(a[3]), "r"(b0), "r"(b1));
}
__device__ __forceinline__ uint32_t smem_u32(const void* p) {
    uint32_t a;
    asm("{ .reg .u64 t; cvta.to.shared.u64 t, %1; cvt.u32.u64 %0, t; }" : "=r"(a) : "l"(p));
    return a;
}
__device__ __forceinline__ void cp_async16(uint32_t dst, const void* src) {
    asm volatile("cp.async.ca.shared.global [%0], [%1], 16;" :: "r"(dst), "l"(src) : "memory");
}
#define CP_COMMIT()  asm volatile("cp.async.commit_group;" ::: "memory")
#define CP_WAIT(n)   asm volatile("cp.async.wait_group %0;" :: "n"(n) : "memory")

// ================== PREAMBLE (merged) ==================
#define PB_INIT  ((C_*MAT_)/256)
#define PB_XCVT  ((T_*N_*F_/4)/256)
#define PB_ZERO  (((T_*R_*N_)+255)/256)
#define PB_TOTAL (PB_INIT + PB_XCVT + PB_ZERO + C_)

__global__ __launch_bounds__(256) void k_prep(const float* __restrict__ Wself,
                                              const float* __restrict__ Wrel,
                                              const float* __restrict__ x,
                                              const float* __restrict__ s_sc,
                                              const float* __restrict__ r_sc) {
    int b = blockIdx.x, tid = threadIdx.x;
    if (b < PB_INIT) {
        int i = b*256 + tid;
        int c = i / MAT_, off = i - c*MAT_;
        g_Q[0][i] = (c == 0) ? Wself[off] : Wrel[(c-1)*MAT_ + off];
    } else if (b < PB_INIT + PB_XCVT) {
        int i = (b - PB_INIT)*256 + tid;
        float4 v = ((const float4*)x)[i];
        v.x = cvt_tf32(v.x); v.y = cvt_tf32(v.y);
        v.z = cvt_tf32(v.z); v.w = cvt_tf32(v.w);
        ((float4*)g_xc)[i] = v;
    } else if (b < PB_INIT + PB_XCVT + PB_ZERO) {
        int i = (b - PB_INIT - PB_XCVT)*256 + tid;
        if (i < T_*R_*N_) g_degI[i] = 0;
        if (i < T_*N_) g_cnt[i] = 0;
    } else {
        int c = b - (PB_INIT + PB_XCVT + PB_ZERO);
        const float* sc = (c == 0) ? s_sc : r_sc + (c-1)*F_;
        float v = sc[tid];
        __shared__ float red[256];
        red[tid] = v * v;
        __syncthreads();
        for (int o = 128; o > 0; o >>= 1) {
            if (tid < o) red[tid] += red[tid + o];
            __syncthreads();
        }
        if (tid == 0) g_denom[c] = sqrtf(red[0]) + 1e-8f;
    }
}

__global__ __launch_bounds__(256) void k_scores_edge(const float* __restrict__ x,
                                                     const float* __restrict__ mask,
                                                     const float* __restrict__ s_sc,
                                                     const float* __restrict__ r_sc,
                                                     const int* __restrict__ ei,
                                                     const int* __restrict__ et) {
    int b = blockIdx.x, tid = threadIdx.x;
    if (b < 7500) {
        int t = b / 2500, blk = b - t*2500;
        __shared__ float sc[C_][F_];
        for (int i = tid; i < C_*F_; i += 256) {
            int c = i / F_, f = i - c*F_;
            sc[c][f] = (c == 0) ? s_sc[f] : r_sc[(c-1)*F_ + f];
        }
        __syncthreads();
        int warp = tid >> 5, lane = tid & 31;
        int n = blk * 8 + warp;
        if (n >= N_) return;
        const float* xr = x + ((size_t)t*N_ + n) * F_;
        float acc[C_] = {0.f, 0.f, 0.f, 0.f, 0.f};
        #pragma unroll
        for (int q = 0; q < 8; q++) {
            float xv = xr[lane + q*32];
            #pragma unroll
            for (int c = 0; c < C_; c++) acc[c] += xv * sc[c][lane + q*32];
        }
        #pragma unroll
        for (int c = 0; c < C_; c++) {
            float v = acc[c];
            for (int o = 16; o > 0; o >>= 1) v += __shfl_down_sync(0xffffffffu, v, o);
            if (lane == 0)
                g_scores[(size_t)(t*C_ + c)*N_ + n] = v / g_denom[c] + mask[(size_t)t*N_ + n];
        }
    } else {
        int idx = b - 7500;
        int t = idx / 1250;
        int e = (idx - t*1250)*256 + tid;
        if (e >= E_) return;
        int row = ei[(size_t)t*2*E_ + e];
        int r   = et[(size_t)t*E_ + e];
        atomicAdd(&g_degI[(t*R_ + r)*N_ + row], 1);
        atomicAdd(&g_cnt[t*N_ + row], 1);
    }
}

// ================== topk + scan + dis ==================
__device__ void topk_body(int tc) {
    uint32_t* s_keys = (uint32_t*)s_dyn;
    __shared__ int      hist[256];
    __shared__ int      sfx[256];
    __shared__ uint32_t selKey[256];
    __shared__ int      selIdx[256];
    __shared__ uint32_t s_prefix;
    __shared__ int      s_remaining, s_eqCount, s_idxTh, s_cnt;

    int tid = threadIdx.x;
    const float* sc = g_scores + (size_t)tc * N_;

    if (tid < 256) hist[tid] = 0;
    if (tid == 0) { s_prefix = 0u; s_remaining = FO_; s_idxTh = 0x7FFFFFFF; s_eqCount = FO_; }
    __syncthreads();

    for (int i = tid; i < N_; i += 1024) {
        uint32_t k = f2key(sc[i]);
        s_keys[i] = k;
        atomicAdd(&hist[k >> 24], 1);
    }
    __syncthreads();

    #pragma unroll
    for (int pass = 3; pass >= 0; pass--) {
        int shift = pass * 8;
        if (pass < 3) {
            if (tid < 256) hist[tid] = 0;
            __syncthreads();
            uint32_t prefix = s_prefix;
            uint32_t pmask = 0xFFFFFFFFu << (shift + 8);
            for (int i = tid; i < N_; i += 1024) {
                uint32_t k = s_keys[i];
                if ((k & pmask) == (prefix & pmask))
                    atomicAdd(&hist[(k >> shift) & 0xFF], 1);
            }
            __syncthreads();
        }
        if (tid < 256) sfx[tid] = hist[tid];
        __syncthreads();
        #pragma unroll
        for (int o = 1; o < 256; o <<= 1) {
            int v = 0;
            if (tid < 256) v = sfx[tid] + ((tid + o < 256) ? sfx[tid + o] : 0);
            __syncthreads();
            if (tid < 256) sfx[tid] = v;
            __syncthreads();
        }
        int rem = s_remaining;
        __syncthreads();
        if (tid < 256) {
            int s  = sfx[tid];
            int sn = (tid < 255) ? sfx[tid + 1] : 0;
            if (s >= rem && sn < rem) {
                s_prefix |= ((uint32_t)tid) << shift;
                s_remaining = rem - sn;
                if (pass == 0) s_eqCount = hist[tid];
            }
        }
        __syncthreads();
    }
    uint32_t kth = s_prefix;
    int need = s_remaining;

    if (need < s_eqCount) {
        if (tid == 0) { s_prefix = 0u; s_remaining = need; }
        __syncthreads();
        #pragma unroll
        for (int pass = 1; pass >= 0; pass--) {
            int shift = pass * 8;
            if (tid < 256) hist[tid] = 0;
            __syncthreads();
            uint32_t prefixI = s_prefix;
            for (int i = tid; i < N_; i += 1024) {
                if (s_keys[i] == kth) {
                    if (pass == 1 || (((uint32_t)i >> 8) & 0xFF) == ((prefixI >> 8) & 0xFF))
                        atomicAdd(&hist[((uint32_t)i >> shift) & 0xFF], 1);
                }
            }
            __syncthreads();
            if (tid == 0) {
                int rem = s_remaining;
                uint32_t pfx = s_prefix;
                for (int bb = 0; bb < 256; bb++) {
                    int cnt = hist[bb];
                    if (cnt >= rem) { pfx |= ((uint32_t)bb) << shift; break; }
                    rem -= cnt;
                }
                s_remaining = rem;
                s_prefix = pfx;
            }
            __syncthreads();
        }
        if (tid == 0) s_idxTh = (int)s_prefix;
    }
    if (tid == 0) s_cnt = 0;
    __syncthreads();
    int idxTh = s_idxTh;

    for (int i = tid; i < N_; i += 1024) {
        uint32_t k = s_keys[i];
        if (k > kth || (k == kth && i <= idxTh)) {
            int p = atomicAdd(&s_cnt, 1);
            selKey[p] = k;
            selIdx[p] = i;
        }
    }
    __syncthreads();

    for (int k = 2; k <= 256; k <<= 1) {
        for (int j = k >> 1; j > 0; j >>= 1) {
            if (tid < 256) {
                int ixj = tid ^ j;
                if (ixj > tid) {
                    bool desc = ((tid & k) == 0);
                    uint32_t ka = selKey[tid], kb = selKey[ixj];
                    int ia = selIdx[tid], ib = selIdx[ixj];
                    bool aGreater = (ka > kb) || (ka == kb && ia < ib);
                    bool doswap = desc ? !aGreater : aGreater;
                    if (doswap) {
                        selKey[tid] = kb; selKey[ixj] = ka;
                        selIdx[tid] = ib; selIdx[ixj] = ia;
                    }
                }
            }
            __syncthreads();
        }
    }

    if (tid < 256) {
        g_vals[(size_t)tc*FO_ + tid] = key2f(selKey[tid]);
        g_tidx[(size_t)tc*FO_ + tid] = selIdx[tid];
    }
}

__device__ void scan_body(int t) {
    __shared__ int part[1024];
    const int* cnt = g_cnt + t*N_;
    int* off = g_off + t*(N_+1);
    int* fill = g_fill + t*N_;
    int tid = threadIdx.x;
    const int CH = (N_ + 1023) / 1024;
    int base = tid * CH;
    int s = 0;
    for (int i = 0; i < CH; i++) {
        int idx = base + i;
        if (idx < N_) s += cnt[idx];
    }
    part[tid] = s;
    __syncthreads();
    for (int o = 1; o < 1024; o <<= 1) {
        int v = (tid >= o) ? part[tid - o] : 0;
        __syncthreads();
        part[tid] += v;
        __syncthreads();
    }
    int run = (tid == 0) ? 0 : part[tid - 1];
    for (int i = 0; i < CH; i++) {
        int idx = base + i;
        if (idx < N_) {
            off[idx] = run;
            run += cnt[idx];
            fill[idx] = 0;
        }
    }
    if (tid == 0) off[N_] = E_;
}

#define SEL_DIS_BLOCKS (((T_*R_*N_)+1023)/1024)
__global__ __launch_bounds__(1024) void k_sel() {
    int b = blockIdx.x;
    if (b < T_*C_) {
        topk_body(b);
    } else if (b < T_*C_ + T_) {
        scan_body(b - T_*C_);
    } else {
        int i = (b - T_*C_ - T_)*1024 + threadIdx.x;
        if (i < T_*R_*N_) {
            int d = g_degI[i];
            g_dis[i] = (d > 0) ? (1.f / sqrtf((float)d)) : 0.f;
        }
    }
}

// ================== zt + scatter ==================
#define ZT_BLOCKS ((T_*C_*FO_)/4)
__global__ __launch_bounds__(256) void k_zt_scatter(const float* __restrict__ x,
                                                    const int* __restrict__ ei,
                                                    const int* __restrict__ et) {
    int b = blockIdx.x, tid = threadIdx.x;
    if (b < ZT_BLOCKS) {
        int sub = tid >> 6, l = tid & 63;
        int jct = b*4 + sub;
        int j = jct & 255;
        int cc = jct >> 8;
        int c = cc % C_, t = cc / C_;
        int tc = t*C_ + c;
        int idx = g_tidx[(size_t)tc*FO_ + j];
        float tv = tanhf(g_vals[(size_t)tc*FO_ + j]);
        const float4* xr = (const float4*)(x + ((size_t)t*N_ + idx) * F_);
        float4 v = xr[l];
        v.x *= tv; v.y *= tv; v.z *= tv; v.w *= tv;
        ((float4*)(g_zt + ((size_t)tc*FO_ + j) * F_))[l] = v;
    } else {
        int idx = b - ZT_BLOCKS;
        int t = idx / 1250;
        int e = (idx - t*1250)*256 + tid;
        if (e >= E_) return;
        int row = ei[(size_t)t*2*E_ + e];
        int col = ei[(size_t)t*2*E_ + E_ + e];
        int r   = et[(size_t)t*E_ + e];
        int pos = g_off[t*(N_+1) + row] + atomicAdd(&g_fill[t*N_ + row], 1);
        g_epack[(size_t)t*E_ + pos] = ((uint32_t)col << 2) | (uint32_t)r;
    }
}

// ================== cell bodies ==================
#define CELL_MMA8(As, Bs)                                                       \
    _Pragma("unroll")                                                           \
    for (int kc = 0; kc < 2; kc++) {                                            \
        int k0 = kc * 8;                                                        \
        uint32_t afr[2][4];                                                     \
        _Pragma("unroll")                                                       \
        for (int mt = 0; mt < 2; mt++) {                                        \
            int mb = wm*32 + mt*16;                                             \
            afr[mt][0] = __float_as_uint(As[k0 + tg    ][mb + grp    ]);        \
            afr[mt][1] = __float_as_uint(As[k0 + tg    ][mb + grp + 8]);        \
            afr[mt][2] = __float_as_uint(As[k0 + tg + 4][mb + grp    ]);        \
            afr[mt][3] = __float_as_uint(As[k0 + tg + 4][mb + grp + 8]);        \
        }                                                                       \
        _Pragma("unroll")                                                       \
        for (int nt = 0; nt < 2; nt++) {                                        \
            int nb = wn*16 + nt*8;                                              \
            uint32_t b0 = __float_as_uint(Bs[k0 + tg    ][nb + grp]);           \
            uint32_t b1 = __float_as_uint(Bs[k0 + tg + 4][nb + grp]);           \
            _Pragma("unroll")                                                   \
            for (int mt = 0; mt < 2; mt++)                                      \
                mma_tf32(d[mt][nt], afr[mt], b0, b1);                           \
        }                                                                       \
    }

__device__ void cell1_body(const float* W, const float* U, const float* B,
                           const float* Z, const float* Qm, float* OUT, int x16) {
    __shared__ float As[16][68], Bs[16][68];
    int tid = threadIdx.x, lane = tid & 31, wid = tid >> 5;
    int wm = wid >> 2, wn = wid & 3;
    int grp = lane >> 2, tg = lane & 3;
    int i0 = (x16 >> 2) * 64, j0 = (x16 & 3) * 64;

    float d[2][2][4];
    #pragma unroll
    for (int mt = 0; mt < 2; mt++)
        #pragma unroll
        for (int nt = 0; nt < 2; nt++)
            #pragma unroll
            for (int q = 0; q < 4; q++) d[mt][nt][q] = 0.f;

    int ar = tid >> 2, ac = (tid & 3) * 4;
    int qk = tid >> 4, qn = (tid & 15) * 4;

    for (int kb = 0; kb < 256; kb += 16) {
        float4 a4 = *(const float4*)(W + (size_t)(i0+ar)*256 + kb + ac);
        As[ac  ][ar]=cvt_tf32(a4.x); As[ac+1][ar]=cvt_tf32(a4.y);
        As[ac+2][ar]=cvt_tf32(a4.z); As[ac+3][ar]=cvt_tf32(a4.w);
        float4 b4 = *(const float4*)(Z + (size_t)(j0+ar)*256 + kb + ac);
        Bs[ac  ][ar]=cvt_tf32(b4.x); Bs[ac+1][ar]=cvt_tf32(b4.y);
        Bs[ac+2][ar]=cvt_tf32(b4.z); Bs[ac+3][ar]=cvt_tf32(b4.w);
        __syncthreads();
        CELL_MMA8(As, Bs);
        __syncthreads();
    }
    for (int kb = 0; kb < 256; kb += 16) {
        float4 a4 = *(const float4*)(U + (size_t)(i0+ar)*256 + kb + ac);
        As[ac  ][ar]=cvt_tf32(a4.x); As[ac+1][ar]=cvt_tf32(a4.y);
        As[ac+2][ar]=cvt_tf32(a4.z); As[ac+3][ar]=cvt_tf32(a4.w);
        float4 b4 = *(const float4*)(Qm + (size_t)(kb+qk)*256 + j0 + qn);
        Bs[qk][qn  ]=cvt_tf32(b4.x); Bs[qk][qn+1]=cvt_tf32(b4.y);
        Bs[qk][qn+2]=cvt_tf32(b4.z); Bs[qk][qn+3]=cvt_tf32(b4.w);
        __syncthreads();
        CELL_MMA8(As, Bs);
        __syncthreads();
    }

    #pragma unroll
    for (int mt = 0; mt < 2; mt++) {
        #pragma unroll
        for (int nt = 0; nt < 2; nt++) {
            int r0 = i0 + wm*32 + mt*16 + grp;
            int col = j0 + wn*16 + nt*8 + 2*tg;
            float2 bi0 = *(const float2*)(B + (size_t)r0*256 + col);
            *(float2*)&OUT[(size_t)r0*256 + col] =
                make_float2(sigmoidf_(d[mt][nt][0] + bi0.x), sigmoidf_(d[mt][nt][1] + bi0.y));
            int r1 = r0 + 8;
            float2 bi1 = *(const float2*)(B + (size_t)r1*256 + col);
            *(float2*)&OUT[(size_t)r1*256 + col] =
                make_float2(sigmoidf_(d[mt][nt][2] + bi1.x), sigmoidf_(d[mt][nt][3] + bi1.y));
        }
    }
}

__device__ void cell2_body(const float* W, const float* U, const float* B,
                           const float* Z, const float* Qin, const float* RST,
                           const float* UPD, float* Qout, float* Qc, int x16) {
    __shared__ float As[16][68], Bs[16][68];
    int tid = threadIdx.x, lane = tid & 31, wid = tid >> 5;
    int wm = wid >> 2, wn = wid & 3;
    int grp = lane >> 2, tg = lane & 3;
    int i0 = (x16 >> 2) * 64, j0 = (x16 & 3) * 64;

    float d[2][2][4];
    #pragma unroll
    for (int mt = 0; mt < 2; mt++)
        #pragma unroll
        for (int nt = 0; nt < 2; nt++)
            #pragma unroll
            for (int q = 0; q < 4; q++) d[mt][nt][q] = 0.f;

    int ar = tid >> 2, ac = (tid & 3) * 4;
    int qk = tid >> 4, qn = (tid & 15) * 4;

    for (int kb = 0; kb < 256; kb += 16) {
        float4 a4 = *(const float4*)(W + (size_t)(i0+ar)*256 + kb + ac);
        As[ac  ][ar]=cvt_tf32(a4.x); As[ac+1][ar]=cvt_tf32(a4.y);
        As[ac+2][ar]=cvt_tf32(a4.z); As[ac+3][ar]=cvt_tf32(a4.w);
        float4 b4 = *(const float4*)(Z + (size_t)(j0+ar)*256 + kb + ac);
        Bs[ac  ][ar]=cvt_tf32(b4.x); Bs[ac+1][ar]=cvt_tf32(b4.y);
        Bs[ac+2][ar]=cvt_tf32(b4.z); Bs[ac+3][ar]=cvt_tf32(b4.w);
        __syncthreads();
        CELL_MMA8(As, Bs);
        __syncthreads();
    }
    for (int kb = 0; kb < 256; kb += 16) {
        float4 a4 = *(const float4*)(U + (size_t)(i0+ar)*256 + kb + ac);
        As[ac  ][ar]=cvt_tf32(a4.x); As[ac+1][ar]=cvt_tf32(a4.y);
        As[ac+2][ar]=cvt_tf32(a4.z); As[ac+3][ar]=cvt_tf32(a4.w);
        float4 b4 = *(const float4*)(Qin + (size_t)(kb+qk)*256 + j0 + qn);
        float4 r4 = *(const float4*)(RST + (size_t)(kb+qk)*256 + j0 + qn);
        Bs[qk][qn  ]=cvt_tf32(b4.x*r4.x); Bs[qk][qn+1]=cvt_tf32(b4.y*r4.y);
        Bs[qk][qn+2]=cvt_tf32(b4.z*r4.z); Bs[qk][qn+3]=cvt_tf32(b4.w*r4.w);
        __syncthreads();
        CELL_MMA8(As, Bs);
        __syncthreads();
    }

    #pragma unroll
    for (int mt = 0; mt < 2; mt++) {
        #pragma unroll
        for (int nt = 0; nt < 2; nt++) {
            #pragma unroll
            for (int half = 0; half < 2; half++) {
                int r = i0 + wm*32 + mt*16 + grp + half*8;
                int col = j0 + wn*16 + nt*8 + 2*tg;
                float d0 = d[mt][nt][half*2], d1 = d[mt][nt][half*2 + 1];
                float2 bi = *(const float2*)(B + (size_t)r*256 + col);
                float2 up = *(const float2*)(UPD + (size_t)r*256 + col);
                float2 qi = *(const float2*)(Qin + (size_t)r*256 + col);
                float h0 = tanhf(d0 + bi.x), h1 = tanhf(d1 + bi.y);
                float v0 = (1.f - up.x)*qi.x + up.x*h0;
                float v1 = (1.f - up.y)*qi.y + up.y*h1;
                *(float2*)&Qout[(size_t)r*256 + col] = make_float2(v0, v1);
                *(float2*)&Qc[(size_t)r*256 + col] = make_float2(cvt_tf32(v0), cvt_tf32(v1));
            }
        }
    }
}

__device__ __forceinline__ void cell1_sel(
    int o, int c,
    const float* sWz, const float* sUz, const float* sbz,
    const float* sWr, const float* sUr, const float* sbr,
    const float* rWz, const float* rUz, const float* rbz,
    const float* rWr, const float* rUr, const float* rbr,
    int par, int t, int x16) {
    const float *W, *U, *B;
    if (o == 0) { W = c ? rWz + (c-1)*MAT_ : sWz; U = c ? rUz + (c-1)*MAT_ : sUz; B = c ? rbz + (c-1)*MAT_ : sbz; }
    else        { W = c ? rWr + (c-1)*MAT_ : sWr; U = c ? rUr + (c-1)*MAT_ : sUr; B = c ? rbr + (c-1)*MAT_ : sbr; }
    cell1_body(W, U, B, g_zt + (size_t)(t*C_ + c)*MAT_, g_Q[par] + c*MAT_,
               (o == 0 ? g_upd : g_rst) + c*MAT_, x16);
}

// ================== big GEMM body: 128x128 tile, 2 CTAs/SM ==================
#define GA_PAD 20
#define GB_PAD 136
#define G_STAGE (128*GA_PAD*4 + 16*GB_PAD*4)    // 10240 + 8704 = 18944
#define G_SMEM  (2*G_STAGE)                      // 37888

__device__ void gemm_body(float* __restrict__ out, int t, int c, int m0, int n0) {
    const float* Ag = g_xc + (size_t)t*N_*F_;
    const float* Bg = g_Qc + (size_t)c*MAT_;
    float* dst = (c == 0) ? out + (size_t)t*N_*FO_ : g_Y + (size_t)(c-1)*N_*FO_;

    float* smf = (float*)s_dyn;
    uint32_t smb = smem_u32(s_dyn);
    int tid = threadIdx.x, wid = tid >> 5, lane = tid & 31;
    int wm = wid >> 1, wn = wid & 1;       // 4 x 2 warps, warp tile 32x64
    int grp = lane >> 2, tg = lane & 3;

    float d[2][8][4];
    #pragma unroll
    for (int mt = 0; mt < 2; mt++)
        #pragma unroll
        for (int nt = 0; nt < 8; nt++)
            #pragma unroll
            for (int q = 0; q < 4; q++) d[mt][nt][q] = 0.f;

    auto load_stage = [&](int stg, int kb) {
        uint32_t sa = smb + stg*G_STAGE;
        uint32_t sb = sa + 128*GA_PAD*4;
        // A: 128 rows x 16 k = 512 x 16B, 2/thread
        #pragma unroll
        for (int i = 0; i < 2; i++) {
            int idx = tid + i*256;
            int row = idx >> 2, ch = idx & 3;
            int gr = m0 + row;
            uint32_t dsta = sa + (uint32_t)(row*GA_PAD + ch*4)*4;
            if (gr < N_) {
                cp_async16(dsta, Ag + (size_t)gr*F_ + kb + ch*4);
            } else {
                *(float4*)(s_dyn + (dsta - smb)) = make_float4(0.f, 0.f, 0.f, 0.f);
            }
        }
        // B: 16 krows x 128 n = 512 x 16B, 2/thread
        #pragma unroll
        for (int i = 0; i < 2; i++) {
            int idx = tid + i*256;
            int kr = idx >> 5, nch = idx & 31;
            uint32_t dstb = sb + (uint32_t)(kr*GB_PAD + nch*4)*4;
            cp_async16(dstb, Bg + (size_t)(kb + kr)*FO_ + n0 + nch*4);
        }
        CP_COMMIT();
    };

    load_stage(0, 0);

    #pragma unroll 1
    for (int step = 0; step < 16; step++) {
        if (step + 1 < 16) load_stage((step + 1) & 1, (step + 1) * 16);
        if (step + 1 < 16) { CP_WAIT(1); } else { CP_WAIT(0); }
        __syncthreads();

        const float* As = smf + ((step & 1) ? G_STAGE/4 : 0);
        const float* Bs = As + 128*GA_PAD;

        #pragma unroll
        for (int kc = 0; kc < 2; kc++) {
            int k0 = kc * 8;
            uint32_t a[2][4];
            #pragma unroll
            for (int mt = 0; mt < 2; mt++) {
                int mb = wm*32 + mt*16;
                a[mt][0] = __float_as_uint(As[(mb + grp    )*GA_PAD + k0 + tg    ]);
                a[mt][1] = __float_as_uint(As[(mb + grp + 8)*GA_PAD + k0 + tg    ]);
                a[mt][2] = __float_as_uint(As[(mb + grp    )*GA_PAD + k0 + tg + 4]);
                a[mt][3] = __float_as_uint(As[(mb + grp + 8)*GA_PAD + k0 + tg + 4]);
            }
            #pragma unroll
            for (int nt = 0; nt < 8; nt++) {
                int nb = wn*64 + nt*8;
                uint32_t b0 = __float_as_uint(Bs[(k0 + tg    )*GB_PAD + nb + grp]);
                uint32_t b1 = __float_as_uint(Bs[(k0 + tg + 4)*GB_PAD + nb + grp]);
                #pragma unroll
                for (int mt = 0; mt < 2; mt++)
                    mma_tf32(d[mt][nt], a[mt], b0, b1);
            }
        }
        __syncthreads();
    }

    #pragma unroll
    for (int mt = 0; mt < 2; mt++) {
        #pragma unroll
        for (int nt = 0; nt < 8; nt++) {
            int r0 = m0 + wm*32 + mt*16 + grp;
            int col = n0 + wn*64 + nt*8 + 2*tg;
            if (r0 < N_)
                *(float2*)&dst[(size_t)r0*FO_ + col] = make_float2(d[mt][nt][0], d[mt][nt][1]);
            int r1 = r0 + 8;
            if (r1 < N_)
                *(float2*)&dst[(size_t)r1*FO_ + col] = make_float2(d[mt][nt][2], d[mt][nt][3]);
        }
    }
}

// ================== agg body ==================
__device__ void agg_body(float* __restrict__ out, int t, int blk) {
    int warp = threadIdx.x >> 5, lane = threadIdx.x & 31;
    int row = blk * 8 + warp;
    if (row >= N_) return;
    const float* dis = g_dis + (size_t)t*R_*N_;
    float disrow[R_];
    #pragma unroll
    for (int r = 0; r < R_; r++) disrow[r] = dis[r*N_ + row];
    float4 a0 = make_float4(0.f, 0.f, 0.f, 0.f);
    float4 a1 = make_float4(0.f, 0.f, 0.f, 0.f);
    int beg = g_off[t*(N_+1) + row], end = g_off[t*(N_+1) + row + 1];
    const uint32_t* ep = g_epack + (size_t)t*E_;
    for (int p = beg; p < end; p++) {
        uint32_t pk = ep[p];
        int r = pk & 3;
        int col = pk >> 2;
        float norm = disrow[r] * dis[r*N_ + col];
        if (norm != 0.f) {
            const float4* src = (const float4*)(g_Y + ((size_t)r*N_ + col) * FO_);
            float4 v0 = src[lane];
            float4 v1 = src[lane + 32];
            a0.x += v0.x*norm; a0.y += v0.y*norm; a0.z += v0.z*norm; a0.w += v0.w*norm;
            a1.x += v1.x*norm; a1.y += v1.y*norm; a1.z += v1.z*norm; a1.w += v1.w*norm;
        }
    }
    float4* dst = (float4*)(out + (size_t)t*N_*FO_ + (size_t)row*FO_);
    float4 o0 = dst[lane];
    float4 o1 = dst[lane + 32];
    o0.x = fmaxf(o0.x + a0.x, 0.f); o0.y = fmaxf(o0.y + a0.y, 0.f);
    o0.z = fmaxf(o0.z + a0.z, 0.f); o0.w = fmaxf(o0.w + a0.w, 0.f);
    o1.x = fmaxf(o1.x + a1.x, 0.f); o1.y = fmaxf(o1.y + a1.y, 0.f);
    o1.z = fmaxf(o1.z + a1.z, 0.f); o1.w = fmaxf(o1.w + a1.w, 0.f);
    dst[lane] = o0;
    dst[lane + 32] = o1;
}

// ================== merged per-t kernels ==================
__global__ __launch_bounds__(256, 2) void k_gemm_cell1(
    float* __restrict__ out, int t,
    const float* sWz, const float* sUz, const float* sbz,
    const float* sWr, const float* sUr, const float* sbr,
    const float* rWz, const float* rUz, const float* rbz,
    const float* rWr, const float* rUr, const float* rbr,
    int parNext, int tNext, int doCell) {
    int z = blockIdx.z;
    if (z < C_) {
        gemm_body(out, t, z, blockIdx.x * 128, blockIdx.y * 128);
    } else {
        if (!doCell || blockIdx.x >= 16 || blockIdx.y != 0) return;
        int u = z - C_;
        cell1_sel(u & 1, u >> 1, sWz, sUz, sbz, sWr, sUr, sbr,
                  rWz, rUz, rbz, rWr, rUr, rbr, parNext, tNext, blockIdx.x);
    }
}

__global__ __launch_bounds__(256) void k_agg_cell2(
    float* __restrict__ out, int t,
    const float* sWh, const float* sUh, const float* sbh,
    const float* rWh, const float* rUh, const float* rbh,
    int parNext, int tNext, int doCell) {
    int x = blockIdx.x;
    if (x < 2500) {
        agg_body(out, t, x);
    } else {
        if (!doCell) return;
        int u = x - 2500;
        int c = u >> 4, x16 = u & 15;
        const float* W = c ? rWh + (c-1)*MAT_ : sWh;
        const float* U = c ? rUh + (c-1)*MAT_ : sUh;
        const float* B = c ? rbh + (c-1)*MAT_ : sbh;
        cell2_body(W, U, B, g_zt + (size_t)(tNext*C_ + c)*MAT_,
                   g_Q[parNext] + c*MAT_, g_rst + c*MAT_, g_upd + c*MAT_,
                   g_Q[parNext ^ 1] + c*MAT_, g_Qc + c*MAT_, x16);
    }
}

// standalone cell launches for t=0
__global__ __launch_bounds__(256) void k_cell1_only(
    const float* sWz, const float* sUz, const float* sbz,
    const float* sWr, const float* sUr, const float* sbr,
    const float* rWz, const float* rUz, const float* rbz,
    const float* rWr, const float* rUr, const float* rbr,
    int par, int t) {
    int u = blockIdx.z;
    cell1_sel(u & 1, u >> 1, sWz, sUz, sbz, sWr, sUr, sbr,
              rWz, rUz, rbz, rWr, rUr, rbr, par, t, blockIdx.x);
}
__global__ __launch_bounds__(256) void k_cell2_only(
    const float* sWh, const float* sUh, const float* sbh,
    const float* rWh, const float* rUh, const float* rbh,
    int par, int t) {
    int c = blockIdx.z;
    const float* W = c ? rWh + (c-1)*MAT_ : sWh;
    const float* U = c ? rUh + (c-1)*MAT_ : sUh;
    const float* B = c ? rbh + (c-1)*MAT_ : sbh;
    cell2_body(W, U, B, g_zt + (size_t)(t*C_ + c)*MAT_,
               g_Q[par] + c*MAT_, g_rst + c*MAT_, g_upd + c*MAT_,
               g_Q[par ^ 1] + c*MAT_, g_Qc + c*MAT_, blockIdx.x);
}

// ================== launcher ==================
extern "C" void kernel_launch(void* const* d_in, const int* in_sizes, int n_in,
                              void* d_out, int out_size) {
    const float* x       = (const float*)d_in[0];
    const float* mask    = (const float*)d_in[1];
    const float* Wself   = (const float*)d_in[2];
    const float* Wrel    = (const float*)d_in[3];
    const float* sWz     = (const float*)d_in[4];
    const float* sUz     = (const float*)d_in[5];
    const float* sbz     = (const float*)d_in[6];
    const float* sWr     = (const float*)d_in[7];
    const float* sUr     = (const float*)d_in[8];
    const float* sbr     = (const float*)d_in[9];
    const float* sWh     = (const float*)d_in[10];
    const float* sUh     = (const float*)d_in[11];
    const float* sbh     = (const float*)d_in[12];
    const float* s_sc    = (const float*)d_in[13];
    const float* rWz     = (const float*)d_in[14];
    const float* rUz     = (const float*)d_in[15];
    const float* rbz     = (const float*)d_in[16];
    const float* rWr     = (const float*)d_in[17];
    const float* rUr     = (const float*)d_in[18];
    const float* rbr     = (const float*)d_in[19];
    const float* rWh     = (const float*)d_in[20];
    const float* rUh     = (const float*)d_in[21];
    const float* rbh     = (const float*)d_in[22];
    const float* r_sc    = (const float*)d_in[23];
    const int*   ei      = (const int*)d_in[24];
    const int*   et      = (const int*)d_in[25];
    float* out = (float*)d_out;

    static bool attr_set = false;
    if (!attr_set) {
        cudaFuncSetAttribute(k_sel, cudaFuncAttributeMaxDynamicSharedMemorySize,
                             N_ * (int)sizeof(uint32_t));
        cudaFuncSetAttribute(k_gemm_cell1, cudaFuncAttributeMaxDynamicSharedMemorySize,
                             G_SMEM);
        attr_set = true;
    }

    // preamble
    k_prep<<<PB_TOTAL, 256>>>(Wself, Wrel, x, s_sc, r_sc);
    k_scores_edge<<<7500 + 3750, 256>>>(x, mask, s_sc, r_sc, ei, et);
    k_sel<<<T_*C_ + T_ + SEL_DIS_BLOCKS, 1024, N_ * sizeof(uint32_t)>>>();
    k_zt_scatter<<<ZT_BLOCKS + 3750, 256>>>(x, ei, et);

    // t = 0 cells
    k_cell1_only<<<dim3(16, 1, 2*C_), 256>>>(sWz, sUz, sbz, sWr, sUr, sbr,
                                             rWz, rUz, rbz, rWr, rUr, rbr, 0, 0);
    k_cell2_only<<<dim3(16, 1, C_), 256>>>(sWh, sUh, sbh, rWh, rUh, rbh, 0, 0);

    // pipelined recurrence
    for (int t = 0; t < T_; t++) {
        int doCell = (t + 1 < T_) ? 1 : 0;
        int parN = (t + 1) & 1;
        k_gemm_cell1<<<dim3((N_ + 127)/128, 2, C_ + 2*C_), 256, G_SMEM>>>(
            out, t, sWz, sUz, sbz, sWr, sUr, sbr,
            rWz, rUz, rbz, rWr, rUr, rbr, parN, t + 1, doCell);
        k_agg_cell2<<<2500 + 80, 256>>>(
            out, t, sWh, sUh, sbh, rWh, rUh, rbh, parN, t + 1, doCell);
    }
}

// round 9
// speedup vs baseline: 4.8968x; 1.1718x over previous
#include <cuda_runtime.h>
#include <math.h>
#include <stdint.h>

#define T_ 3
#define N_ 20000
#define F_ 256
#define FO_ 256
#define E_ 320000
#define R_ 4
#define C_ 5
#define MAT_ (F_*FO_)

// ---------------- scratch ----------------
__device__ float g_scores[T_*C_*N_];
__device__ float g_vals  [T_*C_*FO_];
__device__ int   g_tidx  [T_*C_*FO_];
__device__ float g_zt    [T_*C_*MAT_];
__device__ float g_upd   [C_*MAT_];
__device__ float g_rst   [C_*MAT_];
__device__ float g_Q  [2][C_*MAT_];
__device__ float g_Qc    [C_*MAT_];
__device__ float g_xc    [T_*N_*F_];
__device__ float g_Y     [R_*N_*FO_];
__device__ int   g_degI  [T_*R_*N_];
__device__ float g_dis   [T_*R_*N_];
__device__ float g_denom [C_];
__device__ int      g_cnt [T_*N_];
__device__ int      g_off [T_*(N_+1)];
__device__ int      g_fill[T_*N_];
__device__ uint32_t g_epack[T_*E_];

extern __shared__ unsigned char s_dyn[];

__device__ __forceinline__ uint32_t f2key(float f) {
    uint32_t u = __float_as_uint(f);
    return (u & 0x80000000u) ? ~u : (u | 0x80000000u);
}
__device__ __forceinline__ float key2f(uint32_t k) {
    return (k & 0x80000000u) ? __uint_as_float(k & 0x7FFFFFFFu) : __uint_as_float(~k);
}
__device__ __forceinline__ float cvt_tf32(float f) {
    uint32_t r;
    asm("cvt.rna.tf32.f32 %0, %1;" : "=r"(r) : "f"(f));
    return __uint_as_float(r);
}
__device__ __forceinline__ float sigmoidf_(float v) { return 1.f / (1.f + expf(-v)); }

__device__ __forceinline__ void mma_tf32(float* d, const uint32_t* a, uint32_t b0, uint32_t b1) {
    asm volatile(
        "mma.sync.aligned.m16n8k8.row.col.f32.tf32.tf32.f32 "
        "{%0,%1,%2,%3}, {%4,%5,%6,%7}, {%8,%9}, {%0,%1,%2,%3};"
        : "+f"(d[0]), "+f"(d[1]), "+f"(d[2]), "+f"(d[3])
        : "r"(a[0]), "r"(a[1]), "r"(a[2]), "r"(a[3]), "r"(b0), "r"(b1));
}
__device__ __forceinline__ uint32_t smem_u32(const void* p) {
    uint32_t a;
    asm("{ .reg .u64 t; cvta.to.shared.u64 t, %1; cvt.u32.u64 %0, t; }" : "=r"(a) : "l"(p));
    return a;
}
__device__ __forceinline__ void cp_async16(uint32_t dst, const void* src) {
    asm volatile("cp.async.ca.shared.global [%0], [%1], 16;" :: "r"(dst), "l"(src) : "memory");
}
#define CP_COMMIT()  asm volatile("cp.async.commit_group;" ::: "memory")
#define CP_WAIT(n)   asm volatile("cp.async.wait_group %0;" :: "n"(n) : "memory")

// ================== PREAMBLE ==================
#define PB_INIT  ((C_*MAT_)/256)
#define PB_XCVT  ((T_*N_*F_/4)/256)
#define PB_ZERO  (((T_*R_*N_)+255)/256)
#define PB_TOTAL (PB_INIT + PB_XCVT + PB_ZERO + C_)

__global__ __launch_bounds__(256) void k_prep(const float* __restrict__ Wself,
                                              const float* __restrict__ Wrel,
                                              const float* __restrict__ x,
                                              const float* __restrict__ s_sc,
                                              const float* __restrict__ r_sc) {
    int b = blockIdx.x, tid = threadIdx.x;
    if (b < PB_INIT) {
        int i = b*256 + tid;
        int c = i / MAT_, off = i - c*MAT_;
        g_Q[0][i] = (c == 0) ? Wself[off] : Wrel[(c-1)*MAT_ + off];
    } else if (b < PB_INIT + PB_XCVT) {
        int i = (b - PB_INIT)*256 + tid;
        float4 v = ((const float4*)x)[i];
        v.x = cvt_tf32(v.x); v.y = cvt_tf32(v.y);
        v.z = cvt_tf32(v.z); v.w = cvt_tf32(v.w);
        ((float4*)g_xc)[i] = v;
    } else if (b < PB_INIT + PB_XCVT + PB_ZERO) {
        int i = (b - PB_INIT - PB_XCVT)*256 + tid;
        if (i < T_*R_*N_) g_degI[i] = 0;
        if (i < T_*N_) g_cnt[i] = 0;
    } else {
        int c = b - (PB_INIT + PB_XCVT + PB_ZERO);
        const float* sc = (c == 0) ? s_sc : r_sc + (c-1)*F_;
        float v = sc[tid];
        __shared__ float red[256];
        red[tid] = v * v;
        __syncthreads();
        for (int o = 128; o > 0; o >>= 1) {
            if (tid < o) red[tid] += red[tid + o];
            __syncthreads();
        }
        if (tid == 0) g_denom[c] = sqrtf(red[0]) + 1e-8f;
    }
}

__global__ __launch_bounds__(256) void k_scores_edge(const float* __restrict__ x,
                                                     const float* __restrict__ mask,
                                                     const float* __restrict__ s_sc,
                                                     const float* __restrict__ r_sc,
                                                     const int* __restrict__ ei,
                                                     const int* __restrict__ et) {
    int b = blockIdx.x, tid = threadIdx.x;
    if (b < 7500) {
        int t = b / 2500, blk = b - t*2500;
        __shared__ float sc[C_][F_];
        for (int i = tid; i < C_*F_; i += 256) {
            int c = i / F_, f = i - c*F_;
            sc[c][f] = (c == 0) ? s_sc[f] : r_sc[(c-1)*F_ + f];
        }
        __syncthreads();
        int warp = tid >> 5, lane = tid & 31;
        int n = blk * 8 + warp;
        if (n >= N_) return;
        const float4* xr = (const float4*)(x + ((size_t)t*N_ + n) * F_);
        float acc[C_] = {0.f, 0.f, 0.f, 0.f, 0.f};
        #pragma unroll
        for (int q = 0; q < 2; q++) {
            float4 xv = xr[lane + q*32];
            int e0 = (lane + q*32) * 4;
            #pragma unroll
            for (int c = 0; c < C_; c++) {
                acc[c] += xv.x * sc[c][e0]   + xv.y * sc[c][e0+1]
                        + xv.z * sc[c][e0+2] + xv.w * sc[c][e0+3];
            }
        }
        #pragma unroll
        for (int c = 0; c < C_; c++) {
            float v = acc[c];
            for (int o = 16; o > 0; o >>= 1) v += __shfl_down_sync(0xffffffffu, v, o);
            if (lane == 0)
                g_scores[(size_t)(t*C_ + c)*N_ + n] = v / g_denom[c] + mask[(size_t)t*N_ + n];
        }
    } else {
        int idx = b - 7500;
        int t = idx / 1250;
        int e = (idx - t*1250)*256 + tid;
        if (e >= E_) return;
        int row = ei[(size_t)t*2*E_ + e];
        int r   = et[(size_t)t*E_ + e];
        atomicAdd(&g_degI[(t*R_ + r)*N_ + row], 1);
        atomicAdd(&g_cnt[t*N_ + row], 1);
    }
}

// ================== topk + scan + dis ==================
__device__ void topk_body(int tc) {
    uint32_t* s_keys = (uint32_t*)s_dyn;
    __shared__ int      hist[256];
    __shared__ int      sfx[256];
    __shared__ uint32_t selKey[256];
    __shared__ int      selIdx[256];
    __shared__ uint32_t s_prefix;
    __shared__ int      s_remaining, s_eqCount, s_idxTh, s_cnt;

    int tid = threadIdx.x;
    const float* sc = g_scores + (size_t)tc * N_;

    if (tid < 256) hist[tid] = 0;
    if (tid == 0) { s_prefix = 0u; s_remaining = FO_; s_idxTh = 0x7FFFFFFF; s_eqCount = FO_; }
    __syncthreads();

    for (int i = tid; i < N_; i += 1024) {
        uint32_t k = f2key(sc[i]);
        s_keys[i] = k;
        atomicAdd(&hist[k >> 24], 1);
    }
    __syncthreads();

    #pragma unroll
    for (int pass = 3; pass >= 0; pass--) {
        int shift = pass * 8;
        if (pass < 3) {
            if (tid < 256) hist[tid] = 0;
            __syncthreads();
            uint32_t prefix = s_prefix;
            uint32_t pmask = 0xFFFFFFFFu << (shift + 8);
            for (int i = tid; i < N_; i += 1024) {
                uint32_t k = s_keys[i];
                if ((k & pmask) == (prefix & pmask))
                    atomicAdd(&hist[(k >> shift) & 0xFF], 1);
            }
            __syncthreads();
        }
        if (tid < 256) sfx[tid] = hist[tid];
        __syncthreads();
        #pragma unroll
        for (int o = 1; o < 256; o <<= 1) {
            int v = 0;
            if (tid < 256) v = sfx[tid] + ((tid + o < 256) ? sfx[tid + o] : 0);
            __syncthreads();
            if (tid < 256) sfx[tid] = v;
            __syncthreads();
        }
        int rem = s_remaining;
        __syncthreads();
        if (tid < 256) {
            int s  = sfx[tid];
            int sn = (tid < 255) ? sfx[tid + 1] : 0;
            if (s >= rem && sn < rem) {
                s_prefix |= ((uint32_t)tid) << shift;
                s_remaining = rem - sn;
                if (pass == 0) s_eqCount = hist[tid];
            }
        }
        __syncthreads();
    }
    uint32_t kth = s_prefix;
    int need = s_remaining;

    if (need < s_eqCount) {
        if (tid == 0) { s_prefix = 0u; s_remaining = need; }
        __syncthreads();
        #pragma unroll
        for (int pass = 1; pass >= 0; pass--) {
            int shift = pass * 8;
            if (tid < 256) hist[tid] = 0;
            __syncthreads();
            uint32_t prefixI = s_prefix;
            for (int i = tid; i < N_; i += 1024) {
                if (s_keys[i] == kth) {
                    if (pass == 1 || (((uint32_t)i >> 8) & 0xFF) == ((prefixI >> 8) & 0xFF))
                        atomicAdd(&hist[((uint32_t)i >> shift) & 0xFF], 1);
                }
            }
            __syncthreads();
            if (tid == 0) {
                int rem = s_remaining;
                uint32_t pfx = s_prefix;
                for (int bb = 0; bb < 256; bb++) {
                    int cnt = hist[bb];
                    if (cnt >= rem) { pfx |= ((uint32_t)bb) << shift; break; }
                    rem -= cnt;
                }
                s_remaining = rem;
                s_prefix = pfx;
            }
            __syncthreads();
        }
        if (tid == 0) s_idxTh = (int)s_prefix;
    }
    if (tid == 0) s_cnt = 0;
    __syncthreads();
    int idxTh = s_idxTh;

    for (int i = tid; i < N_; i += 1024) {
        uint32_t k = s_keys[i];
        if (k > kth || (k == kth && i <= idxTh)) {
            int p = atomicAdd(&s_cnt, 1);
            selKey[p] = k;
            selIdx[p] = i;
        }
    }
    __syncthreads();

    for (int k = 2; k <= 256; k <<= 1) {
        for (int j = k >> 1; j > 0; j >>= 1) {
            if (tid < 256) {
                int ixj = tid ^ j;
                if (ixj > tid) {
                    bool desc = ((tid & k) == 0);
                    uint32_t ka = selKey[tid], kb = selKey[ixj];
                    int ia = selIdx[tid], ib = selIdx[ixj];
                    bool aGreater = (ka > kb) || (ka == kb && ia < ib);
                    bool doswap = desc ? !aGreater : aGreater;
                    if (doswap) {
                        selKey[tid] = kb; selKey[ixj] = ka;
                        selIdx[tid] = ib; selIdx[ixj] = ia;
                    }
                }
            }
            __syncthreads();
        }
    }

    if (tid < 256) {
        g_vals[(size_t)tc*FO_ + tid] = key2f(selKey[tid]);
        g_tidx[(size_t)tc*FO_ + tid] = selIdx[tid];
    }
}

__device__ void scan_body(int t) {
    __shared__ int part[1024];
    const int* cnt = g_cnt + t*N_;
    int* off = g_off + t*(N_+1);
    int* fill = g_fill + t*N_;
    int tid = threadIdx.x;
    const int CH = (N_ + 1023) / 1024;
    int base = tid * CH;
    int s = 0;
    for (int i = 0; i < CH; i++) {
        int idx = base + i;
        if (idx < N_) s += cnt[idx];
    }
    part[tid] = s;
    __syncthreads();
    for (int o = 1; o < 1024; o <<= 1) {
        int v = (tid >= o) ? part[tid - o] : 0;
        __syncthreads();
        part[tid] += v;
        __syncthreads();
    }
    int run = (tid == 0) ? 0 : part[tid - 1];
    for (int i = 0; i < CH; i++) {
        int idx = base + i;
        if (idx < N_) {
            off[idx] = run;
            run += cnt[idx];
            fill[idx] = 0;
        }
    }
    if (tid == 0) off[N_] = E_;
}

#define SEL_DIS_BLOCKS (((T_*R_*N_)+1023)/1024)
__global__ __launch_bounds__(1024) void k_sel() {
    int b = blockIdx.x;
    if (b < T_*C_) {
        topk_body(b);
    } else if (b < T_*C_ + T_) {
        scan_body(b - T_*C_);
    } else {
        int i = (b - T_*C_ - T_)*1024 + threadIdx.x;
        if (i < T_*R_*N_) {
            int d = g_degI[i];
            g_dis[i] = (d > 0) ? (1.f / sqrtf((float)d)) : 0.f;
        }
    }
}

// ================== zt + scatter ==================
#define ZT_BLOCKS ((T_*C_*FO_)/4)
__global__ __launch_bounds__(256) void k_zt_scatter(const float* __restrict__ x,
                                                    const int* __restrict__ ei,
                                                    const int* __restrict__ et) {
    int b = blockIdx.x, tid = threadIdx.x;
    if (b < ZT_BLOCKS) {
        int sub = tid >> 6, l = tid & 63;
        int jct = b*4 + sub;
        int j = jct & 255;
        int cc = jct >> 8;
        int c = cc % C_, t = cc / C_;
        int tc = t*C_ + c;
        int idx = g_tidx[(size_t)tc*FO_ + j];
        float tv = tanhf(g_vals[(size_t)tc*FO_ + j]);
        const float4* xr = (const float4*)(x + ((size_t)t*N_ + idx) * F_);
        float4 v = xr[l];
        v.x *= tv; v.y *= tv; v.z *= tv; v.w *= tv;
        ((float4*)(g_zt + ((size_t)tc*FO_ + j) * F_))[l] = v;
    } else {
        int idx = b - ZT_BLOCKS;
        int t = idx / 1250;
        int e = (idx - t*1250)*256 + tid;
        if (e >= E_) return;
        int row = ei[(size_t)t*2*E_ + e];
        int col = ei[(size_t)t*2*E_ + E_ + e];
        int r   = et[(size_t)t*E_ + e];
        int pos = g_off[t*(N_+1) + row] + atomicAdd(&g_fill[t*N_ + row], 1);
        g_epack[(size_t)t*E_ + pos] = ((uint32_t)col << 2) | (uint32_t)r;
    }
}

// ================== cell bodies ==================
// cell1: 128 threads, 4 warps (2x2), warp tile 32x32
#define CELL_MMA_128(As, Bs)                                                    \
    _Pragma("unroll")                                                           \
    for (int kc = 0; kc < 2; kc++) {                                            \
        int k0 = kc * 8;                                                        \
        uint32_t afr[2][4];                                                     \
        _Pragma("unroll")                                                       \
        for (int mt = 0; mt < 2; mt++) {                                        \
            int mb = wm*32 + mt*16;                                             \
            afr[mt][0] = __float_as_uint(As[k0 + tg    ][mb + grp    ]);        \
            afr[mt][1] = __float_as_uint(As[k0 + tg    ][mb + grp + 8]);        \
            afr[mt][2] = __float_as_uint(As[k0 + tg + 4][mb + grp    ]);        \
            afr[mt][3] = __float_as_uint(As[k0 + tg + 4][mb + grp + 8]);        \
        }                                                                       \
        _Pragma("unroll")                                                       \
        for (int nt = 0; nt < 4; nt++) {                                        \
            int nb = wn*32 + nt*8;                                              \
            uint32_t b0 = __float_as_uint(Bs[k0 + tg    ][nb + grp]);           \
            uint32_t b1 = __float_as_uint(Bs[k0 + tg + 4][nb + grp]);           \
            _Pragma("unroll")                                                   \
            for (int mt = 0; mt < 2; mt++)                                      \
                mma_tf32(d[mt][nt], afr[mt], b0, b1);                           \
        }                                                                       \
    }

__device__ void cell1_body(const float* W, const float* U, const float* B,
                           const float* Z, const float* Qm, float* OUT, int x16) {
    __shared__ float As[16][68], Bs[16][68];
    int tid = threadIdx.x, lane = tid & 31, wid = tid >> 5;
    int wm = wid >> 1, wn = wid & 1;
    int grp = lane >> 2, tg = lane & 3;
    int i0 = (x16 >> 2) * 64, j0 = (x16 & 3) * 64;

    float d[2][4][4];
    #pragma unroll
    for (int mt = 0; mt < 2; mt++)
        #pragma unroll
        for (int nt = 0; nt < 4; nt++)
            #pragma unroll
            for (int q = 0; q < 4; q++) d[mt][nt][q] = 0.f;

    int ar = tid >> 1, ac = (tid & 1) * 8;
    int qk = tid >> 3, qn = (tid & 7) * 8;

    for (int kb = 0; kb < 256; kb += 16) {
        float4 a4 = *(const float4*)(W + (size_t)(i0+ar)*256 + kb + ac);
        float4 a5 = *(const float4*)(W + (size_t)(i0+ar)*256 + kb + ac + 4);
        As[ac  ][ar]=cvt_tf32(a4.x); As[ac+1][ar]=cvt_tf32(a4.y);
        As[ac+2][ar]=cvt_tf32(a4.z); As[ac+3][ar]=cvt_tf32(a4.w);
        As[ac+4][ar]=cvt_tf32(a5.x); As[ac+5][ar]=cvt_tf32(a5.y);
        As[ac+6][ar]=cvt_tf32(a5.z); As[ac+7][ar]=cvt_tf32(a5.w);
        float4 b4 = *(const float4*)(Z + (size_t)(j0+ar)*256 + kb + ac);
        float4 b5 = *(const float4*)(Z + (size_t)(j0+ar)*256 + kb + ac + 4);
        Bs[ac  ][ar]=cvt_tf32(b4.x); Bs[ac+1][ar]=cvt_tf32(b4.y);
        Bs[ac+2][ar]=cvt_tf32(b4.z); Bs[ac+3][ar]=cvt_tf32(b4.w);
        Bs[ac+4][ar]=cvt_tf32(b5.x); Bs[ac+5][ar]=cvt_tf32(b5.y);
        Bs[ac+6][ar]=cvt_tf32(b5.z); Bs[ac+7][ar]=cvt_tf32(b5.w);
        __syncthreads();
        CELL_MMA_128(As, Bs);
        __syncthreads();
    }
    for (int kb = 0; kb < 256; kb += 16) {
        float4 a4 = *(const float4*)(U + (size_t)(i0+ar)*256 + kb + ac);
        float4 a5 = *(const float4*)(U + (size_t)(i0+ar)*256 + kb + ac + 4);
        As[ac  ][ar]=cvt_tf32(a4.x); As[ac+1][ar]=cvt_tf32(a4.y);
        As[ac+2][ar]=cvt_tf32(a4.z); As[ac+3][ar]=cvt_tf32(a4.w);
        As[ac+4][ar]=cvt_tf32(a5.x); As[ac+5][ar]=cvt_tf32(a5.y);
        As[ac+6][ar]=cvt_tf32(a5.z); As[ac+7][ar]=cvt_tf32(a5.w);
        float4 b4 = *(const float4*)(Qm + (size_t)(kb+qk)*256 + j0 + qn);
        float4 b5 = *(const float4*)(Qm + (size_t)(kb+qk)*256 + j0 + qn + 4);
        Bs[qk][qn  ]=cvt_tf32(b4.x); Bs[qk][qn+1]=cvt_tf32(b4.y);
        Bs[qk][qn+2]=cvt_tf32(b4.z); Bs[qk][qn+3]=cvt_tf32(b4.w);
        Bs[qk][qn+4]=cvt_tf32(b5.x); Bs[qk][qn+5]=cvt_tf32(b5.y);
        Bs[qk][qn+6]=cvt_tf32(b5.z); Bs[qk][qn+7]=cvt_tf32(b5.w);
        __syncthreads();
        CELL_MMA_128(As, Bs);
        __syncthreads();
    }

    #pragma unroll
    for (int mt = 0; mt < 2; mt++) {
        #pragma unroll
        for (int nt = 0; nt < 4; nt++) {
            int r0 = i0 + wm*32 + mt*16 + grp;
            int col = j0 + wn*32 + nt*8 + 2*tg;
            float2 bi0 = *(const float2*)(B + (size_t)r0*256 + col);
            *(float2*)&OUT[(size_t)r0*256 + col] =
                make_float2(sigmoidf_(d[mt][nt][0] + bi0.x), sigmoidf_(d[mt][nt][1] + bi0.y));
            int r1 = r0 + 8;
            float2 bi1 = *(const float2*)(B + (size_t)r1*256 + col);
            *(float2*)&OUT[(size_t)r1*256 + col] =
                make_float2(sigmoidf_(d[mt][nt][2] + bi1.x), sigmoidf_(d[mt][nt][3] + bi1.y));
        }
    }
}

// cell2: 256 threads, 8 warps (2x4), warp tile 32x16
#define CELL_MMA_256(As, Bs)                                                    \
    _Pragma("unroll")                                                           \
    for (int kc = 0; kc < 2; kc++) {                                            \
        int k0 = kc * 8;                                                        \
        uint32_t afr[2][4];                                                     \
        _Pragma("unroll")                                                       \
        for (int mt = 0; mt < 2; mt++) {                                        \
            int mb = wm*32 + mt*16;                                             \
            afr[mt][0] = __float_as_uint(As[k0 + tg    ][mb + grp    ]);        \
            afr[mt][1] = __float_as_uint(As[k0 + tg    ][mb + grp + 8]);        \
            afr[mt][2] = __float_as_uint(As[k0 + tg + 4][mb + grp    ]);        \
            afr[mt][3] = __float_as_uint(As[k0 + tg + 4][mb + grp + 8]);        \
        }                                                                       \
        _Pragma("unroll")                                                       \
        for (int nt = 0; nt < 2; nt++) {                                        \
            int nb = wn*16 + nt*8;                                              \
            uint32_t b0 = __float_as_uint(Bs[k0 + tg    ][nb + grp]);           \
            uint32_t b1 = __float_as_uint(Bs[k0 + tg + 4][nb + grp]);           \
            _Pragma("unroll")                                                   \
            for (int mt = 0; mt < 2; mt++)                                      \
                mma_tf32(d[mt][nt], afr[mt], b0, b1);                           \
        }                                                                       \
    }

__device__ void cell2_body(const float* W, const float* U, const float* B,
                           const float* Z, const float* Qin, const float* RST,
                           const float* UPD, float* Qout, float* Qc, int x16) {
    __shared__ float As[16][68], Bs[16][68];
    int tid = threadIdx.x, lane = tid & 31, wid = tid >> 5;
    int wm = wid >> 2, wn = wid & 3;
    int grp = lane >> 2, tg = lane & 3;
    int i0 = (x16 >> 2) * 64, j0 = (x16 & 3) * 64;

    float d[2][2][4];
    #pragma unroll
    for (int mt = 0; mt < 2; mt++)
        #pragma unroll
        for (int nt = 0; nt < 2; nt++)
            #pragma unroll
            for (int q = 0; q < 4; q++) d[mt][nt][q] = 0.f;

    int ar = tid >> 2, ac = (tid & 3) * 4;
    int qk = tid >> 4, qn = (tid & 15) * 4;

    for (int kb = 0; kb < 256; kb += 16) {
        float4 a4 = *(const float4*)(W + (size_t)(i0+ar)*256 + kb + ac);
        As[ac  ][ar]=cvt_tf32(a4.x); As[ac+1][ar]=cvt_tf32(a4.y);
        As[ac+2][ar]=cvt_tf32(a4.z); As[ac+3][ar]=cvt_tf32(a4.w);
        float4 b4 = *(const float4*)(Z + (size_t)(j0+ar)*256 + kb + ac);
        Bs[ac  ][ar]=cvt_tf32(b4.x); Bs[ac+1][ar]=cvt_tf32(b4.y);
        Bs[ac+2][ar]=cvt_tf32(b4.z); Bs[ac+3][ar]=cvt_tf32(b4.w);
        __syncthreads();
        CELL_MMA_256(As, Bs);
        __syncthreads();
    }
    for (int kb = 0; kb < 256; kb += 16) {
        float4 a4 = *(const float4*)(U + (size_t)(i0+ar)*256 + kb + ac);
        As[ac  ][ar]=cvt_tf32(a4.x); As[ac+1][ar]=cvt_tf32(a4.y);
        As[ac+2][ar]=cvt_tf32(a4.z); As[ac+3][ar]=cvt_tf32(a4.w);
        float4 b4 = *(const float4*)(Qin + (size_t)(kb+qk)*256 + j0 + qn);
        float4 r4 = *(const float4*)(RST + (size_t)(kb+qk)*256 + j0 + qn);
        Bs[qk][qn  ]=cvt_tf32(b4.x*r4.x); Bs[qk][qn+1]=cvt_tf32(b4.y*r4.y);
        Bs[qk][qn+2]=cvt_tf32(b4.z*r4.z); Bs[qk][qn+3]=cvt_tf32(b4.w*r4.w);
        __syncthreads();
        CELL_MMA_256(As, Bs);
        __syncthreads();
    }

    #pragma unroll
    for (int mt = 0; mt < 2; mt++) {
        #pragma unroll
        for (int nt = 0; nt < 2; nt++) {
            #pragma unroll
            for (int half = 0; half < 2; half++) {
                int r = i0 + wm*32 + mt*16 + grp + half*8;
                int col = j0 + wn*16 + nt*8 + 2*tg;
                float d0 = d[mt][nt][half*2], d1 = d[mt][nt][half*2 + 1];
                float2 bi = *(const float2*)(B + (size_t)r*256 + col);
                float2 up = *(const float2*)(UPD + (size_t)r*256 + col);
                float2 qi = *(const float2*)(Qin + (size_t)r*256 + col);
                float h0 = tanhf(d0 + bi.x), h1 = tanhf(d1 + bi.y);
                float v0 = (1.f - up.x)*qi.x + up.x*h0;
                float v1 = (1.f - up.y)*qi.y + up.y*h1;
                *(float2*)&Qout[(size_t)r*256 + col] = make_float2(v0, v1);
                *(float2*)&Qc[(size_t)r*256 + col] = make_float2(cvt_tf32(v0), cvt_tf32(v1));
            }
        }
    }
}

__device__ __forceinline__ void cell1_sel(
    int o, int c,
    const float* sWz, const float* sUz, const float* sbz,
    const float* sWr, const float* sUr, const float* sbr,
    const float* rWz, const float* rUz, const float* rbz,
    const float* rWr, const float* rUr, const float* rbr,
    int par, int t, int x16) {
    const float *W, *U, *B;
    if (o == 0) { W = c ? rWz + (c-1)*MAT_ : sWz; U = c ? rUz + (c-1)*MAT_ : sUz; B = c ? rbz + (c-1)*MAT_ : sbz; }
    else        { W = c ? rWr + (c-1)*MAT_ : sWr; U = c ? rUr + (c-1)*MAT_ : sUr; B = c ? rbr + (c-1)*MAT_ : sbr; }
    cell1_body(W, U, B, g_zt + (size_t)(t*C_ + c)*MAT_, g_Q[par] + c*MAT_,
               (o == 0 ? g_upd : g_rst) + c*MAT_, x16);
}

// ================== big GEMM: 128x128 tile, 128 threads, warp tile 64x64 ==================
#define GA_PAD 20
#define GB_PAD 136
#define G_STAGE (128*GA_PAD*4 + 16*GB_PAD*4)
#define G_SMEM  (2*G_STAGE)

__device__ void gemm_body(float* __restrict__ out, int t, int c, int m0, int n0) {
    const float* Ag = g_xc + (size_t)t*N_*F_;
    const float* Bg = g_Qc + (size_t)c*MAT_;
    float* dst = (c == 0) ? out + (size_t)t*N_*FO_ : g_Y + (size_t)(c-1)*N_*FO_;

    float* smf = (float*)s_dyn;
    uint32_t smb = smem_u32(s_dyn);
    int tid = threadIdx.x, wid = tid >> 5, lane = tid & 31;
    int wm = wid >> 1, wn = wid & 1;       // 2 x 2 warps, warp tile 64x64
    int grp = lane >> 2, tg = lane & 3;

    float d[4][8][4];
    #pragma unroll
    for (int mt = 0; mt < 4; mt++)
        #pragma unroll
        for (int nt = 0; nt < 8; nt++)
            #pragma unroll
            for (int q = 0; q < 4; q++) d[mt][nt][q] = 0.f;

    auto load_stage = [&](int stg, int kb) {
        uint32_t sa = smb + stg*G_STAGE;
        uint32_t sb = sa + 128*GA_PAD*4;
        // A: 512 x16B chunks, 4/thread
        #pragma unroll
        for (int i = 0; i < 4; i++) {
            int idx = tid + i*128;
            int row = idx >> 2, ch = idx & 3;
            int gr = m0 + row;
            uint32_t dsta = sa + (uint32_t)(row*GA_PAD + ch*4)*4;
            if (gr < N_) {
                cp_async16(dsta, Ag + (size_t)gr*F_ + kb + ch*4);
            } else {
                *(float4*)(s_dyn + (dsta - smb)) = make_float4(0.f, 0.f, 0.f, 0.f);
            }
        }
        // B: 512 x16B chunks, 4/thread
        #pragma unroll
        for (int i = 0; i < 4; i++) {
            int idx = tid + i*128;
            int kr = idx >> 5, nch = idx & 31;
            uint32_t dstb = sb + (uint32_t)(kr*GB_PAD + nch*4)*4;
            cp_async16(dstb, Bg + (size_t)(kb + kr)*FO_ + n0 + nch*4);
        }
        CP_COMMIT();
    };

    load_stage(0, 0);

    #pragma unroll 1
    for (int step = 0; step < 16; step++) {
        if (step + 1 < 16) load_stage((step + 1) & 1, (step + 1) * 16);
        if (step + 1 < 16) { CP_WAIT(1); } else { CP_WAIT(0); }
        __syncthreads();

        const float* As = smf + ((step & 1) ? G_STAGE/4 : 0);
        const float* Bs = As + 128*GA_PAD;

        #pragma unroll
        for (int kc = 0; kc < 2; kc++) {
            int k0 = kc * 8;
            uint32_t a[4][4];
            #pragma unroll
            for (int mt = 0; mt < 4; mt++) {
                int mb = wm*64 + mt*16;
                a[mt][0] = __float_as_uint(As[(mb + grp    )*GA_PAD + k0 + tg    ]);
                a[mt][1] = __float_as_uint(As[(mb + grp + 8)*GA_PAD + k0 + tg    ]);
                a[mt][2] = __float_as_uint(As[(mb + grp    )*GA_PAD + k0 + tg + 4]);
                a[mt][3] = __float_as_uint(As[(mb + grp + 8)*GA_PAD + k0 + tg + 4]);
            }
            #pragma unroll
            for (int nt = 0; nt < 8; nt++) {
                int nb = wn*64 + nt*8;
                uint32_t b0 = __float_as_uint(Bs[(k0 + tg    )*GB_PAD + nb + grp]);
                uint32_t b1 = __float_as_uint(Bs[(k0 + tg + 4)*GB_PAD + nb + grp]);
                #pragma unroll
                for (int mt = 0; mt < 4; mt++)
                    mma_tf32(d[mt][nt], a[mt], b0, b1);
            }
        }
        __syncthreads();
    }

    #pragma unroll
    for (int mt = 0; mt < 4; mt++) {
        #pragma unroll
        for (int nt = 0; nt < 8; nt++) {
            int r0 = m0 + wm*64 + mt*16 + grp;
            int col = n0 + wn*64 + nt*8 + 2*tg;
            if (r0 < N_)
                *(float2*)&dst[(size_t)r0*FO_ + col] = make_float2(d[mt][nt][0], d[mt][nt][1]);
            int r1 = r0 + 8;
            if (r1 < N_)
                *(float2*)&dst[(size_t)r1*FO_ + col] = make_float2(d[mt][nt][2], d[mt][nt][3]);
        }
    }
}

// ================== agg body ==================
__device__ void agg_body(float* __restrict__ out, int t, int blk) {
    int warp = threadIdx.x >> 5, lane = threadIdx.x & 31;
    int row = blk * 8 + warp;
    if (row >= N_) return;
    const float* dis = g_dis + (size_t)t*R_*N_;
    float disrow[R_];
    #pragma unroll
    for (int r = 0; r < R_; r++) disrow[r] = dis[r*N_ + row];
    float4 a0 = make_float4(0.f, 0.f, 0.f, 0.f);
    float4 a1 = make_float4(0.f, 0.f, 0.f, 0.f);
    int beg = g_off[t*(N_+1) + row], end = g_off[t*(N_+1) + row + 1];
    const uint32_t* ep = g_epack + (size_t)t*E_;
    for (int p = beg; p < end; p++) {
        uint32_t pk = ep[p];
        int r = pk & 3;
        int col = pk >> 2;
        float norm = disrow[r] * dis[r*N_ + col];
        if (norm != 0.f) {
            const float4* src = (const float4*)(g_Y + ((size_t)r*N_ + col) * FO_);
            float4 v0 = src[lane];
            float4 v1 = src[lane + 32];
            a0.x += v0.x*norm; a0.y += v0.y*norm; a0.z += v0.z*norm; a0.w += v0.w*norm;
            a1.x += v1.x*norm; a1.y += v1.y*norm; a1.z += v1.z*norm; a1.w += v1.w*norm;
        }
    }
    float4* dst = (float4*)(out + (size_t)t*N_*FO_ + (size_t)row*FO_);
    float4 o0 = dst[lane];
    float4 o1 = dst[lane + 32];
    o0.x = fmaxf(o0.x + a0.x, 0.f); o0.y = fmaxf(o0.y + a0.y, 0.f);
    o0.z = fmaxf(o0.z + a0.z, 0.f); o0.w = fmaxf(o0.w + a0.w, 0.f);
    o1.x = fmaxf(o1.x + a1.x, 0.f); o1.y = fmaxf(o1.y + a1.y, 0.f);
    o1.z = fmaxf(o1.z + a1.z, 0.f); o1.w = fmaxf(o1.w + a1.w, 0.f);
    dst[lane] = o0;
    dst[lane + 32] = o1;
}

// ================== merged per-t kernels (cells at LOW block indices) ==================
__global__ __launch_bounds__(128, 2) void k_gemm_cell1(
    float* __restrict__ out, int t,
    const float* sWz, const float* sUz, const float* sbz,
    const float* sWr, const float* sUr, const float* sbr,
    const float* rWz, const float* rUz, const float* rbz,
    const float* rWr, const float* rUr, const float* rbr,
    int parNext, int tNext, int doCell) {
    int z = blockIdx.z;
    if (z < 2*C_) {
        // cell1 blocks scheduled FIRST (low z) so they overlap the gemm waves
        if (!doCell || blockIdx.x >= 16 || blockIdx.y != 0) return;
        cell1_sel(z & 1, z >> 1, sWz, sUz, sbz, sWr, sUr, sbr,
                  rWz, rUz, rbz, rWr, rUr, rbr, parNext, tNext, blockIdx.x);
    } else {
        gemm_body(out, t, z - 2*C_, blockIdx.x * 128, blockIdx.y * 128);
    }
}

__global__ __launch_bounds__(256) void k_agg_cell2(
    float* __restrict__ out, int t,
    const float* sWh, const float* sUh, const float* sbh,
    const float* rWh, const float* rUh, const float* rbh,
    int parNext, int tNext, int doCell) {
    int x = blockIdx.x;
    if (x < 80) {
        // cell2 blocks scheduled FIRST
        if (!doCell) return;
        int c = x >> 4, x16 = x & 15;
        const float* W = c ? rWh + (c-1)*MAT_ : sWh;
        const float* U = c ? rUh + (c-1)*MAT_ : sUh;
        const float* B = c ? rbh + (c-1)*MAT_ : sbh;
        cell2_body(W, U, B, g_zt + (size_t)(tNext*C_ + c)*MAT_,
                   g_Q[parNext] + c*MAT_, g_rst + c*MAT_, g_upd + c*MAT_,
                   g_Q[parNext ^ 1] + c*MAT_, g_Qc + c*MAT_, x16);
    } else {
        agg_body(out, t, x - 80);
    }
}

// standalone cells for t=0
__global__ __launch_bounds__(128) void k_cell1_only(
    const float* sWz, const float* sUz, const float* sbz,
    const float* sWr, const float* sUr, const float* sbr,
    const float* rWz, const float* rUz, const float* rbz,
    const float* rWr, const float* rUr, const float* rbr,
    int par, int t) {
    int u = blockIdx.z;
    cell1_sel(u & 1, u >> 1, sWz, sUz, sbz, sWr, sUr, sbr,
              rWz, rUz, rbz, rWr, rUr, rbr, par, t, blockIdx.x);
}
__global__ __launch_bounds__(256) void k_cell2_only(
    const float* sWh, const float* sUh, const float* sbh,
    const float* rWh, const float* rUh, const float* rbh,
    int par, int t) {
    int c = blockIdx.z;
    const float* W = c ? rWh + (c-1)*MAT_ : sWh;
    const float* U = c ? rUh + (c-1)*MAT_ : sUh;
    const float* B = c ? rbh + (c-1)*MAT_ : sbh;
    cell2_body(W, U, B, g_zt + (size_t)(t*C_ + c)*MAT_,
               g_Q[par] + c*MAT_, g_rst + c*MAT_, g_upd + c*MAT_,
               g_Q[par ^ 1] + c*MAT_, g_Qc + c*MAT_, blockIdx.x);
}

// ================== launcher ==================
extern "C" void kernel_launch(void* const* d_in, const int* in_sizes, int n_in,
                              void* d_out, int out_size) {
    const float* x       = (const float*)d_in[0];
    const float* mask    = (const float*)d_in[1];
    const float* Wself   = (const float*)d_in[2];
    const float* Wrel    = (const float*)d_in[3];
    const float* sWz     = (const float*)d_in[4];
    const float* sUz     = (const float*)d_in[5];
    const float* sbz     = (const float*)d_in[6];
    const float* sWr     = (const float*)d_in[7];
    const float* sUr     = (const float*)d_in[8];
    const float* sbr     = (const float*)d_in[9];
    const float* sWh     = (const float*)d_in[10];
    const float* sUh     = (const float*)d_in[11];
    const float* sbh     = (const float*)d_in[12];
    const float* s_sc    = (const float*)d_in[13];
    const float* rWz     = (const float*)d_in[14];
    const float* rUz     = (const float*)d_in[15];
    const float* rbz     = (const float*)d_in[16];
    const float* rWr     = (const float*)d_in[17];
    const float* rUr     = (const float*)d_in[18];
    const float* rbr     = (const float*)d_in[19];
    const float* rWh     = (const float*)d_in[20];
    const float* rUh     = (const float*)d_in[21];
    const float* rbh     = (const float*)d_in[22];
    const float* r_sc    = (const float*)d_in[23];
    const int*   ei      = (const int*)d_in[24];
    const int*   et      = (const int*)d_in[25];
    float* out = (float*)d_out;

    static bool attr_set = false;
    if (!attr_set) {
        cudaFuncSetAttribute(k_sel, cudaFuncAttributeMaxDynamicSharedMemorySize,
                             N_ * (int)sizeof(uint32_t));
        cudaFuncSetAttribute(k_gemm_cell1, cudaFuncAttributeMaxDynamicSharedMemorySize,
                             G_SMEM);
        attr_set = true;
    }

    // preamble
    k_prep<<<PB_TOTAL, 256>>>(Wself, Wrel, x, s_sc, r_sc);
    k_scores_edge<<<7500 + 3750, 256>>>(x, mask, s_sc, r_sc, ei, et);
    k_sel<<<T_*C_ + T_ + SEL_DIS_BLOCKS, 1024, N_ * sizeof(uint32_t)>>>();
    k_zt_scatter<<<ZT_BLOCKS + 3750, 256>>>(x, ei, et);

    // t = 0 cells
    k_cell1_only<<<dim3(16, 1, 2*C_), 128>>>(sWz, sUz, sbz, sWr, sUr, sbr,
                                             rWz, rUz, rbz, rWr, rUr, rbr, 0, 0);
    k_cell2_only<<<dim3(16, 1, C_), 256>>>(sWh, sUh, sbh, rWh, rUh, rbh, 0, 0);

    // pipelined recurrence (cells in LOW block indices for true overlap)
    for (int t = 0; t < T_; t++) {
        int doCell = (t + 1 < T_) ? 1 : 0;
        int parN = (t + 1) & 1;
        k_gemm_cell1<<<dim3((N_ + 127)/128, 2, 2*C_ + C_), 128, G_SMEM>>>(
            out, t, sWz, sUz, sbz, sWr, sUr, sbr,
            rWz, rUz, rbz, rWr, rUr, rbr, parN, t + 1, doCell);
        k_agg_cell2<<<80 + 2500, 256>>>(
            out, t, sWh, sUh, sbh, rWh, rUh, rbh, parN, t + 1, doCell);
    }
}